// round 1
// baseline (speedup 1.0000x reference)
#include <cuda_runtime.h>
#include <math.h>

// ---------------------------------------------------------------------------
// Problem constants
// ---------------------------------------------------------------------------
#define BATCH 4096
#define SEQ   41
#define FDIM  128
#define SF    (SEQ*FDIM)        // 5248
#define C64L  (64*128)          // 8192

// ---------------------------------------------------------------------------
// Scratch (device globals; allocation-free contract)
// ---------------------------------------------------------------------------
__device__ float  g_bufA[(size_t)BATCH * C64L];
__device__ float  g_bufB[(size_t)BATCH * C64L];
__device__ float  g_g1[(size_t)BATCH * 128];   // [B,2,64]
__device__ float  g_g2[(size_t)BATCH * 64];    // [B,2,32]
__device__ double g_bnsum[64], g_bnsq[64];
__device__ float  g_bnscale[64], g_bnshift[64];
__device__ double g_bn1acc[4];                 // sum0,sum1,sq0,sq1
__device__ double g_bn2acc[4];
__device__ float  g_bn1p[4];                   // sc0,sc1,sh0,sh1
__device__ float  g_bn2p[4];

__device__ __forceinline__ float* bufsel(int which) {
    return which ? g_bufB : g_bufA;
}

__device__ __forceinline__ float squash_factor(float ssq) {
    float n = sqrtf(ssq);
    return (1.f - 1.f / (expf(n) + 1e-21f)) / (n + 1e-21f);
}

// ---------------------------------------------------------------------------
// 0. zero accumulators
// ---------------------------------------------------------------------------
__global__ void zero_kernel() {
    int t = threadIdx.x;
    if (t < 64) { g_bnsum[t] = 0.0; g_bnsq[t] = 0.0; }
    if (t < 4)  { g_bn1acc[t] = 0.0; g_bn2acc[t] = 0.0; }
}

// ---------------------------------------------------------------------------
// 1. embedding gather -> bufA [B,41,128]
// ---------------------------------------------------------------------------
__global__ void embed_kernel(const int* __restrict__ x, const float* __restrict__ emb) {
    int gid = blockIdx.x * 256 + threadIdx.x;      // B*S*32 threads (float4 per thread)
    int pos = gid >> 5;
    int f4  = (gid & 31) * 4;
    if (pos < BATCH * SEQ) {
        int e = x[pos];
        float4 v = *reinterpret_cast<const float4*>(emb + e * FDIM + f4);
        *reinterpret_cast<float4*>(bufsel(0) + (size_t)pos * FDIM + f4) = v;
    }
}

// ---------------------------------------------------------------------------
// 2-4. position_linear as per-position GEMM.
//   For position s: out[b, s, :] = relu( A_row(b,s) @ W[s] + bias[s] )
//   A_row(b,s)[j*128+f] = in[b, s+j-P, f]  (zero outside [0,41))
//   BM=128, BN=128, BK=16, 256 threads, 8x8 micro-tile.
// ---------------------------------------------------------------------------
template<int WIN>
__global__ void __launch_bounds__(256, 2)
pl_kernel(const float* __restrict__ Wst,   // [41, WIN*128, 128]
          const float* __restrict__ bst,   // [41, 128]
          int src)
{
    constexpr int P = WIN / 2;
    constexpr int K = WIN * 128;
    const float* __restrict__ in = bufsel(src);
    float* __restrict__ out = bufsel(src ^ 1);

    const int s  = blockIdx.y;
    const int bm = blockIdx.x * 128;

    __shared__ float As[16][132];   // [k][m]
    __shared__ float Bs[16][132];   // [k][n]

    const int tid = threadIdx.x;
    const int tx = tid & 15, ty = tid >> 4;

    float acc[8][8];
#pragma unroll
    for (int i = 0; i < 8; i++)
#pragma unroll
        for (int j = 0; j < 8; j++) acc[i][j] = 0.f;

    const float* Wbase = Wst + (size_t)s * K * 128;

    for (int k0 = 0; k0 < K; k0 += 16) {
        int j = k0 >> 7;
        int f0 = k0 & 127;
        int t = s + j - P;
        bool valid = ((unsigned)t < (unsigned)SEQ);
        // A tile: 128 rows x 16 k -> As[k][m]
#pragma unroll
        for (int it = 0; it < 2; it++) {
            int q  = tid + it * 256;          // float4 index, 512 total
            int m  = q >> 2;
            int c4 = (q & 3) * 4;
            float4 v = make_float4(0.f, 0.f, 0.f, 0.f);
            if (valid) {
                const float* sp = in + ((size_t)(bm + m) * SEQ + t) * FDIM + f0 + c4;
                v = *reinterpret_cast<const float4*>(sp);
            }
            As[c4 + 0][m] = v.x; As[c4 + 1][m] = v.y;
            As[c4 + 2][m] = v.z; As[c4 + 3][m] = v.w;
        }
        // B tile: 16 k x 128 n
#pragma unroll
        for (int it = 0; it < 2; it++) {
            int q  = tid + it * 256;
            int kk = q >> 5;
            int n4 = (q & 31) * 4;
            float4 v = *reinterpret_cast<const float4*>(Wbase + (size_t)(k0 + kk) * 128 + n4);
            *reinterpret_cast<float4*>(&Bs[kk][n4]) = v;
        }
        __syncthreads();
#pragma unroll
        for (int kk = 0; kk < 16; kk++) {
            float a[8], b[8];
            *reinterpret_cast<float4*>(a)     = *reinterpret_cast<float4*>(&As[kk][ty * 8]);
            *reinterpret_cast<float4*>(a + 4) = *reinterpret_cast<float4*>(&As[kk][ty * 8 + 4]);
            *reinterpret_cast<float4*>(b)     = *reinterpret_cast<float4*>(&Bs[kk][tx * 8]);
            *reinterpret_cast<float4*>(b + 4) = *reinterpret_cast<float4*>(&Bs[kk][tx * 8 + 4]);
#pragma unroll
            for (int i = 0; i < 8; i++)
#pragma unroll
                for (int jj = 0; jj < 8; jj++)
                    acc[i][jj] += a[i] * b[jj];
        }
        __syncthreads();
    }

    const float* bias = bst + s * 128;
#pragma unroll
    for (int i = 0; i < 8; i++) {
        int m = ty * 8 + i;
        float* dst = out + ((size_t)(bm + m) * SEQ + s) * FDIM;
#pragma unroll
        for (int jj = 0; jj < 8; jj++) {
            int n = tx * 8 + jj;
            float v = acc[i][jj] + bias[n];
            dst[n] = v > 0.f ? v : 0.f;
        }
    }
}

// ---------------------------------------------------------------------------
// 5. conv1d: in bufB [B,41,128] (N=B, C=41, L=128), w [64,41,3], pad 1
//    -> bufA [B,64,128] (raw, +bias, no activation yet)
//    One block per batch. smem: input row-block + all weights.
// ---------------------------------------------------------------------------
#define CONV1_SMEM ((41*130 + 64*123) * 4)
__global__ void conv1_kernel(const float* __restrict__ w, const float* __restrict__ bias) {
    extern __shared__ float sm[];
    float* xin = sm;             // 41 * 130 (padded L)
    float* ws  = sm + 41 * 130;  // 64*123
    const float* __restrict__ in = bufsel(1);
    float* __restrict__ out = bufsel(0);

    int b = blockIdx.x, t = threadIdx.x;
    const float* src = in + (size_t)b * SF;
    for (int idx = t; idx < SF; idx += 256) {
        int c = idx >> 7, l = idx & 127;
        xin[c * 130 + l + 1] = src[idx];
    }
    if (t < 41) { xin[t * 130] = 0.f; xin[t * 130 + 129] = 0.f; }
    for (int idx = t; idx < 64 * 123; idx += 256) ws[idx] = w[idx];
    __syncthreads();

    int og = t >> 4, lg = t & 15;
    int o0 = og * 4;
    float acc[4][8];
#pragma unroll
    for (int a = 0; a < 4; a++)
#pragma unroll
        for (int u = 0; u < 8; u++) acc[a][u] = 0.f;

    for (int c = 0; c < 41; c++) {
        const float* xr = xin + c * 130;
        float wl[4][3];
#pragma unroll
        for (int a = 0; a < 4; a++) {
            const float* wp = ws + (o0 + a) * 123 + c * 3;
            wl[a][0] = wp[0]; wl[a][1] = wp[1]; wl[a][2] = wp[2];
        }
#pragma unroll
        for (int u = 0; u < 8; u++) {
            int l = lg + 16 * u;
            float x0 = xr[l], x1 = xr[l + 1], x2 = xr[l + 2];
#pragma unroll
            for (int a = 0; a < 4; a++)
                acc[a][u] += x0 * wl[a][0] + x1 * wl[a][1] + x2 * wl[a][2];
        }
    }
    float* dst = out + (size_t)b * C64L;
#pragma unroll
    for (int a = 0; a < 4; a++) {
        float bb = bias[o0 + a];
#pragma unroll
        for (int u = 0; u < 8; u++)
            dst[(o0 + a) * 128 + lg + 16 * u] = acc[a][u] + bb;
    }
}

// ---------------------------------------------------------------------------
// 6. BN stats over (B, L) per channel (64 channels)
// ---------------------------------------------------------------------------
__global__ void bn_reduce_kernel() {
    const float* __restrict__ x = bufsel(0);
    int c  = blockIdx.x;
    int b0 = blockIdx.y * 128;
    int t  = threadIdx.x;
    double s = 0.0, q = 0.0;
    for (int it = 0; it < 64; it++) {
        int idx = t + it * 256;          // 0..16383
        int bl = idx >> 7, l = idx & 127;
        float v = x[((size_t)(b0 + bl)) * C64L + c * 128 + l];
        s += v; q += (double)v * v;
    }
    for (int off = 16; off; off >>= 1) {
        s += __shfl_xor_sync(0xffffffffu, s, off);
        q += __shfl_xor_sync(0xffffffffu, q, off);
    }
    __shared__ double ss[8], qq[8];
    if ((t & 31) == 0) { ss[t >> 5] = s; qq[t >> 5] = q; }
    __syncthreads();
    if (t == 0) {
        double S = 0, Q = 0;
        for (int i = 0; i < 8; i++) { S += ss[i]; Q += qq[i]; }
        atomicAdd(&g_bnsum[c], S);
        atomicAdd(&g_bnsq[c], Q);
    }
}

__global__ void bn_fin_conv(const float* __restrict__ g, const float* __restrict__ bb) {
    int c = threadIdx.x;
    double inv = 1.0 / ((double)BATCH * 128.0);
    double mu = g_bnsum[c] * inv;
    double var = g_bnsq[c] * inv - mu * mu;
    float sc = g[c] * rsqrtf((float)var + 1e-5f);
    g_bnscale[c] = sc;
    g_bnshift[c] = bb[c] - (float)mu * sc;
}

// ---------------------------------------------------------------------------
// 8. caps conv (groups=2): BN+ReLU fused at load, +bias, squash fused in epi.
//    bufA -> bufB [B,64,128]
// ---------------------------------------------------------------------------
#define CAPS_SMEM ((64*130 + 64*96 + 64*128) * 4)
__global__ void caps_kernel(const float* __restrict__ w, const float* __restrict__ cb) {
    extern __shared__ float sm[];
    float* xin  = sm;                       // 64*130
    float* ws   = sm + 64 * 130;            // 64*96
    float* sout = sm + 64 * 130 + 64 * 96;  // 64*128
    const float* __restrict__ in = bufsel(0);
    float* __restrict__ out = bufsel(1);

    int b = blockIdx.x, t = threadIdx.x;
    const float* src = in + (size_t)b * C64L;
    for (int idx = t; idx < C64L; idx += 256) {
        int c = idx >> 7, l = idx & 127;
        float v = fmaxf(src[idx] * g_bnscale[c] + g_bnshift[c], 0.f);
        xin[c * 130 + l + 1] = v;
    }
    if (t < 64) { xin[t * 130] = 0.f; xin[t * 130 + 129] = 0.f; }
    for (int idx = t; idx < 64 * 96; idx += 256) ws[idx] = w[idx];
    __syncthreads();

    int og = t >> 4, lg = t & 15;
    int o0 = og * 4;
    int cbase = (o0 >= 32) ? 32 : 0;
    float acc[4][8];
#pragma unroll
    for (int a = 0; a < 4; a++)
#pragma unroll
        for (int u = 0; u < 8; u++) acc[a][u] = 0.f;

    for (int ci = 0; ci < 32; ci++) {
        const float* xr = xin + (cbase + ci) * 130;
        float wl[4][3];
#pragma unroll
        for (int a = 0; a < 4; a++) {
            const float* wp = ws + (o0 + a) * 96 + ci * 3;
            wl[a][0] = wp[0]; wl[a][1] = wp[1]; wl[a][2] = wp[2];
        }
#pragma unroll
        for (int u = 0; u < 8; u++) {
            int l = lg + 16 * u;
            float x0 = xr[l], x1 = xr[l + 1], x2 = xr[l + 2];
#pragma unroll
            for (int a = 0; a < 4; a++)
                acc[a][u] += x0 * wl[a][0] + x1 * wl[a][1] + x2 * wl[a][2];
        }
    }
#pragma unroll
    for (int a = 0; a < 4; a++) {
        float bb = cb[o0 + a];
#pragma unroll
        for (int u = 0; u < 8; u++)
            sout[(o0 + a) * 128 + lg + 16 * u] = acc[a][u] + bb;
    }
    __syncthreads();

    // squash per (b, o) row over 128
    int wid = t >> 5, lane = t & 31;
    float* dst = out + (size_t)b * C64L;
    for (int rr = 0; rr < 8; rr++) {
        int o = wid * 8 + rr;
        float v0 = sout[o * 128 + lane];
        float v1 = sout[o * 128 + lane + 32];
        float v2 = sout[o * 128 + lane + 64];
        float v3 = sout[o * 128 + lane + 96];
        float ssq = v0 * v0 + v1 * v1 + v2 * v2 + v3 * v3;
        for (int off = 16; off; off >>= 1) ssq += __shfl_xor_sync(0xffffffffu, ssq, off);
        float factor = squash_factor(ssq);
        dst[o * 128 + lane]      = v0 * factor;
        dst[o * 128 + lane + 32] = v1 * factor;
        dst[o * 128 + lane + 64] = v2 * factor;
        dst[o * 128 + lane + 96] = v3 * factor;
    }
}

// ---------------------------------------------------------------------------
// 9. routing + squash + pair-max + fc1 (-> g1), bn1 partial stats
//    one block per batch
// ---------------------------------------------------------------------------
__global__ void route_kernel(const float* __restrict__ rW,   // [2,64,128]
                             const float* __restrict__ rb,   // [2,64,1]
                             const float* __restrict__ fc1)  // [128,64]
{
    __shared__ float hs[64 * 128];
    __shared__ float sv_s[2][128];
    __shared__ float yv_s[2][128];
    __shared__ float warp_sq[8];
    __shared__ float factor_s[2];

    const float* __restrict__ h = bufsel(1);
    int b = blockIdx.x, t = threadIdx.x;
    const float* hb = h + (size_t)b * C64L;
    for (int idx = t; idx < C64L; idx += 256) hs[idx] = hb[idx];
    __syncthreads();

    int i = t >> 7;     // 0/1
    int f = t & 127;
    float acc = 0.f;
    const float* rwi = rW + i * 8192 + f;
    const float* rbi = rb + i * 64;
#pragma unroll 8
    for (int j = 0; j < 64; j++) {
        float cj = 1.0f + rbi[j];
        acc += hs[j * 128 + f] * rwi[j * 128] * cj;
    }
    float sq = acc * acc;
    for (int off = 16; off; off >>= 1) sq += __shfl_xor_sync(0xffffffffu, sq, off);
    if ((t & 31) == 0) warp_sq[t >> 5] = sq;
    __syncthreads();
    if (t < 2) {
        float tot = warp_sq[t * 4 + 0] + warp_sq[t * 4 + 1] + warp_sq[t * 4 + 2] + warp_sq[t * 4 + 3];
        factor_s[t] = squash_factor(tot);
    }
    __syncthreads();
    float svv = acc * factor_s[i];
    sv_s[i][f] = svv;
    __syncthreads();
    float y = sv_s[i][f] + fmaxf(sv_s[0][f], sv_s[1][f]);
    yv_s[i][f] = y;
    __syncthreads();

    if (t < 128) {
        int ii = t >> 6, o = t & 63;
        float a = 0.f;
        for (int ff = 0; ff < 128; ff++) a += yv_s[ii][ff] * fc1[ff * 64 + o];
        g_g1[(size_t)b * 128 + ii * 64 + o] = a;
        double s = a, q = (double)a * a;
        for (int off = 16; off; off >>= 1) {
            s += __shfl_xor_sync(0xffffffffu, s, off);
            q += __shfl_xor_sync(0xffffffffu, q, off);
        }
        if ((t & 31) == 0) {
            atomicAdd(&g_bn1acc[ii], s);
            atomicAdd(&g_bn1acc[2 + ii], q);
        }
    }
}

__global__ void bn1_fin(const float* __restrict__ g, const float* __restrict__ bb) {
    int i = threadIdx.x;
    double inv = 1.0 / ((double)BATCH * 64.0);
    double mu = g_bn1acc[i] * inv;
    double var = g_bn1acc[2 + i] * inv - mu * mu;
    float sc = g[i] * rsqrtf((float)var + 1e-5f);
    g_bn1p[i] = sc;
    g_bn1p[2 + i] = bb[i] - (float)mu * sc;
}

// ---------------------------------------------------------------------------
// 11. head1: relu(bn1(g1)) @ fc2 -> g2, bn2 partial stats. 4 batches/block.
// ---------------------------------------------------------------------------
__global__ void head1_kernel(const float* __restrict__ fc2) {
    __shared__ float a_s[4][128];
    int t = threadIdx.x;
    // load + bn1 + relu
    for (int idx = t; idx < 512; idx += 256) {
        int lbb = idx >> 7, rr = idx & 127;
        int ii = rr >> 6;
        float v = g_g1[(size_t)(blockIdx.x * 4 + lbb) * 128 + rr];
        a_s[lbb][rr] = fmaxf(v * g_bn1p[ii] + g_bn1p[2 + ii], 0.f);
    }
    __syncthreads();
    int lb = t >> 6, r = t & 63;
    int b = blockIdx.x * 4 + lb;
    int ii = r >> 5, m = r & 31;
    float acc = 0.f;
    const float* arow = &a_s[lb][ii * 64];
#pragma unroll 8
    for (int o = 0; o < 64; o++) acc += arow[o] * fc2[o * 32 + m];
    g_g2[(size_t)b * 64 + ii * 32 + m] = acc;
    double s = acc, q = (double)acc * acc;
    for (int off = 16; off; off >>= 1) {
        s += __shfl_xor_sync(0xffffffffu, s, off);
        q += __shfl_xor_sync(0xffffffffu, q, off);
    }
    if ((t & 31) == 0) {
        atomicAdd(&g_bn2acc[ii], s);
        atomicAdd(&g_bn2acc[2 + ii], q);
    }
}

__global__ void bn2_fin(const float* __restrict__ g, const float* __restrict__ bb) {
    int i = threadIdx.x;
    double inv = 1.0 / ((double)BATCH * 32.0);
    double mu = g_bn2acc[i] * inv;
    double var = g_bn2acc[2 + i] * inv - mu * mu;
    float sc = g[i] * rsqrtf((float)var + 1e-5f);
    g_bn2p[i] = sc;
    g_bn2p[2 + i] = bb[i] - (float)mu * sc;
}

// ---------------------------------------------------------------------------
// 13. head2: relu(bn2(g2)) @ fc3, sigmoid, max over the 2 rows -> out[B]
// ---------------------------------------------------------------------------
__global__ void head2_kernel(const float* __restrict__ fc3, float* __restrict__ out) {
    int b = blockIdx.x * 256 + threadIdx.x;
    if (b >= BATCH) return;
    float best = -1e30f;
#pragma unroll
    for (int i = 0; i < 2; i++) {
        float sc = g_bn2p[i], sh = g_bn2p[2 + i];
        float s = 0.f;
#pragma unroll
        for (int m = 0; m < 32; m++) {
            float v = fmaxf(g_g2[(size_t)b * 64 + i * 32 + m] * sc + sh, 0.f);
            s += v * fc3[m];
        }
        float sig = 1.f / (1.f + expf(-s));
        best = fmaxf(best, sig);
    }
    out[b] = best;
}

// ---------------------------------------------------------------------------
// launch
// ---------------------------------------------------------------------------
extern "C" void kernel_launch(void* const* d_in, const int* in_sizes, int n_in,
                              void* d_out, int out_size)
{
    const int*   x      = (const int*)d_in[0];
    const float* emb    = (const float*)d_in[1];
    const float* W3     = (const float*)d_in[2];
    const float* b3     = (const float*)d_in[3];
    const float* W5     = (const float*)d_in[4];
    const float* b5     = (const float*)d_in[5];
    const float* W7     = (const float*)d_in[6];
    const float* b7     = (const float*)d_in[7];
    const float* conv1w = (const float*)d_in[8];
    const float* conv1b = (const float*)d_in[9];
    const float* bng    = (const float*)d_in[10];
    const float* bnb    = (const float*)d_in[11];
    const float* capsw  = (const float*)d_in[12];
    const float* capsb  = (const float*)d_in[13];
    const float* routeW = (const float*)d_in[14];
    const float* routeb = (const float*)d_in[15];
    const float* fc1    = (const float*)d_in[16];
    const float* bn1g   = (const float*)d_in[17];
    const float* bn1b   = (const float*)d_in[18];
    const float* fc2    = (const float*)d_in[19];
    const float* bn2g   = (const float*)d_in[20];
    const float* bn2b   = (const float*)d_in[21];
    const float* fc3    = (const float*)d_in[22];
    float* out = (float*)d_out;

    cudaFuncSetAttribute(conv1_kernel, cudaFuncAttributeMaxDynamicSharedMemorySize, CONV1_SMEM);
    cudaFuncSetAttribute(caps_kernel,  cudaFuncAttributeMaxDynamicSharedMemorySize, CAPS_SMEM);

    zero_kernel<<<1, 256>>>();
    embed_kernel<<<(BATCH * SEQ * 32) / 256, 256>>>(x, emb);
    pl_kernel<3><<<dim3(32, 41), 256>>>(W3, b3, 0);   // A -> B
    pl_kernel<5><<<dim3(32, 41), 256>>>(W5, b5, 1);   // B -> A
    pl_kernel<7><<<dim3(32, 41), 256>>>(W7, b7, 0);   // A -> B
    conv1_kernel<<<BATCH, 256, CONV1_SMEM>>>(conv1w, conv1b);   // B -> A (raw)
    bn_reduce_kernel<<<dim3(64, 32), 256>>>();
    bn_fin_conv<<<1, 64>>>(bng, bnb);
    caps_kernel<<<BATCH, 256, CAPS_SMEM>>>(capsw, capsb);       // A -> B (squashed)
    route_kernel<<<BATCH, 256>>>(routeW, routeb, fc1);
    bn1_fin<<<1, 2>>>(bn1g, bn1b);
    head1_kernel<<<BATCH / 4, 256>>>(fc2);
    bn2_fin<<<1, 2>>>(bn2g, bn2b);
    head2_kernel<<<(BATCH + 255) / 256, 256>>>(fc3, out);
}

// round 4
// speedup vs baseline: 1.6880x; 1.6880x over previous
#include <cuda_runtime.h>
#include <cuda_bf16.h>
#include <math.h>
#include <stdint.h>

// ---------------------------------------------------------------------------
// Problem constants
// ---------------------------------------------------------------------------
#define BATCH 4096
#define SEQ   41
#define FDIM  128
#define SF    (SEQ*FDIM)        // 5248
#define C64L  (64*128)          // 8192

// ---------------------------------------------------------------------------
// Scratch (device globals; allocation-free contract)
// ---------------------------------------------------------------------------
__device__ __align__(256) float  g_bufA[(size_t)BATCH * C64L];
__device__ __align__(256) float  g_bufB[(size_t)BATCH * C64L];
__device__ __align__(256) float  g_g1[(size_t)BATCH * 128];   // [B,2,64]
__device__ __align__(256) float  g_g2[(size_t)BATCH * 64];    // [B,2,32]
__device__ double g_bnsum[64], g_bnsq[64];
__device__ float  g_bnscale[64], g_bnshift[64];
__device__ double g_bn1acc[4];
__device__ double g_bn2acc[4];
__device__ float  g_bn1p[4];
__device__ float  g_bn2p[4];

// split-precision activation ping-pong buffers [B,41,128]
__device__ __align__(256) __nv_bfloat16 g_aHi0[(size_t)BATCH * SF];
__device__ __align__(256) __nv_bfloat16 g_aLo0[(size_t)BATCH * SF];
__device__ __align__(256) __nv_bfloat16 g_aHi1[(size_t)BATCH * SF];
__device__ __align__(256) __nv_bfloat16 g_aLo1[(size_t)BATCH * SF];

// transposed + split weights: layout [s][n=128][K] bf16, layers packed
#define WOFF3 ((size_t)0)
#define WOFF5 ((size_t)41*384*128)
#define WOFF7 ((size_t)(41*384*128) + (size_t)41*640*128)
#define WTOT  ((size_t)41*1920*128)
__device__ __align__(256) __nv_bfloat16 g_wHi[WTOT];
__device__ __align__(256) __nv_bfloat16 g_wLo[WTOT];

// single shared extern symbol for all dynamic-smem kernels
extern __shared__ __align__(1024) char sm_raw[];

__device__ __forceinline__ float* bufsel(int which) {
    return which ? g_bufB : g_bufA;
}

__device__ __forceinline__ float squash_factor(float ssq) {
    float n = sqrtf(ssq);
    return (1.f - 1.f / (expf(n) + 1e-21f)) / (n + 1e-21f);
}

__device__ __forceinline__ uint32_t bpack(__nv_bfloat16 a, __nv_bfloat16 b) {
    __nv_bfloat162 t = __halves2bfloat162(a, b);
    return *reinterpret_cast<uint32_t*>(&t);
}

// ---------------------------------------------------------------------------
// PTX helpers (compute_100-safe: mma.sync + cp.async only)
// ---------------------------------------------------------------------------
__device__ __forceinline__ uint32_t smem_u32(const void* p) {
    uint32_t a;
    asm("{ .reg .u64 t; cvta.to.shared.u64 t, %1; cvt.u32.u64 %0, t; }" : "=r"(a) : "l"(p));
    return a;
}
__device__ __forceinline__ uint32_t lds32(uint32_t a) {
    uint32_t v;
    asm volatile("ld.shared.b32 %0, [%1];" : "=r"(v) : "r"(a));
    return v;
}
__device__ __forceinline__ void mma_bf16(float* c, const uint32_t* a, const uint32_t* b) {
    asm volatile(
        "mma.sync.aligned.m16n8k16.row.col.f32.bf16.bf16.f32 "
        "{%0,%1,%2,%3}, {%4,%5,%6,%7}, {%8,%9}, {%0,%1,%2,%3};"
        : "+f"(c[0]), "+f"(c[1]), "+f"(c[2]), "+f"(c[3])
        : "r"(a[0]), "r"(a[1]), "r"(a[2]), "r"(a[3]), "r"(b[0]), "r"(b[1]));
}
#define CP16(dst, src)    asm volatile("cp.async.cg.shared.global [%0], [%1], 16;" :: "r"(dst), "l"(src))
#define CP_COMMIT()       asm volatile("cp.async.commit_group;" ::: "memory")

// ---------------------------------------------------------------------------
// 0. zero accumulators
// ---------------------------------------------------------------------------
__global__ void zero_kernel() {
    int t = threadIdx.x;
    if (t < 64) { g_bnsum[t] = 0.0; g_bnsq[t] = 0.0; }
    if (t < 4)  { g_bn1acc[t] = 0.0; g_bn2acc[t] = 0.0; }
}

// ---------------------------------------------------------------------------
// 1. embedding gather -> (hi, lo) pair buffers 0
// ---------------------------------------------------------------------------
__global__ void embed_pair_kernel(const int* __restrict__ x, const float* __restrict__ emb) {
    int gid = blockIdx.x * 256 + threadIdx.x;
    int pos = gid >> 5;
    int f0  = (gid & 31) * 4;
    if (pos >= BATCH * SEQ) return;
    int e = x[pos];
    float4 v = *reinterpret_cast<const float4*>(emb + e * FDIM + f0);
    __nv_bfloat16 h0 = __float2bfloat16(v.x), h1 = __float2bfloat16(v.y);
    __nv_bfloat16 h2 = __float2bfloat16(v.z), h3 = __float2bfloat16(v.w);
    __nv_bfloat16 l0 = __float2bfloat16(v.x - __bfloat162float(h0));
    __nv_bfloat16 l1 = __float2bfloat16(v.y - __bfloat162float(h1));
    __nv_bfloat16 l2 = __float2bfloat16(v.z - __bfloat162float(h2));
    __nv_bfloat16 l3 = __float2bfloat16(v.w - __bfloat162float(h3));
    size_t off = (size_t)pos * FDIM + f0;
    *reinterpret_cast<uint2*>(g_aHi0 + off) = make_uint2(bpack(h0, h1), bpack(h2, h3));
    *reinterpret_cast<uint2*>(g_aLo0 + off) = make_uint2(bpack(l0, l1), bpack(l2, l3));
}

// ---------------------------------------------------------------------------
// 1b. weight prep: transpose [s][K][128] fp32 -> [s][128][K] bf16 hi/lo
// ---------------------------------------------------------------------------
__global__ void wprep_kernel(const float* __restrict__ W,
                             __nv_bfloat16* __restrict__ oH,
                             __nv_bfloat16* __restrict__ oL, int K) {
    __shared__ float tile[32][129];
    int s = blockIdx.y, kb = blockIdx.x * 32, t = threadIdx.x;
#pragma unroll
    for (int i = 0; i < 16; i++) {
        int e = t + i * 256;
        int kk = e >> 7, n = e & 127;
        tile[kk][n] = W[((size_t)s * K + kb + kk) * 128 + n];
    }
    __syncthreads();
    int n = t >> 1, h = (t & 1) * 16;
    size_t ob = ((size_t)(s * 128 + n)) * K + kb + h;
#pragma unroll
    for (int kk = 0; kk < 16; kk++) {
        float v = tile[h + kk][n];
        __nv_bfloat16 hh = __float2bfloat16(v);
        oH[ob + kk] = hh;
        oL[ob + kk] = __float2bfloat16(v - __bfloat162float(hh));
    }
}

// ---------------------------------------------------------------------------
// 2-4. position_linear via warp-level bf16 split-precision MMA.
//   CTA: M=128 (batch rows) x N=128.  8 warps in 2(M) x 4(N); warp tile 64x32.
//   K streamed in 32-element chunks; 2-stage cp.async double buffer.
//   smem per stage: Ahi, Alo, Bhi, Blo each [128 rows][32 k] bf16 = 8192 B,
//   row = 64 B = 4 x 16B chunks, chunk-XOR swizzle (chunk ^ (row&3)).
// ---------------------------------------------------------------------------
#define PL_SMEM (2 * 4 * 8192)   // 65536

template<int WIN, int OUTF32>
__global__ void __launch_bounds__(256, 2)
pl_wmma_kernel(const __nv_bfloat16* __restrict__ aHi, const __nv_bfloat16* __restrict__ aLo,
               const __nv_bfloat16* __restrict__ wHi, const __nv_bfloat16* __restrict__ wLo,
               const float* __restrict__ bst,
               __nv_bfloat16* __restrict__ oHi, __nv_bfloat16* __restrict__ oLo,
               float* __restrict__ of32)
{
    constexpr int P = WIN / 2;
    constexpr int K = WIN * 128;
    const uint32_t smb = smem_u32(sm_raw);
    const int s   = blockIdx.y;
    const int bm  = blockIdx.x * 128;
    const int tid = threadIdx.x;
    const int warp = tid >> 5, lane = tid & 31;
    const int warp_m = warp >> 2, warp_n = warp & 3;
    const int gid = lane >> 2, tg = lane & 3;

    const int j0 = (P - s) > 0 ? (P - s) : 0;
    const int j1 = (WIN - 1) < (P + SEQ - 1 - s) ? (WIN - 1) : (P + SEQ - 1 - s);
    const int nst = (j1 - j0 + 1) * 4;     // k32 stages

    float acc[4][4][4];
#pragma unroll
    for (int a = 0; a < 4; a++)
#pragma unroll
        for (int b = 0; b < 4; b++)
#pragma unroll
            for (int c = 0; c < 4; c++) acc[a][b][c] = 0.f;

    // ---- stage loader (cp.async) ----
    auto load_stage = [&](int st, int buf) {
        const int jj = j0 + (st >> 2);
        const int f0 = (st & 3) * 32;
        const int tsrc = s + jj - P;
        const int k0 = jj * 128 + f0;
        const uint32_t sb = smb + buf * 32768;
#pragma unroll
        for (int i = 0; i < 2; i++) {
            int idx = tid + i * 256;          // 0..511
            int row = idx >> 2, cs = idx & 3;
            uint32_t d = sb + row * 64 + (((cs ^ (row & 3)) << 4));
            size_t aoff = ((size_t)(bm + row) * SEQ + tsrc) * 128 + f0 + cs * 8;
            size_t boff = ((size_t)(s * 128 + row)) * K + k0 + cs * 8;
            CP16(d,         (const char*)(aHi + aoff));
            CP16(d +  8192, (const char*)(aLo + aoff));
            CP16(d + 16384, (const char*)(wHi + boff));
            CP16(d + 24576, (const char*)(wLo + boff));
        }
        CP_COMMIT();
    };

    load_stage(0, 0);

    for (int st = 0; st < nst; st++) {
        if (st + 1 < nst) {
            load_stage(st + 1, (st + 1) & 1);
            asm volatile("cp.async.wait_group 1;" ::: "memory");
        } else {
            asm volatile("cp.async.wait_group 0;" ::: "memory");
        }
        __syncthreads();

        const uint32_t ab = smb + (st & 1) * 32768;
#pragma unroll
        for (int kt = 0; kt < 2; kt++) {
            uint32_t bh[4][2], bl[4][2];
#pragma unroll
            for (int nt = 0; nt < 4; nt++) {
                int br = warp_n * 32 + nt * 8 + gid;
                uint32_t base = ab + 16384 + br * 64 + tg * 4;
                int sw = br & 3;
                bh[nt][0] = lds32(base + (((kt * 2 + 0) ^ sw) << 4));
                bh[nt][1] = lds32(base + (((kt * 2 + 1) ^ sw) << 4));
                bl[nt][0] = lds32(base + 8192 + (((kt * 2 + 0) ^ sw) << 4));
                bl[nt][1] = lds32(base + 8192 + (((kt * 2 + 1) ^ sw) << 4));
            }
#pragma unroll
            for (int mt = 0; mt < 4; mt++) {
                int r0 = warp_m * 64 + mt * 16 + gid;
                int r1 = r0 + 8;
                uint32_t b0 = ab + r0 * 64 + tg * 4, s0 = r0 & 3;
                uint32_t b1 = ab + r1 * 64 + tg * 4, s1 = r1 & 3;
                uint32_t ah[4], al[4];
                ah[0] = lds32(b0 + (((kt * 2 + 0) ^ s0) << 4));
                ah[1] = lds32(b1 + (((kt * 2 + 0) ^ s1) << 4));
                ah[2] = lds32(b0 + (((kt * 2 + 1) ^ s0) << 4));
                ah[3] = lds32(b1 + (((kt * 2 + 1) ^ s1) << 4));
                al[0] = lds32(b0 + 8192 + (((kt * 2 + 0) ^ s0) << 4));
                al[1] = lds32(b1 + 8192 + (((kt * 2 + 0) ^ s1) << 4));
                al[2] = lds32(b0 + 8192 + (((kt * 2 + 1) ^ s0) << 4));
                al[3] = lds32(b1 + 8192 + (((kt * 2 + 1) ^ s1) << 4));
#pragma unroll
                for (int nt = 0; nt < 4; nt++) {
                    mma_bf16(acc[mt][nt], ah, bh[nt]);
                    mma_bf16(acc[mt][nt], al, bh[nt]);
                    mma_bf16(acc[mt][nt], ah, bl[nt]);
                }
            }
        }
        __syncthreads();
    }

    // ---- epilogue: bias + relu; write fp32 or split bf16 ----
    const float* bias = bst + s * 128;
#pragma unroll
    for (int mt = 0; mt < 4; mt++) {
        int rbase = warp_m * 64 + mt * 16 + gid;
#pragma unroll
        for (int half = 0; half < 2; half++) {
            int r = rbase + half * 8;
            size_t ob = ((size_t)(bm + r) * SEQ + s) * 128;
#pragma unroll
            for (int nt = 0; nt < 4; nt++) {
                int col = warp_n * 32 + nt * 8 + tg * 2;
                float v0 = fmaxf(acc[mt][nt][half * 2 + 0] + bias[col],     0.f);
                float v1 = fmaxf(acc[mt][nt][half * 2 + 1] + bias[col + 1], 0.f);
                if (OUTF32) {
                    float2 v = make_float2(v0, v1);
                    *reinterpret_cast<float2*>(of32 + ob + col) = v;
                } else {
                    __nv_bfloat16 h0 = __float2bfloat16(v0), h1 = __float2bfloat16(v1);
                    *reinterpret_cast<uint32_t*>(oHi + ob + col) = bpack(h0, h1);
                    *reinterpret_cast<uint32_t*>(oLo + ob + col) =
                        bpack(__float2bfloat16(v0 - __bfloat162float(h0)),
                              __float2bfloat16(v1 - __bfloat162float(h1)));
                }
            }
        }
    }
}

// ---------------------------------------------------------------------------
// 5. conv1d: in bufB [B,41,128], w [64,41,3], pad 1 -> bufA [B,64,128]
// ---------------------------------------------------------------------------
#define CONV1_SMEM ((41*130 + 64*123) * 4)
__global__ void conv1_kernel(const float* __restrict__ w, const float* __restrict__ bias) {
    float* sm = reinterpret_cast<float*>(sm_raw);
    float* xin = sm;
    float* ws  = sm + 41 * 130;
    const float* __restrict__ in = bufsel(1);
    float* __restrict__ out = bufsel(0);

    int b = blockIdx.x, t = threadIdx.x;
    const float* src = in + (size_t)b * SF;
    for (int idx = t; idx < SF; idx += 256) {
        int c = idx >> 7, l = idx & 127;
        xin[c * 130 + l + 1] = src[idx];
    }
    if (t < 41) { xin[t * 130] = 0.f; xin[t * 130 + 129] = 0.f; }
    for (int idx = t; idx < 64 * 123; idx += 256) ws[idx] = w[idx];
    __syncthreads();

    int og = t >> 4, lg = t & 15;
    int o0 = og * 4;
    float acc[4][8];
#pragma unroll
    for (int a = 0; a < 4; a++)
#pragma unroll
        for (int u = 0; u < 8; u++) acc[a][u] = 0.f;

    for (int c = 0; c < 41; c++) {
        const float* xr = xin + c * 130;
        float wl[4][3];
#pragma unroll
        for (int a = 0; a < 4; a++) {
            const float* wp = ws + (o0 + a) * 123 + c * 3;
            wl[a][0] = wp[0]; wl[a][1] = wp[1]; wl[a][2] = wp[2];
        }
#pragma unroll
        for (int u = 0; u < 8; u++) {
            int l = lg + 16 * u;
            float x0 = xr[l], x1 = xr[l + 1], x2 = xr[l + 2];
#pragma unroll
            for (int a = 0; a < 4; a++)
                acc[a][u] += x0 * wl[a][0] + x1 * wl[a][1] + x2 * wl[a][2];
        }
    }
    float* dst = out + (size_t)b * C64L;
#pragma unroll
    for (int a = 0; a < 4; a++) {
        float bb = bias[o0 + a];
#pragma unroll
        for (int u = 0; u < 8; u++)
            dst[(o0 + a) * 128 + lg + 16 * u] = acc[a][u] + bb;
    }
}

// ---------------------------------------------------------------------------
// 6. BN stats over (B, L) per channel
// ---------------------------------------------------------------------------
__global__ void bn_reduce_kernel() {
    const float* __restrict__ x = bufsel(0);
    int c  = blockIdx.x;
    int b0 = blockIdx.y * 128;
    int t  = threadIdx.x;
    double s = 0.0, q = 0.0;
    for (int it = 0; it < 64; it++) {
        int idx = t + it * 256;
        int bl = idx >> 7, l = idx & 127;
        float v = x[((size_t)(b0 + bl)) * C64L + c * 128 + l];
        s += v; q += (double)v * v;
    }
    for (int off = 16; off; off >>= 1) {
        s += __shfl_xor_sync(0xffffffffu, s, off);
        q += __shfl_xor_sync(0xffffffffu, q, off);
    }
    __shared__ double ss[8], qq[8];
    if ((t & 31) == 0) { ss[t >> 5] = s; qq[t >> 5] = q; }
    __syncthreads();
    if (t == 0) {
        double S = 0, Q = 0;
        for (int i = 0; i < 8; i++) { S += ss[i]; Q += qq[i]; }
        atomicAdd(&g_bnsum[c], S);
        atomicAdd(&g_bnsq[c], Q);
    }
}

__global__ void bn_fin_conv(const float* __restrict__ g, const float* __restrict__ bb) {
    int c = threadIdx.x;
    double inv = 1.0 / ((double)BATCH * 128.0);
    double mu = g_bnsum[c] * inv;
    double var = g_bnsq[c] * inv - mu * mu;
    float sc = g[c] * rsqrtf((float)var + 1e-5f);
    g_bnscale[c] = sc;
    g_bnshift[c] = bb[c] - (float)mu * sc;
}

// ---------------------------------------------------------------------------
// 8. caps conv (groups=2): BN+ReLU fused at load, squash fused in epi
// ---------------------------------------------------------------------------
#define CAPS_SMEM ((64*130 + 64*96 + 64*128) * 4)
__global__ void caps_kernel(const float* __restrict__ w, const float* __restrict__ cb) {
    float* sm = reinterpret_cast<float*>(sm_raw);
    float* xin  = sm;
    float* ws   = sm + 64 * 130;
    float* sout = sm + 64 * 130 + 64 * 96;
    const float* __restrict__ in = bufsel(0);
    float* __restrict__ out = bufsel(1);

    int b = blockIdx.x, t = threadIdx.x;
    const float* src = in + (size_t)b * C64L;
    for (int idx = t; idx < C64L; idx += 256) {
        int c = idx >> 7, l = idx & 127;
        float v = fmaxf(src[idx] * g_bnscale[c] + g_bnshift[c], 0.f);
        xin[c * 130 + l + 1] = v;
    }
    if (t < 64) { xin[t * 130] = 0.f; xin[t * 130 + 129] = 0.f; }
    for (int idx = t; idx < 64 * 96; idx += 256) ws[idx] = w[idx];
    __syncthreads();

    int og = t >> 4, lg = t & 15;
    int o0 = og * 4;
    int cbase = (o0 >= 32) ? 32 : 0;
    float acc[4][8];
#pragma unroll
    for (int a = 0; a < 4; a++)
#pragma unroll
        for (int u = 0; u < 8; u++) acc[a][u] = 0.f;

    for (int ci = 0; ci < 32; ci++) {
        const float* xr = xin + (cbase + ci) * 130;
        float wl[4][3];
#pragma unroll
        for (int a = 0; a < 4; a++) {
            const float* wp = ws + (o0 + a) * 96 + ci * 3;
            wl[a][0] = wp[0]; wl[a][1] = wp[1]; wl[a][2] = wp[2];
        }
#pragma unroll
        for (int u = 0; u < 8; u++) {
            int l = lg + 16 * u;
            float x0 = xr[l], x1 = xr[l + 1], x2 = xr[l + 2];
#pragma unroll
            for (int a = 0; a < 4; a++)
                acc[a][u] += x0 * wl[a][0] + x1 * wl[a][1] + x2 * wl[a][2];
        }
    }
#pragma unroll
    for (int a = 0; a < 4; a++) {
        float bb = cb[o0 + a];
#pragma unroll
        for (int u = 0; u < 8; u++)
            sout[(o0 + a) * 128 + lg + 16 * u] = acc[a][u] + bb;
    }
    __syncthreads();

    int wid = t >> 5, lane = t & 31;
    float* dst = out + (size_t)b * C64L;
    for (int rr = 0; rr < 8; rr++) {
        int o = wid * 8 + rr;
        float v0 = sout[o * 128 + lane];
        float v1 = sout[o * 128 + lane + 32];
        float v2 = sout[o * 128 + lane + 64];
        float v3 = sout[o * 128 + lane + 96];
        float ssq = v0 * v0 + v1 * v1 + v2 * v2 + v3 * v3;
        for (int off = 16; off; off >>= 1) ssq += __shfl_xor_sync(0xffffffffu, ssq, off);
        float factor = squash_factor(ssq);
        dst[o * 128 + lane]      = v0 * factor;
        dst[o * 128 + lane + 32] = v1 * factor;
        dst[o * 128 + lane + 64] = v2 * factor;
        dst[o * 128 + lane + 96] = v3 * factor;
    }
}

// ---------------------------------------------------------------------------
// 9. routing + squash + pair-max + fc1, bn1 partial stats
// ---------------------------------------------------------------------------
__global__ void route_kernel(const float* __restrict__ rW,
                             const float* __restrict__ rb,
                             const float* __restrict__ fc1)
{
    __shared__ float hs[64 * 128];
    __shared__ float sv_s[2][128];
    __shared__ float yv_s[2][128];
    __shared__ float warp_sq[8];
    __shared__ float factor_s[2];

    const float* __restrict__ h = bufsel(1);
    int b = blockIdx.x, t = threadIdx.x;
    const float* hb = h + (size_t)b * C64L;
    for (int idx = t; idx < C64L; idx += 256) hs[idx] = hb[idx];
    __syncthreads();

    int i = t >> 7;
    int f = t & 127;
    float acc = 0.f;
    const float* rwi = rW + i * 8192 + f;
    const float* rbi = rb + i * 64;
#pragma unroll 8
    for (int j = 0; j < 64; j++) {
        float cj = 1.0f + rbi[j];
        acc += hs[j * 128 + f] * rwi[j * 128] * cj;
    }
    float sq = acc * acc;
    for (int off = 16; off; off >>= 1) sq += __shfl_xor_sync(0xffffffffu, sq, off);
    if ((t & 31) == 0) warp_sq[t >> 5] = sq;
    __syncthreads();
    if (t < 2) {
        float tot = warp_sq[t * 4 + 0] + warp_sq[t * 4 + 1] + warp_sq[t * 4 + 2] + warp_sq[t * 4 + 3];
        factor_s[t] = squash_factor(tot);
    }
    __syncthreads();
    float svv = acc * factor_s[i];
    sv_s[i][f] = svv;
    __syncthreads();
    float y = sv_s[i][f] + fmaxf(sv_s[0][f], sv_s[1][f]);
    yv_s[i][f] = y;
    __syncthreads();

    if (t < 128) {
        int ii = t >> 6, o = t & 63;
        float a = 0.f;
        for (int ff = 0; ff < 128; ff++) a += yv_s[ii][ff] * fc1[ff * 64 + o];
        g_g1[(size_t)b * 128 + ii * 64 + o] = a;
        double s = a, q = (double)a * a;
        for (int off = 16; off; off >>= 1) {
            s += __shfl_xor_sync(0xffffffffu, s, off);
            q += __shfl_xor_sync(0xffffffffu, q, off);
        }
        if ((t & 31) == 0) {
            atomicAdd(&g_bn1acc[ii], s);
            atomicAdd(&g_bn1acc[2 + ii], q);
        }
    }
}

__global__ void bn1_fin(const float* __restrict__ g, const float* __restrict__ bb) {
    int i = threadIdx.x;
    double inv = 1.0 / ((double)BATCH * 64.0);
    double mu = g_bn1acc[i] * inv;
    double var = g_bn1acc[2 + i] * inv - mu * mu;
    float sc = g[i] * rsqrtf((float)var + 1e-5f);
    g_bn1p[i] = sc;
    g_bn1p[2 + i] = bb[i] - (float)mu * sc;
}

// ---------------------------------------------------------------------------
// 11. head1
// ---------------------------------------------------------------------------
__global__ void head1_kernel(const float* __restrict__ fc2) {
    __shared__ float a_s[4][128];
    int t = threadIdx.x;
    for (int idx = t; idx < 512; idx += 256) {
        int lbb = idx >> 7, rr = idx & 127;
        int ii = rr >> 6;
        float v = g_g1[(size_t)(blockIdx.x * 4 + lbb) * 128 + rr];
        a_s[lbb][rr] = fmaxf(v * g_bn1p[ii] + g_bn1p[2 + ii], 0.f);
    }
    __syncthreads();
    int lb = t >> 6, r = t & 63;
    int b = blockIdx.x * 4 + lb;
    int ii = r >> 5, m = r & 31;
    float acc = 0.f;
    const float* arow = &a_s[lb][ii * 64];
#pragma unroll 8
    for (int o = 0; o < 64; o++) acc += arow[o] * fc2[o * 32 + m];
    g_g2[(size_t)b * 64 + ii * 32 + m] = acc;
    double s = acc, q = (double)acc * acc;
    for (int off = 16; off; off >>= 1) {
        s += __shfl_xor_sync(0xffffffffu, s, off);
        q += __shfl_xor_sync(0xffffffffu, q, off);
    }
    if ((t & 31) == 0) {
        atomicAdd(&g_bn2acc[ii], s);
        atomicAdd(&g_bn2acc[2 + ii], q);
    }
}

__global__ void bn2_fin(const float* __restrict__ g, const float* __restrict__ bb) {
    int i = threadIdx.x;
    double inv = 1.0 / ((double)BATCH * 32.0);
    double mu = g_bn2acc[i] * inv;
    double var = g_bn2acc[2 + i] * inv - mu * mu;
    float sc = g[i] * rsqrtf((float)var + 1e-5f);
    g_bn2p[i] = sc;
    g_bn2p[2 + i] = bb[i] - (float)mu * sc;
}

// ---------------------------------------------------------------------------
// 13. head2
// ---------------------------------------------------------------------------
__global__ void head2_kernel(const float* __restrict__ fc3, float* __restrict__ out) {
    int b = blockIdx.x * 256 + threadIdx.x;
    if (b >= BATCH) return;
    float best = -1e30f;
#pragma unroll
    for (int i = 0; i < 2; i++) {
        float sc = g_bn2p[i], sh = g_bn2p[2 + i];
        float s = 0.f;
#pragma unroll
        for (int m = 0; m < 32; m++) {
            float v = fmaxf(g_g2[(size_t)b * 64 + i * 32 + m] * sc + sh, 0.f);
            s += v * fc3[m];
        }
        float sig = 1.f / (1.f + expf(-s));
        best = fmaxf(best, sig);
    }
    out[b] = best;
}

// ---------------------------------------------------------------------------
// launch
// ---------------------------------------------------------------------------
extern "C" void kernel_launch(void* const* d_in, const int* in_sizes, int n_in,
                              void* d_out, int out_size)
{
    const int*   x      = (const int*)d_in[0];
    const float* emb    = (const float*)d_in[1];
    const float* W3     = (const float*)d_in[2];
    const float* b3     = (const float*)d_in[3];
    const float* W5     = (const float*)d_in[4];
    const float* b5     = (const float*)d_in[5];
    const float* W7     = (const float*)d_in[6];
    const float* b7     = (const float*)d_in[7];
    const float* conv1w = (const float*)d_in[8];
    const float* conv1b = (const float*)d_in[9];
    const float* bng    = (const float*)d_in[10];
    const float* bnb    = (const float*)d_in[11];
    const float* capsw  = (const float*)d_in[12];
    const float* capsb  = (const float*)d_in[13];
    const float* routeW = (const float*)d_in[14];
    const float* routeb = (const float*)d_in[15];
    const float* fc1    = (const float*)d_in[16];
    const float* bn1g   = (const float*)d_in[17];
    const float* bn1b   = (const float*)d_in[18];
    const float* fc2    = (const float*)d_in[19];
    const float* bn2g   = (const float*)d_in[20];
    const float* bn2b   = (const float*)d_in[21];
    const float* fc3    = (const float*)d_in[22];
    float* out = (float*)d_out;

    cudaFuncSetAttribute(conv1_kernel, cudaFuncAttributeMaxDynamicSharedMemorySize, CONV1_SMEM);
    cudaFuncSetAttribute(caps_kernel,  cudaFuncAttributeMaxDynamicSharedMemorySize, CAPS_SMEM);
    cudaFuncSetAttribute(pl_wmma_kernel<3,0>, cudaFuncAttributeMaxDynamicSharedMemorySize, PL_SMEM);
    cudaFuncSetAttribute(pl_wmma_kernel<5,0>, cudaFuncAttributeMaxDynamicSharedMemorySize, PL_SMEM);
    cudaFuncSetAttribute(pl_wmma_kernel<7,1>, cudaFuncAttributeMaxDynamicSharedMemorySize, PL_SMEM);

    __nv_bfloat16 *aHi0, *aLo0, *aHi1, *aLo1, *wHi, *wLo;
    cudaGetSymbolAddress((void**)&aHi0, g_aHi0);
    cudaGetSymbolAddress((void**)&aLo0, g_aLo0);
    cudaGetSymbolAddress((void**)&aHi1, g_aHi1);
    cudaGetSymbolAddress((void**)&aLo1, g_aLo1);
    cudaGetSymbolAddress((void**)&wHi,  g_wHi);
    cudaGetSymbolAddress((void**)&wLo,  g_wLo);
    float* bufB;
    cudaGetSymbolAddress((void**)&bufB, g_bufB);

    zero_kernel<<<1, 256>>>();
    embed_pair_kernel<<<(BATCH * SEQ * 32) / 256, 256>>>(x, emb);
    wprep_kernel<<<dim3(384 / 32, 41), 256>>>(W3, wHi + WOFF3, wLo + WOFF3, 384);
    wprep_kernel<<<dim3(640 / 32, 41), 256>>>(W5, wHi + WOFF5, wLo + WOFF5, 640);
    wprep_kernel<<<dim3(896 / 32, 41), 256>>>(W7, wHi + WOFF7, wLo + WOFF7, 896);

    pl_wmma_kernel<3,0><<<dim3(32, 41), 256, PL_SMEM>>>(aHi0, aLo0, wHi + WOFF3, wLo + WOFF3, b3,
                                                        aHi1, aLo1, nullptr);
    pl_wmma_kernel<5,0><<<dim3(32, 41), 256, PL_SMEM>>>(aHi1, aLo1, wHi + WOFF5, wLo + WOFF5, b5,
                                                        aHi0, aLo0, nullptr);
    pl_wmma_kernel<7,1><<<dim3(32, 41), 256, PL_SMEM>>>(aHi0, aLo0, wHi + WOFF7, wLo + WOFF7, b7,
                                                        nullptr, nullptr, bufB);

    conv1_kernel<<<BATCH, 256, CONV1_SMEM>>>(conv1w, conv1b);
    bn_reduce_kernel<<<dim3(64, 32), 256>>>();
    bn_fin_conv<<<1, 64>>>(bng, bnb);
    caps_kernel<<<BATCH, 256, CAPS_SMEM>>>(capsw, capsb);
    route_kernel<<<BATCH, 256>>>(routeW, routeb, fc1);
    bn1_fin<<<1, 2>>>(bn1g, bn1b);
    head1_kernel<<<BATCH / 4, 256>>>(fc2);
    bn2_fin<<<1, 2>>>(bn2g, bn2b);
    head2_kernel<<<(BATCH + 255) / 256, 256>>>(fc3, out);
}

// round 5
// speedup vs baseline: 2.5172x; 1.4912x over previous
#include <cuda_runtime.h>
#include <cuda_fp16.h>
#include <math.h>
#include <stdint.h>

// ---------------------------------------------------------------------------
// Problem constants
// ---------------------------------------------------------------------------
#define BATCH 4096
#define SEQ   41
#define FDIM  128
#define SF    (SEQ*FDIM)        // 5248
#define C64L  (64*128)          // 8192

// ---------------------------------------------------------------------------
// Scratch (device globals; allocation-free contract)
// ---------------------------------------------------------------------------
__device__ __align__(256) __half g_h0[(size_t)BATCH * SF];   // activation ping
__device__ __align__(256) __half g_h1[(size_t)BATCH * SF];   // activation pong
__device__ __align__(256) __half g_c[(size_t)BATCH * C64L];  // conv1 output
__device__ __align__(256) float  g_g1[(size_t)BATCH * 128];  // [B,2,64]
__device__ __align__(256) float  g_g2[(size_t)BATCH * 64];   // [B,2,32]
__device__ double g_bnsum[64], g_bnsq[64];
__device__ float  g_bnscale[64], g_bnshift[64];
__device__ double g_bn1acc[4];
__device__ double g_bn2acc[4];
__device__ float  g_bn1p[4];
__device__ float  g_bn2p[4];

// transposed fp16 weights: layout [s][n=128][K], layers packed
#define WOFF3 ((size_t)0)
#define WOFF5 ((size_t)41*384*128)
#define WOFF7 ((size_t)(41*384*128) + (size_t)41*640*128)
#define WTOT  ((size_t)41*1920*128)
__device__ __align__(256) __half g_w16[WTOT];

// single shared extern symbol for all dynamic-smem kernels
extern __shared__ __align__(1024) char sm_raw[];

__device__ __forceinline__ float squash_factor(float ssq) {
    float n = sqrtf(ssq);
    return (1.f - 1.f / (expf(n) + 1e-21f)) / (n + 1e-21f);
}

// ---------------------------------------------------------------------------
// PTX helpers (compute_100-safe: mma.sync + cp.async only)
// ---------------------------------------------------------------------------
__device__ __forceinline__ uint32_t smem_u32(const void* p) {
    uint32_t a;
    asm("{ .reg .u64 t; cvta.to.shared.u64 t, %1; cvt.u32.u64 %0, t; }" : "=r"(a) : "l"(p));
    return a;
}
__device__ __forceinline__ uint32_t lds32(uint32_t a) {
    uint32_t v;
    asm volatile("ld.shared.b32 %0, [%1];" : "=r"(v) : "r"(a));
    return v;
}
__device__ __forceinline__ void mma_f16(float* c, const uint32_t* a, const uint32_t* b) {
    asm volatile(
        "mma.sync.aligned.m16n8k16.row.col.f32.f16.f16.f32 "
        "{%0,%1,%2,%3}, {%4,%5,%6,%7}, {%8,%9}, {%0,%1,%2,%3};"
        : "+f"(c[0]), "+f"(c[1]), "+f"(c[2]), "+f"(c[3])
        : "r"(a[0]), "r"(a[1]), "r"(a[2]), "r"(a[3]), "r"(b[0]), "r"(b[1]));
}
#define CP16(dst, src)    asm volatile("cp.async.cg.shared.global [%0], [%1], 16;" :: "r"(dst), "l"(src))
#define CP_COMMIT()       asm volatile("cp.async.commit_group;" ::: "memory")

__device__ __forceinline__ uint32_t hpack(float a, float b) {
    __half2 t = __floats2half2_rn(a, b);
    return *reinterpret_cast<uint32_t*>(&t);
}

// ---------------------------------------------------------------------------
// 0. zero accumulators
// ---------------------------------------------------------------------------
__global__ void zero_kernel() {
    int t = threadIdx.x;
    if (t < 64) { g_bnsum[t] = 0.0; g_bnsq[t] = 0.0; }
    if (t < 4)  { g_bn1acc[t] = 0.0; g_bn2acc[t] = 0.0; }
}

// ---------------------------------------------------------------------------
// 1. embedding gather -> g_h0 fp16
// ---------------------------------------------------------------------------
__global__ void embed_kernel(const int* __restrict__ x, const float* __restrict__ emb) {
    int gid = blockIdx.x * 256 + threadIdx.x;
    int pos = gid >> 4;                 // 16 threads per row (8 f each)
    int f0  = (gid & 15) * 8;
    if (pos >= BATCH * SEQ) return;
    int e = x[pos];
    const float4* sp = reinterpret_cast<const float4*>(emb + e * FDIM + f0);
    float4 v0 = sp[0], v1 = sp[1];
    uint4 o;
    o.x = hpack(v0.x, v0.y); o.y = hpack(v0.z, v0.w);
    o.z = hpack(v1.x, v1.y); o.w = hpack(v1.z, v1.w);
    *reinterpret_cast<uint4*>(g_h0 + (size_t)pos * FDIM + f0) = o;
}

// ---------------------------------------------------------------------------
// 1b. weight prep: transpose [s][K][128] fp32 -> [s][128][K] fp16
// ---------------------------------------------------------------------------
__global__ void wprep_kernel(const float* __restrict__ W, __half* __restrict__ o, int K) {
    __shared__ float tile[32][129];
    int s = blockIdx.y, kb = blockIdx.x * 32, t = threadIdx.x;
#pragma unroll
    for (int i = 0; i < 16; i++) {
        int e = t + i * 256;
        int kk = e >> 7, n = e & 127;
        tile[kk][n] = W[((size_t)s * K + kb + kk) * 128 + n];
    }
    __syncthreads();
    int n = t >> 1, h = (t & 1) * 16;
    size_t ob = ((size_t)(s * 128 + n)) * K + kb + h;
#pragma unroll
    for (int kk = 0; kk < 16; kk += 2) {
        *reinterpret_cast<uint32_t*>(&o[ob + kk]) = hpack(tile[h + kk][n], tile[h + kk + 1][n]);
    }
}

// ---------------------------------------------------------------------------
// 2-4. position_linear via warp-level fp16 single-term MMA.
//   CTA: M=128 x N=128. 8 warps 2(M) x 4(N); warp tile 64x32.
//   K streamed in 32-chunks; 2-stage cp.async double buffer.
//   smem per stage: A, B each [128 rows][32 k] fp16 = 8192 B.
// ---------------------------------------------------------------------------
#define PL_SMEM (2 * 16384)   // 32768

template<int WIN>
__global__ void __launch_bounds__(256, 2)
pl_kernel(const __half* __restrict__ aIn, const __half* __restrict__ wIn,
          const float* __restrict__ bst, __half* __restrict__ aOut)
{
    constexpr int P = WIN / 2;
    constexpr int K = WIN * 128;
    const uint32_t smb = smem_u32(sm_raw);
    const int s   = blockIdx.y;
    const int bm  = blockIdx.x * 128;
    const int tid = threadIdx.x;
    const int warp = tid >> 5, lane = tid & 31;
    const int warp_m = warp >> 2, warp_n = warp & 3;
    const int gid = lane >> 2, tg = lane & 3;

    const int j0 = (P - s) > 0 ? (P - s) : 0;
    const int j1 = (WIN - 1) < (P + SEQ - 1 - s) ? (WIN - 1) : (P + SEQ - 1 - s);
    const int nst = (j1 - j0 + 1) * 4;     // k32 stages

    float acc[4][4][4];
#pragma unroll
    for (int a = 0; a < 4; a++)
#pragma unroll
        for (int b = 0; b < 4; b++)
#pragma unroll
            for (int c = 0; c < 4; c++) acc[a][b][c] = 0.f;

    auto load_stage = [&](int st, int buf) {
        const int jj = j0 + (st >> 2);
        const int f0 = (st & 3) * 32;
        const int tsrc = s + jj - P;
        const int k0 = jj * 128 + f0;
        const uint32_t sb = smb + buf * 16384;
#pragma unroll
        for (int i = 0; i < 2; i++) {
            int idx = tid + i * 256;          // 0..511
            int row = idx >> 2, cs = idx & 3;
            uint32_t d = sb + row * 64 + (((cs ^ (row & 3)) << 4));
            size_t aoff = ((size_t)(bm + row) * SEQ + tsrc) * 128 + f0 + cs * 8;
            size_t boff = ((size_t)(s * 128 + row)) * K + k0 + cs * 8;
            CP16(d,        (const char*)(aIn + aoff));
            CP16(d + 8192, (const char*)(wIn + boff));
        }
        CP_COMMIT();
    };

    load_stage(0, 0);

    for (int st = 0; st < nst; st++) {
        if (st + 1 < nst) {
            load_stage(st + 1, (st + 1) & 1);
            asm volatile("cp.async.wait_group 1;" ::: "memory");
        } else {
            asm volatile("cp.async.wait_group 0;" ::: "memory");
        }
        __syncthreads();

        const uint32_t ab = smb + (st & 1) * 16384;
#pragma unroll
        for (int kt = 0; kt < 2; kt++) {
            uint32_t bf[4][2];
#pragma unroll
            for (int nt = 0; nt < 4; nt++) {
                int br = warp_n * 32 + nt * 8 + gid;
                uint32_t base = ab + 8192 + br * 64 + tg * 4;
                int sw = br & 3;
                bf[nt][0] = lds32(base + (((kt * 2 + 0) ^ sw) << 4));
                bf[nt][1] = lds32(base + (((kt * 2 + 1) ^ sw) << 4));
            }
#pragma unroll
            for (int mt = 0; mt < 4; mt++) {
                int r0 = warp_m * 64 + mt * 16 + gid;
                int r1 = r0 + 8;
                uint32_t b0 = ab + r0 * 64 + tg * 4; int s0 = r0 & 3;
                uint32_t b1 = ab + r1 * 64 + tg * 4; int s1 = r1 & 3;
                uint32_t af[4];
                af[0] = lds32(b0 + (((kt * 2 + 0) ^ s0) << 4));
                af[1] = lds32(b1 + (((kt * 2 + 0) ^ s1) << 4));
                af[2] = lds32(b0 + (((kt * 2 + 1) ^ s0) << 4));
                af[3] = lds32(b1 + (((kt * 2 + 1) ^ s1) << 4));
#pragma unroll
                for (int nt = 0; nt < 4; nt++)
                    mma_f16(acc[mt][nt], af, bf[nt]);
            }
        }
        __syncthreads();
    }

    // ---- epilogue: bias + relu; write fp16 ----
    const float* bias = bst + s * 128;
#pragma unroll
    for (int mt = 0; mt < 4; mt++) {
        int rbase = warp_m * 64 + mt * 16 + gid;
#pragma unroll
        for (int half = 0; half < 2; half++) {
            int r = rbase + half * 8;
            size_t ob = ((size_t)(bm + r) * SEQ + s) * 128;
#pragma unroll
            for (int nt = 0; nt < 4; nt++) {
                int col = warp_n * 32 + nt * 8 + tg * 2;
                float v0 = fmaxf(acc[mt][nt][half * 2 + 0] + bias[col],     0.f);
                float v1 = fmaxf(acc[mt][nt][half * 2 + 1] + bias[col + 1], 0.f);
                *reinterpret_cast<uint32_t*>(aOut + ob + col) = hpack(v0, v1);
            }
        }
    }
}

// ---------------------------------------------------------------------------
// 5. conv1d + fused BN partial stats:
//    in g_h1 [B,41,128] fp16, w [64,41,3], pad 1 -> g_c [B,64,128] fp16
// ---------------------------------------------------------------------------
#define CONV1_SMEM ((41*130 + 64*123) * 4)
__global__ void conv1_kernel(const float* __restrict__ w, const float* __restrict__ bias) {
    float* sm = reinterpret_cast<float*>(sm_raw);
    float* xin = sm;
    float* ws  = sm + 41 * 130;

    int b = blockIdx.x, t = threadIdx.x;
    const __half* src = g_h1 + (size_t)b * SF;
    for (int idx = t; idx < SF; idx += 256) {
        int c = idx >> 7, l = idx & 127;
        xin[c * 130 + l + 1] = __half2float(src[idx]);
    }
    if (t < 41) { xin[t * 130] = 0.f; xin[t * 130 + 129] = 0.f; }
    for (int idx = t; idx < 64 * 123; idx += 256) ws[idx] = w[idx];
    __syncthreads();

    int og = t >> 4, lg = t & 15;
    int o0 = og * 4;
    float acc[4][8];
#pragma unroll
    for (int a = 0; a < 4; a++)
#pragma unroll
        for (int u = 0; u < 8; u++) acc[a][u] = 0.f;

    for (int c = 0; c < 41; c++) {
        const float* xr = xin + c * 130;
        float wl[4][3];
#pragma unroll
        for (int a = 0; a < 4; a++) {
            const float* wp = ws + (o0 + a) * 123 + c * 3;
            wl[a][0] = wp[0]; wl[a][1] = wp[1]; wl[a][2] = wp[2];
        }
#pragma unroll
        for (int u = 0; u < 8; u++) {
            int l = lg + 16 * u;
            float x0 = xr[l], x1 = xr[l + 1], x2 = xr[l + 2];
#pragma unroll
            for (int a = 0; a < 4; a++)
                acc[a][u] += x0 * wl[a][0] + x1 * wl[a][1] + x2 * wl[a][2];
        }
    }
    __half* dst = g_c + (size_t)b * C64L;
    float sa[4], qa[4];
#pragma unroll
    for (int a = 0; a < 4; a++) {
        float bb = bias[o0 + a];
        sa[a] = 0.f; qa[a] = 0.f;
#pragma unroll
        for (int u = 0; u < 8; u++) {
            float v = acc[a][u] + bb;
            dst[(o0 + a) * 128 + lg + 16 * u] = __float2half(v);
            sa[a] += v;
            qa[a] += v * v;
        }
    }
    // reduce over 16 lanes (same channel group stays within half-warp)
#pragma unroll
    for (int a = 0; a < 4; a++) {
#pragma unroll
        for (int off = 8; off; off >>= 1) {
            sa[a] += __shfl_xor_sync(0xffffffffu, sa[a], off);
            qa[a] += __shfl_xor_sync(0xffffffffu, qa[a], off);
        }
    }
    if (lg == 0) {
#pragma unroll
        for (int a = 0; a < 4; a++) {
            atomicAdd(&g_bnsum[o0 + a], (double)sa[a]);
            atomicAdd(&g_bnsq[o0 + a],  (double)qa[a]);
        }
    }
}

__global__ void bn_fin_conv(const float* __restrict__ g, const float* __restrict__ bb) {
    int c = threadIdx.x;
    double inv = 1.0 / ((double)BATCH * 128.0);
    double mu = g_bnsum[c] * inv;
    double var = g_bnsq[c] * inv - mu * mu;
    float sc = g[c] * rsqrtf((float)var + 1e-5f);
    g_bnscale[c] = sc;
    g_bnshift[c] = bb[c] - (float)mu * sc;
}

// ---------------------------------------------------------------------------
// 8-9. FUSED: caps conv (groups=2, BN+ReLU at load) + squash (in smem)
//      + routing + squash + pair-max + fc1 -> g_g1 + bn1 partial stats
// ---------------------------------------------------------------------------
#define CR_SMEM ((64*130 + 64*96 + 64*128) * 4)
__global__ void capsroute_kernel(const float* __restrict__ w, const float* __restrict__ cb,
                                 const float* __restrict__ rW, const float* __restrict__ rb,
                                 const float* __restrict__ fc1)
{
    float* sm = reinterpret_cast<float*>(sm_raw);
    float* xin  = sm;                     // 64*130
    float* ws   = sm + 64 * 130;          // 64*96
    float* sout = sm + 64 * 130 + 64 * 96; // 64*128  (becomes squashed h)
    __shared__ float warp_sq[8];
    __shared__ float factor_s[2];
    __shared__ float sv_s[2][128];
    __shared__ float yv_s[2][128];

    int b = blockIdx.x, t = threadIdx.x;
    const __half* src = g_c + (size_t)b * C64L;
    for (int idx = t; idx < C64L; idx += 256) {
        int c = idx >> 7, l = idx & 127;
        float v = fmaxf(__half2float(src[idx]) * g_bnscale[c] + g_bnshift[c], 0.f);
        xin[c * 130 + l + 1] = v;
    }
    if (t < 64) { xin[t * 130] = 0.f; xin[t * 130 + 129] = 0.f; }
    for (int idx = t; idx < 64 * 96; idx += 256) ws[idx] = w[idx];
    __syncthreads();

    {
        int og = t >> 4, lg = t & 15;
        int o0 = og * 4;
        int cbase = (o0 >= 32) ? 32 : 0;
        float acc[4][8];
#pragma unroll
        for (int a = 0; a < 4; a++)
#pragma unroll
            for (int u = 0; u < 8; u++) acc[a][u] = 0.f;

        for (int ci = 0; ci < 32; ci++) {
            const float* xr = xin + (cbase + ci) * 130;
            float wl[4][3];
#pragma unroll
            for (int a = 0; a < 4; a++) {
                const float* wp = ws + (o0 + a) * 96 + ci * 3;
                wl[a][0] = wp[0]; wl[a][1] = wp[1]; wl[a][2] = wp[2];
            }
#pragma unroll
            for (int u = 0; u < 8; u++) {
                int l = lg + 16 * u;
                float x0 = xr[l], x1 = xr[l + 1], x2 = xr[l + 2];
#pragma unroll
                for (int a = 0; a < 4; a++)
                    acc[a][u] += x0 * wl[a][0] + x1 * wl[a][1] + x2 * wl[a][2];
            }
        }
#pragma unroll
        for (int a = 0; a < 4; a++) {
            float bb = cb[o0 + a];
#pragma unroll
            for (int u = 0; u < 8; u++)
                sout[(o0 + a) * 128 + lg + 16 * u] = acc[a][u] + bb;
        }
    }
    __syncthreads();

    // squash each of 64 rows (in place)
    {
        int wid = t >> 5, lane = t & 31;
        for (int rr = 0; rr < 8; rr++) {
            int o = wid * 8 + rr;
            float v0 = sout[o * 128 + lane];
            float v1 = sout[o * 128 + lane + 32];
            float v2 = sout[o * 128 + lane + 64];
            float v3 = sout[o * 128 + lane + 96];
            float ssq = v0 * v0 + v1 * v1 + v2 * v2 + v3 * v3;
            for (int off = 16; off; off >>= 1) ssq += __shfl_xor_sync(0xffffffffu, ssq, off);
            float factor = squash_factor(ssq);
            sout[o * 128 + lane]      = v0 * factor;
            sout[o * 128 + lane + 32] = v1 * factor;
            sout[o * 128 + lane + 64] = v2 * factor;
            sout[o * 128 + lane + 96] = v3 * factor;
        }
    }
    __syncthreads();

    // routing + squash + pair-max
    int i = t >> 7;
    int f = t & 127;
    float acc = 0.f;
    const float* rwi = rW + i * 8192 + f;
    const float* rbi = rb + i * 64;
#pragma unroll 8
    for (int j = 0; j < 64; j++) {
        float cj = 1.0f + rbi[j];
        acc += sout[j * 128 + f] * rwi[j * 128] * cj;
    }
    float sq = acc * acc;
    for (int off = 16; off; off >>= 1) sq += __shfl_xor_sync(0xffffffffu, sq, off);
    if ((t & 31) == 0) warp_sq[t >> 5] = sq;
    __syncthreads();
    if (t < 2) {
        float tot = warp_sq[t * 4 + 0] + warp_sq[t * 4 + 1] + warp_sq[t * 4 + 2] + warp_sq[t * 4 + 3];
        factor_s[t] = squash_factor(tot);
    }
    __syncthreads();
    float svv = acc * factor_s[i];
    sv_s[i][f] = svv;
    __syncthreads();
    float y = sv_s[i][f] + fmaxf(sv_s[0][f], sv_s[1][f]);
    yv_s[i][f] = y;
    __syncthreads();

    if (t < 128) {
        int ii = t >> 6, o = t & 63;
        float a = 0.f;
        for (int ff = 0; ff < 128; ff++) a += yv_s[ii][ff] * fc1[ff * 64 + o];
        g_g1[(size_t)b * 128 + ii * 64 + o] = a;
        double s = a, q = (double)a * a;
        for (int off = 16; off; off >>= 1) {
            s += __shfl_xor_sync(0xffffffffu, s, off);
            q += __shfl_xor_sync(0xffffffffu, q, off);
        }
        if ((t & 31) == 0) {
            atomicAdd(&g_bn1acc[ii], s);
            atomicAdd(&g_bn1acc[2 + ii], q);
        }
    }
}

__global__ void bn1_fin(const float* __restrict__ g, const float* __restrict__ bb) {
    int i = threadIdx.x;
    double inv = 1.0 / ((double)BATCH * 64.0);
    double mu = g_bn1acc[i] * inv;
    double var = g_bn1acc[2 + i] * inv - mu * mu;
    float sc = g[i] * rsqrtf((float)var + 1e-5f);
    g_bn1p[i] = sc;
    g_bn1p[2 + i] = bb[i] - (float)mu * sc;
}

// ---------------------------------------------------------------------------
// 11. head1
// ---------------------------------------------------------------------------
__global__ void head1_kernel(const float* __restrict__ fc2) {
    __shared__ float a_s[4][128];
    int t = threadIdx.x;
    for (int idx = t; idx < 512; idx += 256) {
        int lbb = idx >> 7, rr = idx & 127;
        int ii = rr >> 6;
        float v = g_g1[(size_t)(blockIdx.x * 4 + lbb) * 128 + rr];
        a_s[lbb][rr] = fmaxf(v * g_bn1p[ii] + g_bn1p[2 + ii], 0.f);
    }
    __syncthreads();
    int lb = t >> 6, r = t & 63;
    int b = blockIdx.x * 4 + lb;
    int ii = r >> 5, m = r & 31;
    float acc = 0.f;
    const float* arow = &a_s[lb][ii * 64];
#pragma unroll 8
    for (int o = 0; o < 64; o++) acc += arow[o] * fc2[o * 32 + m];
    g_g2[(size_t)b * 64 + ii * 32 + m] = acc;
    double s = acc, q = (double)acc * acc;
    for (int off = 16; off; off >>= 1) {
        s += __shfl_xor_sync(0xffffffffu, s, off);
        q += __shfl_xor_sync(0xffffffffu, q, off);
    }
    if ((t & 31) == 0) {
        atomicAdd(&g_bn2acc[ii], s);
        atomicAdd(&g_bn2acc[2 + ii], q);
    }
}

__global__ void bn2_fin(const float* __restrict__ g, const float* __restrict__ bb) {
    int i = threadIdx.x;
    double inv = 1.0 / ((double)BATCH * 32.0);
    double mu = g_bn2acc[i] * inv;
    double var = g_bn2acc[2 + i] * inv - mu * mu;
    float sc = g[i] * rsqrtf((float)var + 1e-5f);
    g_bn2p[i] = sc;
    g_bn2p[2 + i] = bb[i] - (float)mu * sc;
}

// ---------------------------------------------------------------------------
// 13. head2
// ---------------------------------------------------------------------------
__global__ void head2_kernel(const float* __restrict__ fc3, float* __restrict__ out) {
    int b = blockIdx.x * 256 + threadIdx.x;
    if (b >= BATCH) return;
    float best = -1e30f;
#pragma unroll
    for (int i = 0; i < 2; i++) {
        float sc = g_bn2p[i], sh = g_bn2p[2 + i];
        float s = 0.f;
#pragma unroll
        for (int m = 0; m < 32; m++) {
            float v = fmaxf(g_g2[(size_t)b * 64 + i * 32 + m] * sc + sh, 0.f);
            s += v * fc3[m];
        }
        float sig = 1.f / (1.f + expf(-s));
        best = fmaxf(best, sig);
    }
    out[b] = best;
}

// ---------------------------------------------------------------------------
// launch
// ---------------------------------------------------------------------------
extern "C" void kernel_launch(void* const* d_in, const int* in_sizes, int n_in,
                              void* d_out, int out_size)
{
    const int*   x      = (const int*)d_in[0];
    const float* emb    = (const float*)d_in[1];
    const float* W3     = (const float*)d_in[2];
    const float* b3     = (const float*)d_in[3];
    const float* W5     = (const float*)d_in[4];
    const float* b5     = (const float*)d_in[5];
    const float* W7     = (const float*)d_in[6];
    const float* b7     = (const float*)d_in[7];
    const float* conv1w = (const float*)d_in[8];
    const float* conv1b = (const float*)d_in[9];
    const float* bng    = (const float*)d_in[10];
    const float* bnb    = (const float*)d_in[11];
    const float* capsw  = (const float*)d_in[12];
    const float* capsb  = (const float*)d_in[13];
    const float* routeW = (const float*)d_in[14];
    const float* routeb = (const float*)d_in[15];
    const float* fc1    = (const float*)d_in[16];
    const float* bn1g   = (const float*)d_in[17];
    const float* bn1b   = (const float*)d_in[18];
    const float* fc2    = (const float*)d_in[19];
    const float* bn2g   = (const float*)d_in[20];
    const float* bn2b   = (const float*)d_in[21];
    const float* fc3    = (const float*)d_in[22];
    float* out = (float*)d_out;

    cudaFuncSetAttribute(conv1_kernel,     cudaFuncAttributeMaxDynamicSharedMemorySize, CONV1_SMEM);
    cudaFuncSetAttribute(capsroute_kernel, cudaFuncAttributeMaxDynamicSharedMemorySize, CR_SMEM);
    cudaFuncSetAttribute(pl_kernel<3>, cudaFuncAttributeMaxDynamicSharedMemorySize, PL_SMEM);
    cudaFuncSetAttribute(pl_kernel<5>, cudaFuncAttributeMaxDynamicSharedMemorySize, PL_SMEM);
    cudaFuncSetAttribute(pl_kernel<7>, cudaFuncAttributeMaxDynamicSharedMemorySize, PL_SMEM);

    __half *h0, *h1, *w16;
    cudaGetSymbolAddress((void**)&h0,  g_h0);
    cudaGetSymbolAddress((void**)&h1,  g_h1);
    cudaGetSymbolAddress((void**)&w16, g_w16);

    zero_kernel<<<1, 256>>>();
    embed_kernel<<<(BATCH * SEQ * 16 + 255) / 256, 256>>>(x, emb);
    wprep_kernel<<<dim3(384 / 32, 41), 256>>>(W3, w16 + WOFF3, 384);
    wprep_kernel<<<dim3(640 / 32, 41), 256>>>(W5, w16 + WOFF5, 640);
    wprep_kernel<<<dim3(896 / 32, 41), 256>>>(W7, w16 + WOFF7, 896);

    pl_kernel<3><<<dim3(32, 41), 256, PL_SMEM>>>(h0, w16 + WOFF3, b3, h1);
    pl_kernel<5><<<dim3(32, 41), 256, PL_SMEM>>>(h1, w16 + WOFF5, b5, h0);
    pl_kernel<7><<<dim3(32, 41), 256, PL_SMEM>>>(h0, w16 + WOFF7, b7, h1);

    conv1_kernel<<<BATCH, 256, CONV1_SMEM>>>(conv1w, conv1b);
    bn_fin_conv<<<1, 64>>>(bng, bnb);
    capsroute_kernel<<<BATCH, 256, CR_SMEM>>>(capsw, capsb, routeW, routeb, fc1);
    bn1_fin<<<1, 2>>>(bn1g, bn1b);
    head1_kernel<<<BATCH / 4, 256>>>(fc2);
    bn2_fin<<<1, 2>>>(bn2g, bn2b);
    head2_kernel<<<(BATCH + 255) / 256, 256>>>(fc3, out);
}

// round 7
// speedup vs baseline: 4.0146x; 1.5949x over previous
#include <cuda_runtime.h>
#include <cuda_fp16.h>
#include <math.h>
#include <stdint.h>

// ---------------------------------------------------------------------------
// Problem constants
// ---------------------------------------------------------------------------
#define BATCH 4096
#define SEQ   41
#define FDIM  128
#define SF    (SEQ*FDIM)        // 5248
#define C64L  (64*128)          // 8192

// ---------------------------------------------------------------------------
// Scratch (device globals; allocation-free contract)
// ---------------------------------------------------------------------------
__device__ __align__(256) __half g_h0[(size_t)BATCH * SF];   // activation ping
__device__ __align__(256) __half g_h1[(size_t)BATCH * SF];   // activation pong
__device__ __align__(256) __half g_c[(size_t)BATCH * C64L];  // conv1 out [b][l=128][o=64]
__device__ __align__(256) float  g_g1[(size_t)BATCH * 128];  // [B,2,64]
__device__ __align__(256) float  g_g2[(size_t)BATCH * 64];   // [B,2,32]
__device__ double g_bnsum[64], g_bnsq[64];
__device__ float  g_bnscale[64], g_bnshift[64];
__device__ double g_bn1acc[4];
__device__ double g_bn2acc[4];
__device__ float  g_bn1p[4];
__device__ float  g_bn2p[4];

// transposed fp16 PL weights: layout [s][n=128][K], layers packed
#define WOFF3 ((size_t)0)
#define WOFF5 ((size_t)41*384*128)
#define WOFF7 ((size_t)(41*384*128) + (size_t)41*640*128)
#define WTOT  ((size_t)41*1920*128)
__device__ __align__(256) __half g_w16[WTOT];

// conv weights fp16, pitched: wc1 [3][64][56], wc2 [3][64][40]
__device__ __align__(256) __half g_wc1[3*64*56];
__device__ __align__(256) __half g_wc2[3*64*40];

// single shared extern symbol for all dynamic-smem kernels
extern __shared__ __align__(1024) char sm_raw[];

__device__ __forceinline__ float squash_factor(float ssq) {
    float n = sqrtf(ssq);
    return (1.f - 1.f / (expf(n) + 1e-21f)) / (n + 1e-21f);
}

// ---------------------------------------------------------------------------
// PTX helpers (compute_100-safe: mma.sync + cp.async only)
// ---------------------------------------------------------------------------
__device__ __forceinline__ uint32_t smem_u32(const void* p) {
    uint32_t a;
    asm("{ .reg .u64 t; cvta.to.shared.u64 t, %1; cvt.u32.u64 %0, t; }" : "=r"(a) : "l"(p));
    return a;
}
__device__ __forceinline__ uint32_t lds32(uint32_t a) {
    uint32_t v;
    asm volatile("ld.shared.b32 %0, [%1];" : "=r"(v) : "r"(a));
    return v;
}
__device__ __forceinline__ void sts32(uint32_t a, uint32_t v) {
    asm volatile("st.shared.b32 [%0], %1;" :: "r"(a), "r"(v));
}
__device__ __forceinline__ void sts16(uint32_t a, uint16_t v) {
    asm volatile("st.shared.u16 [%0], %1;" :: "r"(a), "h"(v));
}
__device__ __forceinline__ void mma_f16(float* c, const uint32_t* a, const uint32_t* b) {
    asm volatile(
        "mma.sync.aligned.m16n8k16.row.col.f32.f16.f16.f32 "
        "{%0,%1,%2,%3}, {%4,%5,%6,%7}, {%8,%9}, {%0,%1,%2,%3};"
        : "+f"(c[0]), "+f"(c[1]), "+f"(c[2]), "+f"(c[3])
        : "r"(a[0]), "r"(a[1]), "r"(a[2]), "r"(a[3]), "r"(b[0]), "r"(b[1]));
}
#define CP16(dst, src)    asm volatile("cp.async.cg.shared.global [%0], [%1], 16;" :: "r"(dst), "l"(src))
#define CP_COMMIT()       asm volatile("cp.async.commit_group;" ::: "memory")
#define CP_WAIT0()        asm volatile("cp.async.wait_group 0;" ::: "memory")

__device__ __forceinline__ uint32_t hpack(float a, float b) {
    __half2 t = __floats2half2_rn(a, b);
    return *reinterpret_cast<uint32_t*>(&t);
}

// ---------------------------------------------------------------------------
// 0. zero accumulators + conv weight pads
// ---------------------------------------------------------------------------
__global__ void zero_kernel() {
    int t = threadIdx.x;
    if (t < 64) { g_bnsum[t] = 0.0; g_bnsq[t] = 0.0; }
    if (t < 4)  { g_bn1acc[t] = 0.0; g_bn2acc[t] = 0.0; }
    uint32_t* p1 = reinterpret_cast<uint32_t*>(g_wc1);
    for (int i = t; i < 3*64*56/2; i += 256) p1[i] = 0;
    uint32_t* p2 = reinterpret_cast<uint32_t*>(g_wc2);
    for (int i = t; i < 3*64*40/2; i += 256) p2[i] = 0;
}

// ---------------------------------------------------------------------------
// 0b. conv weight prep (after zero): fp32 [o][c][k] -> fp16 [k][o][c] pitched
// ---------------------------------------------------------------------------
__global__ void wprep_conv(const float* __restrict__ c1w, const float* __restrict__ c2w) {
    int t = blockIdx.x * 256 + threadIdx.x;
    if (t < 64 * 41 * 3) {
        int k = t % 3, c = (t / 3) % 41, o = t / 123;
        g_wc1[(k * 64 + o) * 56 + c] = __float2half(c1w[t]);
    }
    if (t < 64 * 32 * 3) {
        int k = t % 3, c = (t / 3) % 32, o = t / 96;
        g_wc2[(k * 64 + o) * 40 + c] = __float2half(c2w[t]);
    }
}

// ---------------------------------------------------------------------------
// 1. embedding gather -> g_h0 fp16
// ---------------------------------------------------------------------------
__global__ void embed_kernel(const int* __restrict__ x, const float* __restrict__ emb) {
    int gid = blockIdx.x * 256 + threadIdx.x;
    int pos = gid >> 4;
    int f0  = (gid & 15) * 8;
    if (pos >= BATCH * SEQ) return;
    int e = x[pos];
    const float4* sp = reinterpret_cast<const float4*>(emb + e * FDIM + f0);
    float4 v0 = sp[0], v1 = sp[1];
    uint4 o;
    o.x = hpack(v0.x, v0.y); o.y = hpack(v0.z, v0.w);
    o.z = hpack(v1.x, v1.y); o.w = hpack(v1.z, v1.w);
    *reinterpret_cast<uint4*>(g_h0 + (size_t)pos * FDIM + f0) = o;
}

// ---------------------------------------------------------------------------
// 1b. PL weight prep: transpose [s][K][128] fp32 -> [s][128][K] fp16
// ---------------------------------------------------------------------------
__global__ void wprep_kernel(const float* __restrict__ W, __half* __restrict__ o, int K) {
    __shared__ float tile[32][129];
    int s = blockIdx.y, kb = blockIdx.x * 32, t = threadIdx.x;
#pragma unroll
    for (int i = 0; i < 16; i++) {
        int e = t + i * 256;
        int kk = e >> 7, n = e & 127;
        tile[kk][n] = W[((size_t)s * K + kb + kk) * 128 + n];
    }
    __syncthreads();
    int n = t >> 1, h = (t & 1) * 16;
    size_t ob = ((size_t)(s * 128 + n)) * K + kb + h;
#pragma unroll
    for (int kk = 0; kk < 16; kk += 2) {
        *reinterpret_cast<uint32_t*>(&o[ob + kk]) = hpack(tile[h + kk][n], tile[h + kk + 1][n]);
    }
}

// ---------------------------------------------------------------------------
// 2-4. position_linear via warp-level fp16 MMA
// ---------------------------------------------------------------------------
#define PL_SMEM (2 * 16384)   // 32768

template<int WIN>
__global__ void __launch_bounds__(256, 2)
pl_kernel(const __half* __restrict__ aIn, const __half* __restrict__ wIn,
          const float* __restrict__ bst, __half* __restrict__ aOut)
{
    constexpr int P = WIN / 2;
    constexpr int K = WIN * 128;
    const uint32_t smb = smem_u32(sm_raw);
    const int s   = blockIdx.y;
    const int bm  = blockIdx.x * 128;
    const int tid = threadIdx.x;
    const int warp = tid >> 5, lane = tid & 31;
    const int warp_m = warp >> 2, warp_n = warp & 3;
    const int gid = lane >> 2, tg = lane & 3;

    const int j0 = (P - s) > 0 ? (P - s) : 0;
    const int j1 = (WIN - 1) < (P + SEQ - 1 - s) ? (WIN - 1) : (P + SEQ - 1 - s);
    const int nst = (j1 - j0 + 1) * 4;

    float acc[4][4][4];
#pragma unroll
    for (int a = 0; a < 4; a++)
#pragma unroll
        for (int b = 0; b < 4; b++)
#pragma unroll
            for (int c = 0; c < 4; c++) acc[a][b][c] = 0.f;

    auto load_stage = [&](int st, int buf) {
        const int jj = j0 + (st >> 2);
        const int f0 = (st & 3) * 32;
        const int tsrc = s + jj - P;
        const int k0 = jj * 128 + f0;
        const uint32_t sb = smb + buf * 16384;
#pragma unroll
        for (int i = 0; i < 2; i++) {
            int idx = tid + i * 256;
            int row = idx >> 2, cs = idx & 3;
            uint32_t d = sb + row * 64 + (((cs ^ (row & 3)) << 4));
            size_t aoff = ((size_t)(bm + row) * SEQ + tsrc) * 128 + f0 + cs * 8;
            size_t boff = ((size_t)(s * 128 + row)) * K + k0 + cs * 8;
            CP16(d,        (const char*)(aIn + aoff));
            CP16(d + 8192, (const char*)(wIn + boff));
        }
        CP_COMMIT();
    };

    load_stage(0, 0);

    for (int st = 0; st < nst; st++) {
        if (st + 1 < nst) {
            load_stage(st + 1, (st + 1) & 1);
            asm volatile("cp.async.wait_group 1;" ::: "memory");
        } else {
            asm volatile("cp.async.wait_group 0;" ::: "memory");
        }
        __syncthreads();

        const uint32_t ab = smb + (st & 1) * 16384;
#pragma unroll
        for (int kt = 0; kt < 2; kt++) {
            uint32_t bf[4][2];
#pragma unroll
            for (int nt = 0; nt < 4; nt++) {
                int br = warp_n * 32 + nt * 8 + gid;
                uint32_t base = ab + 8192 + br * 64 + tg * 4;
                int sw = br & 3;
                bf[nt][0] = lds32(base + (((kt * 2 + 0) ^ sw) << 4));
                bf[nt][1] = lds32(base + (((kt * 2 + 1) ^ sw) << 4));
            }
#pragma unroll
            for (int mt = 0; mt < 4; mt++) {
                int r0 = warp_m * 64 + mt * 16 + gid;
                int r1 = r0 + 8;
                uint32_t b0 = ab + r0 * 64 + tg * 4; int s0 = r0 & 3;
                uint32_t b1 = ab + r1 * 64 + tg * 4; int s1 = r1 & 3;
                uint32_t af[4];
                af[0] = lds32(b0 + (((kt * 2 + 0) ^ s0) << 4));
                af[1] = lds32(b1 + (((kt * 2 + 0) ^ s1) << 4));
                af[2] = lds32(b0 + (((kt * 2 + 1) ^ s0) << 4));
                af[3] = lds32(b1 + (((kt * 2 + 1) ^ s1) << 4));
#pragma unroll
                for (int nt = 0; nt < 4; nt++)
                    mma_f16(acc[mt][nt], af, bf[nt]);
            }
        }
        __syncthreads();
    }

    const float* bias = bst + s * 128;
#pragma unroll
    for (int mt = 0; mt < 4; mt++) {
        int rbase = warp_m * 64 + mt * 16 + gid;
#pragma unroll
        for (int half = 0; half < 2; half++) {
            int r = rbase + half * 8;
            size_t ob = ((size_t)(bm + r) * SEQ + s) * 128;
#pragma unroll
            for (int nt = 0; nt < 4; nt++) {
                int col = warp_n * 32 + nt * 8 + tg * 2;
                float v0 = fmaxf(acc[mt][nt][half * 2 + 0] + bias[col],     0.f);
                float v1 = fmaxf(acc[mt][nt][half * 2 + 1] + bias[col + 1], 0.f);
                *reinterpret_cast<uint32_t*>(aOut + ob + col) = hpack(v0, v1);
            }
        }
    }
}

// ---------------------------------------------------------------------------
// 5. conv1 via tensor cores. Per-batch CTA.
// ---------------------------------------------------------------------------
#define C1_STG   0
#define C1_A     10496
#define C1_W     (C1_A + 130*112)        // 25056
#define C1_STATS (C1_W + 3*64*112)       // 46560
#define CONV1_SMEM (C1_STATS + 2*64*4)   // 47072

__global__ void __launch_bounds__(256, 2)
conv1_kernel(const float* __restrict__ bias) {
    const uint32_t smb = smem_u32(sm_raw);
    const int b = blockIdx.x, t = threadIdx.x;
    const int warp = t >> 5, lane = t & 31;
    const int warp_m = warp >> 1, warp_n = warp & 1;
    const int gid = lane >> 2, tg = lane & 3;

    // zero A region + stats
    for (int i = t; i < 130 * 112 / 4; i += 256) sts32(smb + C1_A + i * 4, 0u);
    for (int i = t; i < 128; i += 256) sts32(smb + C1_STATS + i * 4, 0u);

    // cp.async: staging [41][128] fp16 from g_h1[b], weights
    {
        const char* src = (const char*)(g_h1 + (size_t)b * SF);
        for (int i = t; i < 41 * 16; i += 256)
            CP16(smb + C1_STG + i * 16, src + i * 16);
        const char* wsrc = (const char*)g_wc1;
        for (int i = t; i < 3 * 64 * 56 * 2 / 16; i += 256)
            CP16(smb + C1_W + i * 16, wsrc + i * 16);
        CP_COMMIT(); CP_WAIT0();
    }
    __syncthreads();

    // transpose staging [c][f] -> A[(f+1)*112 + c*2]
    for (int idx = t; idx < 41 * 64; idx += 256) {
        int c = idx >> 6, f2 = idx & 63;
        uint32_t v = lds32(smb + C1_STG + c * 256 + f2 * 4);
        sts16(smb + C1_A + (2 * f2 + 1) * 112 + c * 2, (uint16_t)(v & 0xFFFF));
        sts16(smb + C1_A + (2 * f2 + 2) * 112 + c * 2, (uint16_t)(v >> 16));
    }
    __syncthreads();

    float acc[2][4][4];
#pragma unroll
    for (int a = 0; a < 2; a++)
#pragma unroll
        for (int bb = 0; bb < 4; bb++)
#pragma unroll
            for (int c = 0; c < 4; c++) acc[a][bb][c] = 0.f;

#pragma unroll
    for (int k = 0; k < 3; k++) {
#pragma unroll
        for (int ks = 0; ks < 3; ks++) {
            uint32_t bf[4][2];
#pragma unroll
            for (int nt = 0; nt < 4; nt++) {
                uint32_t ba = smb + C1_W + k * (64 * 112) + (warp_n * 32 + nt * 8 + gid) * 112 + ks * 32 + tg * 4;
                bf[nt][0] = lds32(ba);
                bf[nt][1] = lds32(ba + 16);
            }
#pragma unroll
            for (int mt = 0; mt < 2; mt++) {
                int r0 = warp_m * 32 + mt * 16 + gid + k;
                uint32_t a0a = smb + C1_A + r0 * 112 + ks * 32 + tg * 4;
                uint32_t a1a = a0a + 8 * 112;
                uint32_t af[4];
                af[0] = lds32(a0a);
                af[1] = lds32(a1a);
                af[2] = lds32(a0a + 16);
                af[3] = lds32(a1a + 16);
#pragma unroll
                for (int nt = 0; nt < 4; nt++)
                    mma_f16(acc[mt][nt], af, bf[nt]);
            }
        }
    }

    // epilogue: bias, write g_c [b][l][o], BN partial stats
    float s0[4], s1[4], q0[4], q1[4];
#pragma unroll
    for (int nt = 0; nt < 4; nt++) { s0[nt] = s1[nt] = q0[nt] = q1[nt] = 0.f; }
    __half* dst = g_c + (size_t)b * C64L;
#pragma unroll
    for (int mt = 0; mt < 2; mt++) {
        int l0 = warp_m * 32 + mt * 16 + gid;
#pragma unroll
        for (int nt = 0; nt < 4; nt++) {
            int o = warp_n * 32 + nt * 8 + tg * 2;
            float bb0 = bias[o], bb1 = bias[o + 1];
            float v0 = acc[mt][nt][0] + bb0, v1 = acc[mt][nt][1] + bb1;
            float v2 = acc[mt][nt][2] + bb0, v3 = acc[mt][nt][3] + bb1;
            *reinterpret_cast<uint32_t*>(dst + l0 * 64 + o)       = hpack(v0, v1);
            *reinterpret_cast<uint32_t*>(dst + (l0 + 8) * 64 + o) = hpack(v2, v3);
            s0[nt] += v0 + v2; s1[nt] += v1 + v3;
            q0[nt] += v0 * v0 + v2 * v2; q1[nt] += v1 * v1 + v3 * v3;
        }
    }
#pragma unroll
    for (int nt = 0; nt < 4; nt++) {
#pragma unroll
        for (int off = 4; off < 32; off <<= 1) {
            s0[nt] += __shfl_xor_sync(0xffffffffu, s0[nt], off);
            s1[nt] += __shfl_xor_sync(0xffffffffu, s1[nt], off);
            q0[nt] += __shfl_xor_sync(0xffffffffu, q0[nt], off);
            q1[nt] += __shfl_xor_sync(0xffffffffu, q1[nt], off);
        }
    }
    if (gid == 0) {
        float* sums = reinterpret_cast<float*>(sm_raw + C1_STATS);
        float* sqs  = sums + 64;
#pragma unroll
        for (int nt = 0; nt < 4; nt++) {
            int o = warp_n * 32 + nt * 8 + tg * 2;
            atomicAdd(&sums[o],     s0[nt]);
            atomicAdd(&sums[o + 1], s1[nt]);
            atomicAdd(&sqs[o],      q0[nt]);
            atomicAdd(&sqs[o + 1],  q1[nt]);
        }
    }
    __syncthreads();
    if (t < 64) {
        float* sums = reinterpret_cast<float*>(sm_raw + C1_STATS);
        atomicAdd(&g_bnsum[t], (double)sums[t]);
        atomicAdd(&g_bnsq[t],  (double)sums[64 + t]);
    }
}

__global__ void bn_fin_conv(const float* __restrict__ g, const float* __restrict__ bb) {
    int c = threadIdx.x;
    double inv = 1.0 / ((double)BATCH * 128.0);
    double mu = g_bnsum[c] * inv;
    double var = g_bnsq[c] * inv - mu * mu;
    float sc = g[c] * rsqrtf((float)var + 1e-5f);
    g_bnscale[c] = sc;
    g_bnshift[c] = bb[c] - (float)mu * sc;
}

// ---------------------------------------------------------------------------
// 8-9. FUSED capsroute
// ---------------------------------------------------------------------------
#define CR_A    0
#define CR_W    16640
#define CR_SOUT 32000
#define CR_SMEM (CR_SOUT + 128*73*4)   // 69376

__global__ void __launch_bounds__(256, 2)
capsroute_kernel(const float* __restrict__ cb,
                 const float* __restrict__ rW, const float* __restrict__ rb,
                 const float* __restrict__ fc1)
{
    const uint32_t smb = smem_u32(sm_raw);
    float* sout = reinterpret_cast<float*>(sm_raw + CR_SOUT);  // [128 l][73]
    __shared__ float red4[4][64];
    __shared__ float sfac[64];
    __shared__ float coef[2][64];
    __shared__ float warp_sq[8];
    __shared__ float factor_s[2];
    __shared__ float sv_s[2][128];
    __shared__ float yv_s[2][128];

    const int b = blockIdx.x, t = threadIdx.x;
    const int warp = t >> 5, lane = t & 31;
    const int warp_m = warp >> 1, g = warp & 1;
    const int gid = lane >> 2, tg = lane & 3;

    // zero halo rows 0 and 129  (FIX: row 129 starts at 129*128 = 16512)
    if (t < 64) sts32(smb + CR_A + ((t < 32) ? 0 : (129 * 128)) + (t & 31) * 4, 0u);

    // cp.async A rows 1..128 from g_c[b] (chunk-XOR swizzle), weights
    {
        const char* src = (const char*)(g_c + (size_t)b * C64L);
        for (int i = t; i < 128 * 8; i += 256) {
            int row = (i >> 3) + 1, ch = i & 7;
            CP16(smb + CR_A + row * 128 + ((ch ^ (row & 7)) << 4), src + (row - 1) * 128 + ch * 16);
        }
        const char* wsrc = (const char*)g_wc2;
        for (int i = t; i < 3 * 64 * 40 * 2 / 16; i += 256)
            CP16(smb + CR_W + i * 16, wsrc + i * 16);
        CP_COMMIT(); CP_WAIT0();
    }
    __syncthreads();

    // BN + ReLU in place on A rows 1..128
    for (int idx = t; idx < 128 * 32; idx += 256) {
        int r = (idx >> 5) + 1, wd = idx & 31;
        int o = wd * 2;
        uint32_t addr = smb + CR_A + r * 128 + (((wd >> 2) ^ (r & 7)) << 4) + ((wd * 4) & 15);
        uint32_t v = lds32(addr);
        __half2 h = *reinterpret_cast<__half2*>(&v);
        float f0 = fmaxf(__low2float(h)  * g_bnscale[o]     + g_bnshift[o],     0.f);
        float f1 = fmaxf(__high2float(h) * g_bnscale[o + 1] + g_bnshift[o + 1], 0.f);
        sts32(addr, hpack(f0, f1));
    }
    __syncthreads();

    // caps MMA: M=128(l) per 4 warp_m, N=32 per group g, K=32, 3 taps
    float acc[2][4][4];
#pragma unroll
    for (int a = 0; a < 2; a++)
#pragma unroll
        for (int bb = 0; bb < 4; bb++)
#pragma unroll
            for (int c = 0; c < 4; c++) acc[a][bb][c] = 0.f;

#pragma unroll
    for (int k = 0; k < 3; k++) {
#pragma unroll
        for (int ks = 0; ks < 2; ks++) {
            uint32_t bf[4][2];
#pragma unroll
            for (int nt = 0; nt < 4; nt++) {
                uint32_t ba = smb + CR_W + k * (64 * 80) + (g * 32 + nt * 8 + gid) * 80 + ks * 32 + tg * 4;
                bf[nt][0] = lds32(ba);
                bf[nt][1] = lds32(ba + 16);
            }
            int cbase = g * 4 + ks * 2;
#pragma unroll
            for (int mt = 0; mt < 2; mt++) {
                int r0 = warp_m * 32 + mt * 16 + gid + k;
                int r1 = r0 + 8;
                uint32_t af[4];
                af[0] = lds32(smb + CR_A + r0 * 128 + (((cbase)     ^ (r0 & 7)) << 4) + tg * 4);
                af[1] = lds32(smb + CR_A + r1 * 128 + (((cbase)     ^ (r1 & 7)) << 4) + tg * 4);
                af[2] = lds32(smb + CR_A + r0 * 128 + (((cbase + 1) ^ (r0 & 7)) << 4) + tg * 4);
                af[3] = lds32(smb + CR_A + r1 * 128 + (((cbase + 1) ^ (r1 & 7)) << 4) + tg * 4);
#pragma unroll
                for (int nt = 0; nt < 4; nt++)
                    mma_f16(acc[mt][nt], af, bf[nt]);
            }
        }
    }

    // epilogue: + bias -> sout [l][73] fp32 (pre-squash)
#pragma unroll
    for (int mt = 0; mt < 2; mt++) {
        int l0 = warp_m * 32 + mt * 16 + gid;
#pragma unroll
        for (int nt = 0; nt < 4; nt++) {
            int o = g * 32 + nt * 8 + tg * 2;
            float bb0 = cb[o], bb1 = cb[o + 1];
            sout[l0 * 73 + o]           = acc[mt][nt][0] + bb0;
            sout[l0 * 73 + o + 1]       = acc[mt][nt][1] + bb1;
            sout[(l0 + 8) * 73 + o]     = acc[mt][nt][2] + bb0;
            sout[(l0 + 8) * 73 + o + 1] = acc[mt][nt][3] + bb1;
        }
    }
    __syncthreads();

    // squash factors per capsule o (norm over l)
    {
        int o = t & 63, seg = t >> 6;
        float p = 0.f;
        for (int l = seg * 32; l < seg * 32 + 32; l++) {
            float v = sout[l * 73 + o];
            p += v * v;
        }
        red4[seg][o] = p;
    }
    __syncthreads();
    if (t < 64) {
        float tot = red4[0][t] + red4[1][t] + red4[2][t] + red4[3][t];
        sfac[t] = squash_factor(tot);
    }
    __syncthreads();
    if (t < 128) {
        int i = t >> 6, j = t & 63;
        coef[i][j] = sfac[j] * (1.0f + rb[i * 64 + j]);
    }
    __syncthreads();

    // routing: s[i][f] then squash + pair-max
    int i = t >> 7;
    int f = t & 127;
    float acc2 = 0.f;
    const float* rwi = rW + i * 8192 + f;
    const float* srow = sout + f * 73;
#pragma unroll 8
    for (int j = 0; j < 64; j++)
        acc2 += srow[j] * rwi[j * 128] * coef[i][j];

    float sq = acc2 * acc2;
    for (int off = 16; off; off >>= 1) sq += __shfl_xor_sync(0xffffffffu, sq, off);
    if ((t & 31) == 0) warp_sq[t >> 5] = sq;
    __syncthreads();
    if (t < 2) {
        float tot = warp_sq[t * 4 + 0] + warp_sq[t * 4 + 1] + warp_sq[t * 4 + 2] + warp_sq[t * 4 + 3];
        factor_s[t] = squash_factor(tot);
    }
    __syncthreads();
    sv_s[i][f] = acc2 * factor_s[i];
    __syncthreads();
    yv_s[i][f] = sv_s[i][f] + fmaxf(sv_s[0][f], sv_s[1][f]);
    __syncthreads();

    if (t < 128) {
        int ii = t >> 6, o = t & 63;
        float a = 0.f;
        for (int ff = 0; ff < 128; ff++) a += yv_s[ii][ff] * fc1[ff * 64 + o];
        g_g1[(size_t)b * 128 + ii * 64 + o] = a;
        double s = a, q = (double)a * a;
        for (int off = 16; off; off >>= 1) {
            s += __shfl_xor_sync(0xffffffffu, s, off);
            q += __shfl_xor_sync(0xffffffffu, q, off);
        }
        if ((t & 31) == 0) {
            atomicAdd(&g_bn1acc[ii], s);
            atomicAdd(&g_bn1acc[2 + ii], q);
        }
    }
}

__global__ void bn1_fin(const float* __restrict__ g, const float* __restrict__ bb) {
    int i = threadIdx.x;
    double inv = 1.0 / ((double)BATCH * 64.0);
    double mu = g_bn1acc[i] * inv;
    double var = g_bn1acc[2 + i] * inv - mu * mu;
    float sc = g[i] * rsqrtf((float)var + 1e-5f);
    g_bn1p[i] = sc;
    g_bn1p[2 + i] = bb[i] - (float)mu * sc;
}

// ---------------------------------------------------------------------------
// 11. head1
// ---------------------------------------------------------------------------
__global__ void head1_kernel(const float* __restrict__ fc2) {
    __shared__ float a_s[4][128];
    int t = threadIdx.x;
    for (int idx = t; idx < 512; idx += 256) {
        int lbb = idx >> 7, rr = idx & 127;
        int ii = rr >> 6;
        float v = g_g1[(size_t)(blockIdx.x * 4 + lbb) * 128 + rr];
        a_s[lbb][rr] = fmaxf(v * g_bn1p[ii] + g_bn1p[2 + ii], 0.f);
    }
    __syncthreads();
    int lb = t >> 6, r = t & 63;
    int b = blockIdx.x * 4 + lb;
    int ii = r >> 5, m = r & 31;
    float acc = 0.f;
    const float* arow = &a_s[lb][ii * 64];
#pragma unroll 8
    for (int o = 0; o < 64; o++) acc += arow[o] * fc2[o * 32 + m];
    g_g2[(size_t)b * 64 + ii * 32 + m] = acc;
    double s = acc, q = (double)acc * acc;
    for (int off = 16; off; off >>= 1) {
        s += __shfl_xor_sync(0xffffffffu, s, off);
        q += __shfl_xor_sync(0xffffffffu, q, off);
    }
    if ((t & 31) == 0) {
        atomicAdd(&g_bn2acc[ii], s);
        atomicAdd(&g_bn2acc[2 + ii], q);
    }
}

__global__ void bn2_fin(const float* __restrict__ g, const float* __restrict__ bb) {
    int i = threadIdx.x;
    double inv = 1.0 / ((double)BATCH * 32.0);
    double mu = g_bn2acc[i] * inv;
    double var = g_bn2acc[2 + i] * inv - mu * mu;
    float sc = g[i] * rsqrtf((float)var + 1e-5f);
    g_bn2p[i] = sc;
    g_bn2p[2 + i] = bb[i] - (float)mu * sc;
}

// ---------------------------------------------------------------------------
// 13. head2
// ---------------------------------------------------------------------------
__global__ void head2_kernel(const float* __restrict__ fc3, float* __restrict__ out) {
    int b = blockIdx.x * 256 + threadIdx.x;
    if (b >= BATCH) return;
    float best = -1e30f;
#pragma unroll
    for (int i = 0; i < 2; i++) {
        float sc = g_bn2p[i], sh = g_bn2p[2 + i];
        float s = 0.f;
#pragma unroll
        for (int m = 0; m < 32; m++) {
            float v = fmaxf(g_g2[(size_t)b * 64 + i * 32 + m] * sc + sh, 0.f);
            s += v * fc3[m];
        }
        float sig = 1.f / (1.f + expf(-s));
        best = fmaxf(best, sig);
    }
    out[b] = best;
}

// ---------------------------------------------------------------------------
// launch
// ---------------------------------------------------------------------------
extern "C" void kernel_launch(void* const* d_in, const int* in_sizes, int n_in,
                              void* d_out, int out_size)
{
    const int*   x      = (const int*)d_in[0];
    const float* emb    = (const float*)d_in[1];
    const float* W3     = (const float*)d_in[2];
    const float* b3     = (const float*)d_in[3];
    const float* W5     = (const float*)d_in[4];
    const float* b5     = (const float*)d_in[5];
    const float* W7     = (const float*)d_in[6];
    const float* b7     = (const float*)d_in[7];
    const float* conv1w = (const float*)d_in[8];
    const float* conv1b = (const float*)d_in[9];
    const float* bng    = (const float*)d_in[10];
    const float* bnb    = (const float*)d_in[11];
    const float* capsw  = (const float*)d_in[12];
    const float* capsb  = (const float*)d_in[13];
    const float* routeW = (const float*)d_in[14];
    const float* routeb = (const float*)d_in[15];
    const float* fc1    = (const float*)d_in[16];
    const float* bn1g   = (const float*)d_in[17];
    const float* bn1b   = (const float*)d_in[18];
    const float* fc2    = (const float*)d_in[19];
    const float* bn2g   = (const float*)d_in[20];
    const float* bn2b   = (const float*)d_in[21];
    const float* fc3    = (const float*)d_in[22];
    float* out = (float*)d_out;

    cudaFuncSetAttribute(conv1_kernel,     cudaFuncAttributeMaxDynamicSharedMemorySize, CONV1_SMEM);
    cudaFuncSetAttribute(capsroute_kernel, cudaFuncAttributeMaxDynamicSharedMemorySize, CR_SMEM);
    cudaFuncSetAttribute(pl_kernel<3>, cudaFuncAttributeMaxDynamicSharedMemorySize, PL_SMEM);
    cudaFuncSetAttribute(pl_kernel<5>, cudaFuncAttributeMaxDynamicSharedMemorySize, PL_SMEM);
    cudaFuncSetAttribute(pl_kernel<7>, cudaFuncAttributeMaxDynamicSharedMemorySize, PL_SMEM);

    __half *h0, *h1, *w16;
    cudaGetSymbolAddress((void**)&h0,  g_h0);
    cudaGetSymbolAddress((void**)&h1,  g_h1);
    cudaGetSymbolAddress((void**)&w16, g_w16);

    zero_kernel<<<1, 256>>>();
    wprep_conv<<<31, 256>>>(conv1w, capsw);
    embed_kernel<<<(BATCH * SEQ * 16 + 255) / 256, 256>>>(x, emb);
    wprep_kernel<<<dim3(384 / 32, 41), 256>>>(W3, w16 + WOFF3, 384);
    wprep_kernel<<<dim3(640 / 32, 41), 256>>>(W5, w16 + WOFF5, 640);
    wprep_kernel<<<dim3(896 / 32, 41), 256>>>(W7, w16 + WOFF7, 896);

    pl_kernel<3><<<dim3(32, 41), 256, PL_SMEM>>>(h0, w16 + WOFF3, b3, h1);
    pl_kernel<5><<<dim3(32, 41), 256, PL_SMEM>>>(h1, w16 + WOFF5, b5, h0);
    pl_kernel<7><<<dim3(32, 41), 256, PL_SMEM>>>(h0, w16 + WOFF7, b7, h1);

    conv1_kernel<<<BATCH, 256, CONV1_SMEM>>>(conv1b);
    bn_fin_conv<<<1, 64>>>(bng, bnb);
    capsroute_kernel<<<BATCH, 256, CR_SMEM>>>(capsb, routeW, routeb, fc1);
    bn1_fin<<<1, 2>>>(bn1g, bn1b);
    head1_kernel<<<BATCH / 4, 256>>>(fc2);
    bn2_fin<<<1, 2>>>(bn2g, bn2b);
    head2_kernel<<<(BATCH + 255) / 256, 256>>>(fc3, out);
}

// round 8
// speedup vs baseline: 4.7503x; 1.1833x over previous
#include <cuda_runtime.h>
#include <cuda_fp16.h>
#include <math.h>
#include <stdint.h>

// ---------------------------------------------------------------------------
// Problem constants
// ---------------------------------------------------------------------------
#define BATCH 4096
#define SEQ   41
#define FDIM  128
#define SF    (SEQ*FDIM)        // 5248
#define C64L  (64*128)          // 8192

// ---------------------------------------------------------------------------
// Scratch (device globals; allocation-free contract)
// ---------------------------------------------------------------------------
__device__ __align__(256) __half g_h0[(size_t)BATCH * SF];   // activation ping
__device__ __align__(256) __half g_h1[(size_t)BATCH * SF];   // activation pong
__device__ __align__(256) __half g_c[(size_t)BATCH * C64L];  // conv1 out [b][l=128][o=64]
__device__ __align__(256) float  g_g1[(size_t)BATCH * 128];  // [B,2,64]
__device__ __align__(256) float  g_g2[(size_t)BATCH * 64];   // [B,2,32]
__device__ double g_bnsum[64], g_bnsq[64];
__device__ float  g_bnscale[64], g_bnshift[64];
__device__ double g_bn1acc[4];
__device__ double g_bn2acc[4];
__device__ float  g_bn1p[4];
__device__ float  g_bn2p[4];

// transposed fp16 PL weights: layout [s][n=128][K], layers packed
#define WOFF3 ((size_t)0)
#define WOFF5 ((size_t)41*384*128)
#define WOFF7 ((size_t)(41*384*128) + (size_t)41*640*128)
#define WTOT  ((size_t)41*1920*128)
__device__ __align__(256) __half g_w16[WTOT];

// conv weights fp16, pitched: wc1 [3][64][56], wc2 [3][64][40]
__device__ __align__(256) __half g_wc1[3*64*56];
__device__ __align__(256) __half g_wc2[3*64*40];

// single shared extern symbol for all dynamic-smem kernels
extern __shared__ __align__(1024) char sm_raw[];

__device__ __forceinline__ float squash_factor(float ssq) {
    float n = sqrtf(ssq);
    return (1.f - 1.f / (expf(n) + 1e-21f)) / (n + 1e-21f);
}

// ---------------------------------------------------------------------------
// PTX helpers (compute_100-safe: mma.sync + cp.async only)
// ---------------------------------------------------------------------------
__device__ __forceinline__ uint32_t smem_u32(const void* p) {
    uint32_t a;
    asm("{ .reg .u64 t; cvta.to.shared.u64 t, %1; cvt.u32.u64 %0, t; }" : "=r"(a) : "l"(p));
    return a;
}
__device__ __forceinline__ uint32_t lds32(uint32_t a) {
    uint32_t v;
    asm volatile("ld.shared.b32 %0, [%1];" : "=r"(v) : "r"(a));
    return v;
}
__device__ __forceinline__ void sts32(uint32_t a, uint32_t v) {
    asm volatile("st.shared.b32 [%0], %1;" :: "r"(a), "r"(v));
}
__device__ __forceinline__ void sts16(uint32_t a, uint16_t v) {
    asm volatile("st.shared.u16 [%0], %1;" :: "r"(a), "h"(v));
}
__device__ __forceinline__ void mma_f16(float* c, const uint32_t* a, const uint32_t* b) {
    asm volatile(
        "mma.sync.aligned.m16n8k16.row.col.f32.f16.f16.f32 "
        "{%0,%1,%2,%3}, {%4,%5,%6,%7}, {%8,%9}, {%0,%1,%2,%3};"
        : "+f"(c[0]), "+f"(c[1]), "+f"(c[2]), "+f"(c[3])
        : "r"(a[0]), "r"(a[1]), "r"(a[2]), "r"(a[3]), "r"(b[0]), "r"(b[1]));
}
#define CP16(dst, src)    asm volatile("cp.async.cg.shared.global [%0], [%1], 16;" :: "r"(dst), "l"(src))
#define CP_COMMIT()       asm volatile("cp.async.commit_group;" ::: "memory")
#define CP_WAIT0()        asm volatile("cp.async.wait_group 0;" ::: "memory")

__device__ __forceinline__ uint32_t hpack(float a, float b) {
    __half2 t = __floats2half2_rn(a, b);
    return *reinterpret_cast<uint32_t*>(&t);
}

// ---------------------------------------------------------------------------
// 0. conv weight prep + accumulator zero (single launch)
//    fp32 [o][c][k] -> fp16 [k][o][c'] pitched with zero pad
// ---------------------------------------------------------------------------
__global__ void wprep_conv(const float* __restrict__ c1w, const float* __restrict__ c2w) {
    int t = blockIdx.x * 256 + threadIdx.x;
    if (blockIdx.x == 0) {
        int tt = threadIdx.x;
        if (tt < 64) { g_bnsum[tt] = 0.0; g_bnsq[tt] = 0.0; }
        if (tt < 4)  { g_bn1acc[tt] = 0.0; g_bn2acc[tt] = 0.0; }
    }
    if (t < 3 * 64 * 56) {
        int c = t % 56, o = (t / 56) % 64, k = t / (56 * 64);
        g_wc1[t] = (c < 41) ? __float2half(c1w[(o * 41 + c) * 3 + k]) : __float2half(0.f);
    }
    if (t < 3 * 64 * 40) {
        int c = t % 40, o = (t / 40) % 64, k = t / (40 * 64);
        g_wc2[t] = (c < 32) ? __float2half(c2w[(o * 32 + c) * 3 + k]) : __float2half(0.f);
    }
}

// ---------------------------------------------------------------------------
// 1. embedding gather -> g_h0 fp16
// ---------------------------------------------------------------------------
__global__ void embed_kernel(const int* __restrict__ x, const float* __restrict__ emb) {
    int gid = blockIdx.x * 256 + threadIdx.x;
    int pos = gid >> 4;
    int f0  = (gid & 15) * 8;
    if (pos >= BATCH * SEQ) return;
    int e = x[pos];
    const float4* sp = reinterpret_cast<const float4*>(emb + e * FDIM + f0);
    float4 v0 = sp[0], v1 = sp[1];
    uint4 o;
    o.x = hpack(v0.x, v0.y); o.y = hpack(v0.z, v0.w);
    o.z = hpack(v1.x, v1.y); o.w = hpack(v1.z, v1.w);
    *reinterpret_cast<uint4*>(g_h0 + (size_t)pos * FDIM + f0) = o;
}

// ---------------------------------------------------------------------------
// 1b. PL weight prep, all 3 layers in one launch.
//     blockIdx.x: 0..11 -> W3, 12..31 -> W5, 32..59 -> W7.  blockIdx.y = s.
// ---------------------------------------------------------------------------
__global__ void wprep_all(const float* __restrict__ W3, const float* __restrict__ W5,
                          const float* __restrict__ W7) {
    __shared__ float tile[32][129];
    int bx = blockIdx.x, s = blockIdx.y, t = threadIdx.x;
    const float* W; __half* o; int K, kb;
    if (bx < 12)      { W = W3; o = g_w16 + WOFF3; K = 384; kb = bx * 32; }
    else if (bx < 32) { W = W5; o = g_w16 + WOFF5; K = 640; kb = (bx - 12) * 32; }
    else              { W = W7; o = g_w16 + WOFF7; K = 896; kb = (bx - 32) * 32; }
#pragma unroll
    for (int i = 0; i < 16; i++) {
        int e = t + i * 256;
        int kk = e >> 7, n = e & 127;
        tile[kk][n] = W[((size_t)s * K + kb + kk) * 128 + n];
    }
    __syncthreads();
    int n = t >> 1, h = (t & 1) * 16;
    size_t ob = ((size_t)(s * 128 + n)) * K + kb + h;
#pragma unroll
    for (int kk = 0; kk < 16; kk += 2) {
        *reinterpret_cast<uint32_t*>(&o[ob + kk]) = hpack(tile[h + kk][n], tile[h + kk + 1][n]);
    }
}

// ---------------------------------------------------------------------------
// 2-4. position_linear via warp-level fp16 MMA, K-chunk 64.
//   CTA: M=128 x N=128. 8 warps 2(M) x 4(N); warp tile 64x32.
//   Stage: A,B each [128 rows][64 k] fp16 = 16KB, pitch 128B, 8-chunk XOR swizzle.
// ---------------------------------------------------------------------------
#define PL_SMEM (2 * 32768)   // 65536

template<int WIN>
__global__ void __launch_bounds__(256, 2)
pl_kernel(const __half* __restrict__ aIn, const __half* __restrict__ wIn,
          const float* __restrict__ bst, __half* __restrict__ aOut)
{
    constexpr int P = WIN / 2;
    constexpr int K = WIN * 128;
    const uint32_t smb = smem_u32(sm_raw);
    const int s   = blockIdx.y;
    const int bm  = blockIdx.x * 128;
    const int tid = threadIdx.x;
    const int warp = tid >> 5, lane = tid & 31;
    const int warp_m = warp >> 2, warp_n = warp & 3;
    const int gid = lane >> 2, tg = lane & 3;

    const int j0 = (P - s) > 0 ? (P - s) : 0;
    const int j1 = (WIN - 1) < (P + SEQ - 1 - s) ? (WIN - 1) : (P + SEQ - 1 - s);
    const int nst = (j1 - j0 + 1) * 2;     // k64 stages

    float acc[4][4][4];
#pragma unroll
    for (int a = 0; a < 4; a++)
#pragma unroll
        for (int b = 0; b < 4; b++)
#pragma unroll
            for (int c = 0; c < 4; c++) acc[a][b][c] = 0.f;

    auto load_stage = [&](int st, int buf) {
        const int jj = j0 + (st >> 1);
        const int f0 = (st & 1) * 64;
        const int tsrc = s + jj - P;
        const int k0 = jj * 128 + f0;
        const uint32_t sb = smb + buf * 32768;
#pragma unroll
        for (int i = 0; i < 4; i++) {
            int idx = tid + i * 256;           // 0..1023
            int row = idx >> 3, ch = idx & 7;
            uint32_t d = sb + row * 128 + (((ch ^ (row & 7)) << 4));
            size_t aoff = ((size_t)(bm + row) * SEQ + tsrc) * 128 + f0 + ch * 8;
            size_t boff = ((size_t)(s * 128 + row)) * K + k0 + ch * 8;
            CP16(d,         (const char*)(aIn + aoff));
            CP16(d + 16384, (const char*)(wIn + boff));
        }
        CP_COMMIT();
    };

    load_stage(0, 0);

    for (int st = 0; st < nst; st++) {
        if (st + 1 < nst) {
            load_stage(st + 1, (st + 1) & 1);
            asm volatile("cp.async.wait_group 1;" ::: "memory");
        } else {
            asm volatile("cp.async.wait_group 0;" ::: "memory");
        }
        __syncthreads();

        const uint32_t ab = smb + (st & 1) * 32768;
#pragma unroll
        for (int kt = 0; kt < 4; kt++) {
            uint32_t bf[4][2];
#pragma unroll
            for (int nt = 0; nt < 4; nt++) {
                int br = warp_n * 32 + nt * 8 + gid;
                uint32_t base = ab + 16384 + br * 128 + tg * 4;
                int sw = br & 7;
                bf[nt][0] = lds32(base + (((kt * 2 + 0) ^ sw) << 4));
                bf[nt][1] = lds32(base + (((kt * 2 + 1) ^ sw) << 4));
            }
#pragma unroll
            for (int mt = 0; mt < 4; mt++) {
                int r0 = warp_m * 64 + mt * 16 + gid;
                int r1 = r0 + 8;
                uint32_t b0 = ab + r0 * 128 + tg * 4; int s0 = r0 & 7;
                uint32_t b1 = ab + r1 * 128 + tg * 4; int s1 = r1 & 7;
                uint32_t af[4];
                af[0] = lds32(b0 + (((kt * 2 + 0) ^ s0) << 4));
                af[1] = lds32(b1 + (((kt * 2 + 0) ^ s1) << 4));
                af[2] = lds32(b0 + (((kt * 2 + 1) ^ s0) << 4));
                af[3] = lds32(b1 + (((kt * 2 + 1) ^ s1) << 4));
#pragma unroll
                for (int nt = 0; nt < 4; nt++)
                    mma_f16(acc[mt][nt], af, bf[nt]);
            }
        }
        __syncthreads();
    }

    const float* bias = bst + s * 128;
#pragma unroll
    for (int mt = 0; mt < 4; mt++) {
        int rbase = warp_m * 64 + mt * 16 + gid;
#pragma unroll
        for (int half = 0; half < 2; half++) {
            int r = rbase + half * 8;
            size_t ob = ((size_t)(bm + r) * SEQ + s) * 128;
#pragma unroll
            for (int nt = 0; nt < 4; nt++) {
                int col = warp_n * 32 + nt * 8 + tg * 2;
                float v0 = fmaxf(acc[mt][nt][half * 2 + 0] + bias[col],     0.f);
                float v1 = fmaxf(acc[mt][nt][half * 2 + 1] + bias[col + 1], 0.f);
                *reinterpret_cast<uint32_t*>(aOut + ob + col) = hpack(v0, v1);
            }
        }
    }
}

// ---------------------------------------------------------------------------
// 5. conv1 via tensor cores. Per-batch CTA.
// ---------------------------------------------------------------------------
#define C1_STG   0
#define C1_A     10496
#define C1_W     (C1_A + 130*112)        // 25056
#define C1_STATS (C1_W + 3*64*112)       // 46560
#define CONV1_SMEM (C1_STATS + 2*64*4)   // 47072

__global__ void __launch_bounds__(256, 2)
conv1_kernel(const float* __restrict__ bias) {
    const uint32_t smb = smem_u32(sm_raw);
    const int b = blockIdx.x, t = threadIdx.x;
    const int warp = t >> 5, lane = t & 31;
    const int warp_m = warp >> 1, warp_n = warp & 1;
    const int gid = lane >> 2, tg = lane & 3;

    for (int i = t; i < 130 * 112 / 4; i += 256) sts32(smb + C1_A + i * 4, 0u);
    for (int i = t; i < 128; i += 256) sts32(smb + C1_STATS + i * 4, 0u);

    {
        const char* src = (const char*)(g_h1 + (size_t)b * SF);
        for (int i = t; i < 41 * 16; i += 256)
            CP16(smb + C1_STG + i * 16, src + i * 16);
        const char* wsrc = (const char*)g_wc1;
        for (int i = t; i < 3 * 64 * 56 * 2 / 16; i += 256)
            CP16(smb + C1_W + i * 16, wsrc + i * 16);
        CP_COMMIT(); CP_WAIT0();
    }
    __syncthreads();

    for (int idx = t; idx < 41 * 64; idx += 256) {
        int c = idx >> 6, f2 = idx & 63;
        uint32_t v = lds32(smb + C1_STG + c * 256 + f2 * 4);
        sts16(smb + C1_A + (2 * f2 + 1) * 112 + c * 2, (uint16_t)(v & 0xFFFF));
        sts16(smb + C1_A + (2 * f2 + 2) * 112 + c * 2, (uint16_t)(v >> 16));
    }
    __syncthreads();

    float acc[2][4][4];
#pragma unroll
    for (int a = 0; a < 2; a++)
#pragma unroll
        for (int bb = 0; bb < 4; bb++)
#pragma unroll
            for (int c = 0; c < 4; c++) acc[a][bb][c] = 0.f;

#pragma unroll
    for (int k = 0; k < 3; k++) {
#pragma unroll
        for (int ks = 0; ks < 3; ks++) {
            uint32_t bf[4][2];
#pragma unroll
            for (int nt = 0; nt < 4; nt++) {
                uint32_t ba = smb + C1_W + k * (64 * 112) + (warp_n * 32 + nt * 8 + gid) * 112 + ks * 32 + tg * 4;
                bf[nt][0] = lds32(ba);
                bf[nt][1] = lds32(ba + 16);
            }
#pragma unroll
            for (int mt = 0; mt < 2; mt++) {
                int r0 = warp_m * 32 + mt * 16 + gid + k;
                uint32_t a0a = smb + C1_A + r0 * 112 + ks * 32 + tg * 4;
                uint32_t a1a = a0a + 8 * 112;
                uint32_t af[4];
                af[0] = lds32(a0a);
                af[1] = lds32(a1a);
                af[2] = lds32(a0a + 16);
                af[3] = lds32(a1a + 16);
#pragma unroll
                for (int nt = 0; nt < 4; nt++)
                    mma_f16(acc[mt][nt], af, bf[nt]);
            }
        }
    }

    float s0[4], s1[4], q0[4], q1[4];
#pragma unroll
    for (int nt = 0; nt < 4; nt++) { s0[nt] = s1[nt] = q0[nt] = q1[nt] = 0.f; }
    __half* dst = g_c + (size_t)b * C64L;
#pragma unroll
    for (int mt = 0; mt < 2; mt++) {
        int l0 = warp_m * 32 + mt * 16 + gid;
#pragma unroll
        for (int nt = 0; nt < 4; nt++) {
            int o = warp_n * 32 + nt * 8 + tg * 2;
            float bb0 = bias[o], bb1 = bias[o + 1];
            float v0 = acc[mt][nt][0] + bb0, v1 = acc[mt][nt][1] + bb1;
            float v2 = acc[mt][nt][2] + bb0, v3 = acc[mt][nt][3] + bb1;
            *reinterpret_cast<uint32_t*>(dst + l0 * 64 + o)       = hpack(v0, v1);
            *reinterpret_cast<uint32_t*>(dst + (l0 + 8) * 64 + o) = hpack(v2, v3);
            s0[nt] += v0 + v2; s1[nt] += v1 + v3;
            q0[nt] += v0 * v0 + v2 * v2; q1[nt] += v1 * v1 + v3 * v3;
        }
    }
#pragma unroll
    for (int nt = 0; nt < 4; nt++) {
#pragma unroll
        for (int off = 4; off < 32; off <<= 1) {
            s0[nt] += __shfl_xor_sync(0xffffffffu, s0[nt], off);
            s1[nt] += __shfl_xor_sync(0xffffffffu, s1[nt], off);
            q0[nt] += __shfl_xor_sync(0xffffffffu, q0[nt], off);
            q1[nt] += __shfl_xor_sync(0xffffffffu, q1[nt], off);
        }
    }
    if (gid == 0) {
        float* sums = reinterpret_cast<float*>(sm_raw + C1_STATS);
        float* sqs  = sums + 64;
#pragma unroll
        for (int nt = 0; nt < 4; nt++) {
            int o = warp_n * 32 + nt * 8 + tg * 2;
            atomicAdd(&sums[o],     s0[nt]);
            atomicAdd(&sums[o + 1], s1[nt]);
            atomicAdd(&sqs[o],      q0[nt]);
            atomicAdd(&sqs[o + 1],  q1[nt]);
        }
    }
    __syncthreads();
    if (t < 64) {
        float* sums = reinterpret_cast<float*>(sm_raw + C1_STATS);
        atomicAdd(&g_bnsum[t], (double)sums[t]);
        atomicAdd(&g_bnsq[t],  (double)sums[64 + t]);
    }
}

__global__ void bn_fin_conv(const float* __restrict__ g, const float* __restrict__ bb) {
    int c = threadIdx.x;
    double inv = 1.0 / ((double)BATCH * 128.0);
    double mu = g_bnsum[c] * inv;
    double var = g_bnsq[c] * inv - mu * mu;
    float sc = g[c] * rsqrtf((float)var + 1e-5f);
    g_bnscale[c] = sc;
    g_bnshift[c] = bb[c] - (float)mu * sc;
}

// ---------------------------------------------------------------------------
// 8-9. FUSED capsroute
// ---------------------------------------------------------------------------
#define CR_A    0
#define CR_W    16640
#define CR_SOUT 32000
#define CR_SMEM (CR_SOUT + 128*73*4)   // 69376

__global__ void __launch_bounds__(256, 2)
capsroute_kernel(const float* __restrict__ cb,
                 const float* __restrict__ rW, const float* __restrict__ rb,
                 const float* __restrict__ fc1)
{
    const uint32_t smb = smem_u32(sm_raw);
    float* sout = reinterpret_cast<float*>(sm_raw + CR_SOUT);  // [128 l][73]
    __shared__ float red4[4][64];
    __shared__ float sfac[64];
    __shared__ float coef[2][64];
    __shared__ float warp_sq[8];
    __shared__ float factor_s[2];
    __shared__ float sv_s[2][128];
    __shared__ float yv_s[2][128];

    const int b = blockIdx.x, t = threadIdx.x;
    const int warp = t >> 5, lane = t & 31;
    const int warp_m = warp >> 1, g = warp & 1;
    const int gid = lane >> 2, tg = lane & 3;

    // zero halo rows 0 and 129
    if (t < 64) sts32(smb + CR_A + ((t < 32) ? 0 : (129 * 128)) + (t & 31) * 4, 0u);

    {
        const char* src = (const char*)(g_c + (size_t)b * C64L);
        for (int i = t; i < 128 * 8; i += 256) {
            int row = (i >> 3) + 1, ch = i & 7;
            CP16(smb + CR_A + row * 128 + ((ch ^ (row & 7)) << 4), src + (row - 1) * 128 + ch * 16);
        }
        const char* wsrc = (const char*)g_wc2;
        for (int i = t; i < 3 * 64 * 40 * 2 / 16; i += 256)
            CP16(smb + CR_W + i * 16, wsrc + i * 16);
        CP_COMMIT(); CP_WAIT0();
    }
    __syncthreads();

    // BN + ReLU in place on A rows 1..128
    for (int idx = t; idx < 128 * 32; idx += 256) {
        int r = (idx >> 5) + 1, wd = idx & 31;
        int o = wd * 2;
        uint32_t addr = smb + CR_A + r * 128 + (((wd >> 2) ^ (r & 7)) << 4) + ((wd * 4) & 15);
        uint32_t v = lds32(addr);
        __half2 h = *reinterpret_cast<__half2*>(&v);
        float f0 = fmaxf(__low2float(h)  * g_bnscale[o]     + g_bnshift[o],     0.f);
        float f1 = fmaxf(__high2float(h) * g_bnscale[o + 1] + g_bnshift[o + 1], 0.f);
        sts32(addr, hpack(f0, f1));
    }
    __syncthreads();

    float acc[2][4][4];
#pragma unroll
    for (int a = 0; a < 2; a++)
#pragma unroll
        for (int bb = 0; bb < 4; bb++)
#pragma unroll
            for (int c = 0; c < 4; c++) acc[a][bb][c] = 0.f;

#pragma unroll
    for (int k = 0; k < 3; k++) {
#pragma unroll
        for (int ks = 0; ks < 2; ks++) {
            uint32_t bf[4][2];
#pragma unroll
            for (int nt = 0; nt < 4; nt++) {
                uint32_t ba = smb + CR_W + k * (64 * 80) + (g * 32 + nt * 8 + gid) * 80 + ks * 32 + tg * 4;
                bf[nt][0] = lds32(ba);
                bf[nt][1] = lds32(ba + 16);
            }
            int cbase = g * 4 + ks * 2;
#pragma unroll
            for (int mt = 0; mt < 2; mt++) {
                int r0 = warp_m * 32 + mt * 16 + gid + k;
                int r1 = r0 + 8;
                uint32_t af[4];
                af[0] = lds32(smb + CR_A + r0 * 128 + (((cbase)     ^ (r0 & 7)) << 4) + tg * 4);
                af[1] = lds32(smb + CR_A + r1 * 128 + (((cbase)     ^ (r1 & 7)) << 4) + tg * 4);
                af[2] = lds32(smb + CR_A + r0 * 128 + (((cbase + 1) ^ (r0 & 7)) << 4) + tg * 4);
                af[3] = lds32(smb + CR_A + r1 * 128 + (((cbase + 1) ^ (r1 & 7)) << 4) + tg * 4);
#pragma unroll
                for (int nt = 0; nt < 4; nt++)
                    mma_f16(acc[mt][nt], af, bf[nt]);
            }
        }
    }

#pragma unroll
    for (int mt = 0; mt < 2; mt++) {
        int l0 = warp_m * 32 + mt * 16 + gid;
#pragma unroll
        for (int nt = 0; nt < 4; nt++) {
            int o = g * 32 + nt * 8 + tg * 2;
            float bb0 = cb[o], bb1 = cb[o + 1];
            sout[l0 * 73 + o]           = acc[mt][nt][0] + bb0;
            sout[l0 * 73 + o + 1]       = acc[mt][nt][1] + bb1;
            sout[(l0 + 8) * 73 + o]     = acc[mt][nt][2] + bb0;
            sout[(l0 + 8) * 73 + o + 1] = acc[mt][nt][3] + bb1;
        }
    }
    __syncthreads();

    {
        int o = t & 63, seg = t >> 6;
        float p = 0.f;
        for (int l = seg * 32; l < seg * 32 + 32; l++) {
            float v = sout[l * 73 + o];
            p += v * v;
        }
        red4[seg][o] = p;
    }
    __syncthreads();
    if (t < 64) {
        float tot = red4[0][t] + red4[1][t] + red4[2][t] + red4[3][t];
        sfac[t] = squash_factor(tot);
    }
    __syncthreads();
    if (t < 128) {
        int i = t >> 6, j = t & 63;
        coef[i][j] = sfac[j] * (1.0f + rb[i * 64 + j]);
    }
    __syncthreads();

    int i = t >> 7;
    int f = t & 127;
    float acc2 = 0.f;
    const float* rwi = rW + i * 8192 + f;
    const float* srow = sout + f * 73;
#pragma unroll 8
    for (int j = 0; j < 64; j++)
        acc2 += srow[j] * rwi[j * 128] * coef[i][j];

    float sq = acc2 * acc2;
    for (int off = 16; off; off >>= 1) sq += __shfl_xor_sync(0xffffffffu, sq, off);
    if ((t & 31) == 0) warp_sq[t >> 5] = sq;
    __syncthreads();
    if (t < 2) {
        float tot = warp_sq[t * 4 + 0] + warp_sq[t * 4 + 1] + warp_sq[t * 4 + 2] + warp_sq[t * 4 + 3];
        factor_s[t] = squash_factor(tot);
    }
    __syncthreads();
    sv_s[i][f] = acc2 * factor_s[i];
    __syncthreads();
    yv_s[i][f] = sv_s[i][f] + fmaxf(sv_s[0][f], sv_s[1][f]);
    __syncthreads();

    // fc1 on all 256 threads: pair p splits the 128-ff loop
    {
        int ii = t >> 7;
        int o  = (t >> 1) & 63;
        int p  = t & 1;
        float a = 0.f;
        const float* yb = yv_s[ii];
        const float* fb = fc1 + p * 64 * 64 + o;
#pragma unroll 8
        for (int ff = 0; ff < 64; ff++) a += yb[p * 64 + ff] * fb[ff * 64];
        a += __shfl_xor_sync(0xffffffffu, a, 1);
        double s = 0.0, q = 0.0;
        if (p == 0) {
            g_g1[(size_t)b * 128 + ii * 64 + o] = a;
            s = a; q = (double)a * a;
        }
        for (int off = 16; off; off >>= 1) {
            s += __shfl_xor_sync(0xffffffffu, s, off);
            q += __shfl_xor_sync(0xffffffffu, q, off);
        }
        if ((t & 31) == 0) {
            atomicAdd(&g_bn1acc[ii], s);
            atomicAdd(&g_bn1acc[2 + ii], q);
        }
    }
}

__global__ void bn1_fin(const float* __restrict__ g, const float* __restrict__ bb) {
    int i = threadIdx.x;
    double inv = 1.0 / ((double)BATCH * 64.0);
    double mu = g_bn1acc[i] * inv;
    double var = g_bn1acc[2 + i] * inv - mu * mu;
    float sc = g[i] * rsqrtf((float)var + 1e-5f);
    g_bn1p[i] = sc;
    g_bn1p[2 + i] = bb[i] - (float)mu * sc;
}

// ---------------------------------------------------------------------------
// 11. head1
// ---------------------------------------------------------------------------
__global__ void head1_kernel(const float* __restrict__ fc2) {
    __shared__ float a_s[4][128];
    int t = threadIdx.x;
    for (int idx = t; idx < 512; idx += 256) {
        int lbb = idx >> 7, rr = idx & 127;
        int ii = rr >> 6;
        float v = g_g1[(size_t)(blockIdx.x * 4 + lbb) * 128 + rr];
        a_s[lbb][rr] = fmaxf(v * g_bn1p[ii] + g_bn1p[2 + ii], 0.f);
    }
    __syncthreads();
    int lb = t >> 6, r = t & 63;
    int b = blockIdx.x * 4 + lb;
    int ii = r >> 5, m = r & 31;
    float acc = 0.f;
    const float* arow = &a_s[lb][ii * 64];
#pragma unroll 8
    for (int o = 0; o < 64; o++) acc += arow[o] * fc2[o * 32 + m];
    g_g2[(size_t)b * 64 + ii * 32 + m] = acc;
    double s = acc, q = (double)acc * acc;
    for (int off = 16; off; off >>= 1) {
        s += __shfl_xor_sync(0xffffffffu, s, off);
        q += __shfl_xor_sync(0xffffffffu, q, off);
    }
    if ((t & 31) == 0) {
        atomicAdd(&g_bn2acc[ii], s);
        atomicAdd(&g_bn2acc[2 + ii], q);
    }
}

__global__ void bn2_fin(const float* __restrict__ g, const float* __restrict__ bb) {
    int i = threadIdx.x;
    double inv = 1.0 / ((double)BATCH * 32.0);
    double mu = g_bn2acc[i] * inv;
    double var = g_bn2acc[2 + i] * inv - mu * mu;
    float sc = g[i] * rsqrtf((float)var + 1e-5f);
    g_bn2p[i] = sc;
    g_bn2p[2 + i] = bb[i] - (float)mu * sc;
}

// ---------------------------------------------------------------------------
// 13. head2
// ---------------------------------------------------------------------------
__global__ void head2_kernel(const float* __restrict__ fc3, float* __restrict__ out) {
    int b = blockIdx.x * 256 + threadIdx.x;
    if (b >= BATCH) return;
    float best = -1e30f;
#pragma unroll
    for (int i = 0; i < 2; i++) {
        float sc = g_bn2p[i], sh = g_bn2p[2 + i];
        float s = 0.f;
#pragma unroll
        for (int m = 0; m < 32; m++) {
            float v = fmaxf(g_g2[(size_t)b * 64 + i * 32 + m] * sc + sh, 0.f);
            s += v * fc3[m];
        }
        float sig = 1.f / (1.f + expf(-s));
        best = fmaxf(best, sig);
    }
    out[b] = best;
}

// ---------------------------------------------------------------------------
// launch
// ---------------------------------------------------------------------------
extern "C" void kernel_launch(void* const* d_in, const int* in_sizes, int n_in,
                              void* d_out, int out_size)
{
    const int*   x      = (const int*)d_in[0];
    const float* emb    = (const float*)d_in[1];
    const float* W3     = (const float*)d_in[2];
    const float* b3     = (const float*)d_in[3];
    const float* W5     = (const float*)d_in[4];
    const float* b5     = (const float*)d_in[5];
    const float* W7     = (const float*)d_in[6];
    const float* b7     = (const float*)d_in[7];
    const float* conv1w = (const float*)d_in[8];
    const float* conv1b = (const float*)d_in[9];
    const float* bng    = (const float*)d_in[10];
    const float* bnb    = (const float*)d_in[11];
    const float* capsw  = (const float*)d_in[12];
    const float* capsb  = (const float*)d_in[13];
    const float* routeW = (const float*)d_in[14];
    const float* routeb = (const float*)d_in[15];
    const float* fc1    = (const float*)d_in[16];
    const float* bn1g   = (const float*)d_in[17];
    const float* bn1b   = (const float*)d_in[18];
    const float* fc2    = (const float*)d_in[19];
    const float* bn2g   = (const float*)d_in[20];
    const float* bn2b   = (const float*)d_in[21];
    const float* fc3    = (const float*)d_in[22];
    float* out = (float*)d_out;

    cudaFuncSetAttribute(conv1_kernel,     cudaFuncAttributeMaxDynamicSharedMemorySize, CONV1_SMEM);
    cudaFuncSetAttribute(capsroute_kernel, cudaFuncAttributeMaxDynamicSharedMemorySize, CR_SMEM);
    cudaFuncSetAttribute(pl_kernel<3>, cudaFuncAttributeMaxDynamicSharedMemorySize, PL_SMEM);
    cudaFuncSetAttribute(pl_kernel<5>, cudaFuncAttributeMaxDynamicSharedMemorySize, PL_SMEM);
    cudaFuncSetAttribute(pl_kernel<7>, cudaFuncAttributeMaxDynamicSharedMemorySize, PL_SMEM);

    __half *h0, *h1, *w16;
    cudaGetSymbolAddress((void**)&h0,  g_h0);
    cudaGetSymbolAddress((void**)&h1,  g_h1);
    cudaGetSymbolAddress((void**)&w16, g_w16);

    wprep_conv<<<42, 256>>>(conv1w, capsw);
    embed_kernel<<<(BATCH * SEQ * 16 + 255) / 256, 256>>>(x, emb);
    wprep_all<<<dim3(60, 41), 256>>>(W3, W5, W7);

    pl_kernel<3><<<dim3(32, 41), 256, PL_SMEM>>>(h0, w16 + WOFF3, b3, h1);
    pl_kernel<5><<<dim3(32, 41), 256, PL_SMEM>>>(h1, w16 + WOFF5, b5, h0);
    pl_kernel<7><<<dim3(32, 41), 256, PL_SMEM>>>(h0, w16 + WOFF7, b7, h1);

    conv1_kernel<<<BATCH, 256, CONV1_SMEM>>>(conv1b);
    bn_fin_conv<<<1, 64>>>(bng, bnb);
    capsroute_kernel<<<BATCH, 256, CR_SMEM>>>(capsb, routeW, routeb, fc1);
    bn1_fin<<<1, 2>>>(bn1g, bn1b);
    head1_kernel<<<BATCH / 4, 256>>>(fc2);
    bn2_fin<<<1, 2>>>(bn2g, bn2b);
    head2_kernel<<<(BATCH + 255) / 256, 256>>>(fc3, out);
}

// round 9
// speedup vs baseline: 4.9061x; 1.0328x over previous
#include <cuda_runtime.h>
#include <cuda_fp16.h>
#include <math.h>
#include <stdint.h>

// ---------------------------------------------------------------------------
// Problem constants
// ---------------------------------------------------------------------------
#define BATCH 4096
#define SEQ   41
#define FDIM  128
#define SF    (SEQ*FDIM)        // 5248
#define C64L  (64*128)          // 8192

// ---------------------------------------------------------------------------
// Scratch (device globals; allocation-free contract)
// ---------------------------------------------------------------------------
__device__ __align__(256) __half g_h0[(size_t)BATCH * SF];   // activation ping
__device__ __align__(256) __half g_h1[(size_t)BATCH * SF];   // activation pong
__device__ __align__(256) __half g_c[(size_t)BATCH * C64L];  // conv1 out [b][l=128][o=64]
__device__ __align__(256) float  g_g1[(size_t)BATCH * 128];  // [B,2,64]
__device__ __align__(256) float  g_g2[(size_t)BATCH * 64];   // [B,2,32]
__device__ double g_bnsum[64], g_bnsq[64];
__device__ float  g_bnscale[64], g_bnshift[64];
__device__ double g_bn1acc[4];
__device__ double g_bn2acc[4];
__device__ float  g_bn1p[4];
__device__ float  g_bn2p[4];

// transposed fp16 PL weights: layout [s][n=128][K], layers packed
#define WOFF3 ((size_t)0)
#define WOFF5 ((size_t)41*384*128)
#define WOFF7 ((size_t)(41*384*128) + (size_t)41*640*128)
#define WTOT  ((size_t)41*1920*128)
__device__ __align__(256) __half g_w16[WTOT];

// conv weights fp16, pitched: wc1 [3][64][56], wc2 [3][64][40]
__device__ __align__(256) __half g_wc1[3*64*56];
__device__ __align__(256) __half g_wc2[3*64*40];

// single shared extern symbol for all dynamic-smem kernels
extern __shared__ __align__(1024) char sm_raw[];

__device__ __forceinline__ float squash_factor(float ssq) {
    float n = sqrtf(ssq);
    return (1.f - 1.f / (expf(n) + 1e-21f)) / (n + 1e-21f);
}

// ---------------------------------------------------------------------------
// PTX helpers (compute_100-safe: mma.sync + cp.async + ldmatrix)
// ---------------------------------------------------------------------------
__device__ __forceinline__ uint32_t smem_u32(const void* p) {
    uint32_t a;
    asm("{ .reg .u64 t; cvta.to.shared.u64 t, %1; cvt.u32.u64 %0, t; }" : "=r"(a) : "l"(p));
    return a;
}
__device__ __forceinline__ uint32_t lds32(uint32_t a) {
    uint32_t v;
    asm volatile("ld.shared.b32 %0, [%1];" : "=r"(v) : "r"(a));
    return v;
}
__device__ __forceinline__ void sts32(uint32_t a, uint32_t v) {
    asm volatile("st.shared.b32 [%0], %1;" :: "r"(a), "r"(v));
}
__device__ __forceinline__ void sts16(uint32_t a, uint16_t v) {
    asm volatile("st.shared.u16 [%0], %1;" :: "r"(a), "h"(v));
}
__device__ __forceinline__ void ldsm_x4(uint32_t* r, uint32_t addr) {
    asm volatile("ldmatrix.sync.aligned.m8n8.x4.shared.b16 {%0,%1,%2,%3}, [%4];"
        : "=r"(r[0]), "=r"(r[1]), "=r"(r[2]), "=r"(r[3]) : "r"(addr));
}
__device__ __forceinline__ void mma_f16(float* c, const uint32_t* a, const uint32_t* b) {
    asm volatile(
        "mma.sync.aligned.m16n8k16.row.col.f32.f16.f16.f32 "
        "{%0,%1,%2,%3}, {%4,%5,%6,%7}, {%8,%9}, {%0,%1,%2,%3};"
        : "+f"(c[0]), "+f"(c[1]), "+f"(c[2]), "+f"(c[3])
        : "r"(a[0]), "r"(a[1]), "r"(a[2]), "r"(a[3]), "r"(b[0]), "r"(b[1]));
}
#define CP16(dst, src)    asm volatile("cp.async.cg.shared.global [%0], [%1], 16;" :: "r"(dst), "l"(src))
#define CP_COMMIT()       asm volatile("cp.async.commit_group;" ::: "memory")
#define CP_WAIT0()        asm volatile("cp.async.wait_group 0;" ::: "memory")

__device__ __forceinline__ uint32_t hpack(float a, float b) {
    __half2 t = __floats2half2_rn(a, b);
    return *reinterpret_cast<uint32_t*>(&t);
}

// ---------------------------------------------------------------------------
// 0. conv weight prep + accumulator zero (single launch)
// ---------------------------------------------------------------------------
__global__ void wprep_conv(const float* __restrict__ c1w, const float* __restrict__ c2w) {
    int t = blockIdx.x * 256 + threadIdx.x;
    if (blockIdx.x == 0) {
        int tt = threadIdx.x;
        if (tt < 64) { g_bnsum[tt] = 0.0; g_bnsq[tt] = 0.0; }
        if (tt < 4)  { g_bn1acc[tt] = 0.0; g_bn2acc[tt] = 0.0; }
    }
    if (t < 3 * 64 * 56) {
        int c = t % 56, o = (t / 56) % 64, k = t / (56 * 64);
        g_wc1[t] = (c < 41) ? __float2half(c1w[(o * 41 + c) * 3 + k]) : __float2half(0.f);
    }
    if (t < 3 * 64 * 40) {
        int c = t % 40, o = (t / 40) % 64, k = t / (40 * 64);
        g_wc2[t] = (c < 32) ? __float2half(c2w[(o * 32 + c) * 3 + k]) : __float2half(0.f);
    }
}

// ---------------------------------------------------------------------------
// 1. embedding gather -> g_h0 fp16
// ---------------------------------------------------------------------------
__global__ void embed_kernel(const int* __restrict__ x, const float* __restrict__ emb) {
    int gid = blockIdx.x * 256 + threadIdx.x;
    int pos = gid >> 4;
    int f0  = (gid & 15) * 8;
    if (pos >= BATCH * SEQ) return;
    int e = x[pos];
    const float4* sp = reinterpret_cast<const float4*>(emb + e * FDIM + f0);
    float4 v0 = sp[0], v1 = sp[1];
    uint4 o;
    o.x = hpack(v0.x, v0.y); o.y = hpack(v0.z, v0.w);
    o.z = hpack(v1.x, v1.y); o.w = hpack(v1.z, v1.w);
    *reinterpret_cast<uint4*>(g_h0 + (size_t)pos * FDIM + f0) = o;
}

// ---------------------------------------------------------------------------
// 1b. PL weight prep, all 3 layers in one launch.
// ---------------------------------------------------------------------------
__global__ void wprep_all(const float* __restrict__ W3, const float* __restrict__ W5,
                          const float* __restrict__ W7) {
    __shared__ float tile[32][129];
    int bx = blockIdx.x, s = blockIdx.y, t = threadIdx.x;
    const float* W; __half* o; int K, kb;
    if (bx < 12)      { W = W3; o = g_w16 + WOFF3; K = 384; kb = bx * 32; }
    else if (bx < 32) { W = W5; o = g_w16 + WOFF5; K = 640; kb = (bx - 12) * 32; }
    else              { W = W7; o = g_w16 + WOFF7; K = 896; kb = (bx - 32) * 32; }
#pragma unroll
    for (int i = 0; i < 16; i++) {
        int e = t + i * 256;
        int kk = e >> 7, n = e & 127;
        tile[kk][n] = W[((size_t)s * K + kb + kk) * 128 + n];
    }
    __syncthreads();
    int n = t >> 1, h = (t & 1) * 16;
    size_t ob = ((size_t)(s * 128 + n)) * K + kb + h;
#pragma unroll
    for (int kk = 0; kk < 16; kk += 2) {
        *reinterpret_cast<uint32_t*>(&o[ob + kk]) = hpack(tile[h + kk][n], tile[h + kk + 1][n]);
    }
}

// ---------------------------------------------------------------------------
// 2-4. position_linear via warp-level fp16 MMA, K-chunk 64, ldmatrix frag loads.
// ---------------------------------------------------------------------------
#define PL_SMEM (2 * 32768)   // 65536

template<int WIN>
__global__ void __launch_bounds__(256, 2)
pl_kernel(const __half* __restrict__ aIn, const __half* __restrict__ wIn,
          const float* __restrict__ bst, __half* __restrict__ aOut)
{
    constexpr int P = WIN / 2;
    constexpr int K = WIN * 128;
    const uint32_t smb = smem_u32(sm_raw);
    const int s   = blockIdx.y;
    const int bm  = blockIdx.x * 128;
    const int tid = threadIdx.x;
    const int warp = tid >> 5, lane = tid & 31;
    const int warp_m = warp >> 2, warp_n = warp & 3;
    const int gid = lane >> 2, tg = lane & 3;

    const int j0 = (P - s) > 0 ? (P - s) : 0;
    const int j1 = (WIN - 1) < (P + SEQ - 1 - s) ? (WIN - 1) : (P + SEQ - 1 - s);
    const int nst = (j1 - j0 + 1) * 2;     // k64 stages

    // ldmatrix lane-invariant address components
    const int a_moff = (lane & 7) + ((lane >> 3) & 1) * 8;   // m offset within 16
    const int a_cbit = lane >> 4;                            // k-half select
    const int b_roff = ((lane >> 4) & 1) * 8 + (lane & 7);   // n offset within pair
    const int b_cbit = (lane >> 3) & 1;                      // k-half select

    float acc[4][4][4];
#pragma unroll
    for (int a = 0; a < 4; a++)
#pragma unroll
        for (int b = 0; b < 4; b++)
#pragma unroll
            for (int c = 0; c < 4; c++) acc[a][b][c] = 0.f;

    auto load_stage = [&](int st, int buf) {
        const int jj = j0 + (st >> 1);
        const int f0 = (st & 1) * 64;
        const int tsrc = s + jj - P;
        const int k0 = jj * 128 + f0;
        const uint32_t sb = smb + buf * 32768;
#pragma unroll
        for (int i = 0; i < 4; i++) {
            int idx = tid + i * 256;           // 0..1023
            int row = idx >> 3, ch = idx & 7;
            uint32_t d = sb + row * 128 + (((ch ^ (row & 7)) << 4));
            size_t aoff = ((size_t)(bm + row) * SEQ + tsrc) * 128 + f0 + ch * 8;
            size_t boff = ((size_t)(s * 128 + row)) * K + k0 + ch * 8;
            CP16(d,         (const char*)(aIn + aoff));
            CP16(d + 16384, (const char*)(wIn + boff));
        }
        CP_COMMIT();
    };

    load_stage(0, 0);

    for (int st = 0; st < nst; st++) {
        if (st + 1 < nst) {
            load_stage(st + 1, (st + 1) & 1);
            asm volatile("cp.async.wait_group 1;" ::: "memory");
        } else {
            asm volatile("cp.async.wait_group 0;" ::: "memory");
        }
        __syncthreads();

        const uint32_t ab = smb + (st & 1) * 32768;
#pragma unroll
        for (int kt = 0; kt < 4; kt++) {
            uint32_t bf[4][2];
#pragma unroll
            for (int p = 0; p < 2; p++) {
                int row = warp_n * 32 + p * 16 + b_roff;
                int sw = row & 7;
                uint32_t addr = ab + 16384 + row * 128 + (((kt * 2 + b_cbit) ^ sw) << 4);
                uint32_t r[4];
                ldsm_x4(r, addr);
                bf[2 * p][0] = r[0]; bf[2 * p][1] = r[1];
                bf[2 * p + 1][0] = r[2]; bf[2 * p + 1][1] = r[3];
            }
#pragma unroll
            for (int mt = 0; mt < 4; mt++) {
                int row = warp_m * 64 + mt * 16 + a_moff;
                int sw = row & 7;
                uint32_t addr = ab + row * 128 + (((kt * 2 + a_cbit) ^ sw) << 4);
                uint32_t af[4];
                ldsm_x4(af, addr);
#pragma unroll
                for (int nt = 0; nt < 4; nt++)
                    mma_f16(acc[mt][nt], af, bf[nt]);
            }
        }
        __syncthreads();
    }

    const float* bias = bst + s * 128;
#pragma unroll
    for (int mt = 0; mt < 4; mt++) {
        int rbase = warp_m * 64 + mt * 16 + gid;
#pragma unroll
        for (int half = 0; half < 2; half++) {
            int r = rbase + half * 8;
            size_t ob = ((size_t)(bm + r) * SEQ + s) * 128;
#pragma unroll
            for (int nt = 0; nt < 4; nt++) {
                int col = warp_n * 32 + nt * 8 + tg * 2;
                float v0 = fmaxf(acc[mt][nt][half * 2 + 0] + bias[col],     0.f);
                float v1 = fmaxf(acc[mt][nt][half * 2 + 1] + bias[col + 1], 0.f);
                *reinterpret_cast<uint32_t*>(aOut + ob + col) = hpack(v0, v1);
            }
        }
    }
}

// ---------------------------------------------------------------------------
// 5. conv1 via tensor cores. Per-batch CTA.
// ---------------------------------------------------------------------------
#define C1_STG   0
#define C1_A     10496
#define C1_W     (C1_A + 130*112)        // 25056
#define C1_STATS (C1_W + 3*64*112)       // 46560
#define CONV1_SMEM (C1_STATS + 2*64*4)   // 47072

__global__ void __launch_bounds__(256, 2)
conv1_kernel(const float* __restrict__ bias) {
    const uint32_t smb = smem_u32(sm_raw);
    const int b = blockIdx.x, t = threadIdx.x;
    const int warp = t >> 5, lane = t & 31;
    const int warp_m = warp >> 1, warp_n = warp & 1;
    const int gid = lane >> 2, tg = lane & 3;

    for (int i = t; i < 130 * 112 / 4; i += 256) sts32(smb + C1_A + i * 4, 0u);
    for (int i = t; i < 128; i += 256) sts32(smb + C1_STATS + i * 4, 0u);

    {
        const char* src = (const char*)(g_h1 + (size_t)b * SF);
        for (int i = t; i < 41 * 16; i += 256)
            CP16(smb + C1_STG + i * 16, src + i * 16);
        const char* wsrc = (const char*)g_wc1;
        for (int i = t; i < 3 * 64 * 56 * 2 / 16; i += 256)
            CP16(smb + C1_W + i * 16, wsrc + i * 16);
        CP_COMMIT(); CP_WAIT0();
    }
    __syncthreads();

    for (int idx = t; idx < 41 * 64; idx += 256) {
        int c = idx >> 6, f2 = idx & 63;
        uint32_t v = lds32(smb + C1_STG + c * 256 + f2 * 4);
        sts16(smb + C1_A + (2 * f2 + 1) * 112 + c * 2, (uint16_t)(v & 0xFFFF));
        sts16(smb + C1_A + (2 * f2 + 2) * 112 + c * 2, (uint16_t)(v >> 16));
    }
    __syncthreads();

    float acc[2][4][4];
#pragma unroll
    for (int a = 0; a < 2; a++)
#pragma unroll
        for (int bb = 0; bb < 4; bb++)
#pragma unroll
            for (int c = 0; c < 4; c++) acc[a][bb][c] = 0.f;

#pragma unroll
    for (int k = 0; k < 3; k++) {
#pragma unroll
        for (int ks = 0; ks < 3; ks++) {
            uint32_t bf[4][2];
#pragma unroll
            for (int nt = 0; nt < 4; nt++) {
                uint32_t ba = smb + C1_W + k * (64 * 112) + (warp_n * 32 + nt * 8 + gid) * 112 + ks * 32 + tg * 4;
                bf[nt][0] = lds32(ba);
                bf[nt][1] = lds32(ba + 16);
            }
#pragma unroll
            for (int mt = 0; mt < 2; mt++) {
                int r0 = warp_m * 32 + mt * 16 + gid + k;
                uint32_t a0a = smb + C1_A + r0 * 112 + ks * 32 + tg * 4;
                uint32_t a1a = a0a + 8 * 112;
                uint32_t af[4];
                af[0] = lds32(a0a);
                af[1] = lds32(a1a);
                af[2] = lds32(a0a + 16);
                af[3] = lds32(a1a + 16);
#pragma unroll
                for (int nt = 0; nt < 4; nt++)
                    mma_f16(acc[mt][nt], af, bf[nt]);
            }
        }
    }

    float s0[4], s1[4], q0[4], q1[4];
#pragma unroll
    for (int nt = 0; nt < 4; nt++) { s0[nt] = s1[nt] = q0[nt] = q1[nt] = 0.f; }
    __half* dst = g_c + (size_t)b * C64L;
#pragma unroll
    for (int mt = 0; mt < 2; mt++) {
        int l0 = warp_m * 32 + mt * 16 + gid;
#pragma unroll
        for (int nt = 0; nt < 4; nt++) {
            int o = warp_n * 32 + nt * 8 + tg * 2;
            float bb0 = bias[o], bb1 = bias[o + 1];
            float v0 = acc[mt][nt][0] + bb0, v1 = acc[mt][nt][1] + bb1;
            float v2 = acc[mt][nt][2] + bb0, v3 = acc[mt][nt][3] + bb1;
            *reinterpret_cast<uint32_t*>(dst + l0 * 64 + o)       = hpack(v0, v1);
            *reinterpret_cast<uint32_t*>(dst + (l0 + 8) * 64 + o) = hpack(v2, v3);
            s0[nt] += v0 + v2; s1[nt] += v1 + v3;
            q0[nt] += v0 * v0 + v2 * v2; q1[nt] += v1 * v1 + v3 * v3;
        }
    }
#pragma unroll
    for (int nt = 0; nt < 4; nt++) {
#pragma unroll
        for (int off = 4; off < 32; off <<= 1) {
            s0[nt] += __shfl_xor_sync(0xffffffffu, s0[nt], off);
            s1[nt] += __shfl_xor_sync(0xffffffffu, s1[nt], off);
            q0[nt] += __shfl_xor_sync(0xffffffffu, q0[nt], off);
            q1[nt] += __shfl_xor_sync(0xffffffffu, q1[nt], off);
        }
    }
    if (gid == 0) {
        float* sums = reinterpret_cast<float*>(sm_raw + C1_STATS);
        float* sqs  = sums + 64;
#pragma unroll
        for (int nt = 0; nt < 4; nt++) {
            int o = warp_n * 32 + nt * 8 + tg * 2;
            atomicAdd(&sums[o],     s0[nt]);
            atomicAdd(&sums[o + 1], s1[nt]);
            atomicAdd(&sqs[o],      q0[nt]);
            atomicAdd(&sqs[o + 1],  q1[nt]);
        }
    }
    __syncthreads();
    if (t < 64) {
        float* sums = reinterpret_cast<float*>(sm_raw + C1_STATS);
        atomicAdd(&g_bnsum[t], (double)sums[t]);
        atomicAdd(&g_bnsq[t],  (double)sums[64 + t]);
    }
}

__global__ void bn_fin_conv(const float* __restrict__ g, const float* __restrict__ bb) {
    int c = threadIdx.x;
    double inv = 1.0 / ((double)BATCH * 128.0);
    double mu = g_bnsum[c] * inv;
    double var = g_bnsq[c] * inv - mu * mu;
    float sc = g[c] * rsqrtf((float)var + 1e-5f);
    g_bnscale[c] = sc;
    g_bnshift[c] = bb[c] - (float)mu * sc;
}

// ---------------------------------------------------------------------------
// 8-9. FUSED capsroute
// ---------------------------------------------------------------------------
#define CR_A    0
#define CR_W    16640
#define CR_SOUT 32000
#define CR_SMEM (CR_SOUT + 128*73*4)   // 69376

__global__ void __launch_bounds__(256, 2)
capsroute_kernel(const float* __restrict__ cb,
                 const float* __restrict__ rW, const float* __restrict__ rb,
                 const float* __restrict__ fc1)
{
    const uint32_t smb = smem_u32(sm_raw);
    float* sout = reinterpret_cast<float*>(sm_raw + CR_SOUT);  // [128 l][73]
    __shared__ float red4[4][64];
    __shared__ float sfac[64];
    __shared__ float coef[2][64];
    __shared__ float warp_sq[8];
    __shared__ float factor_s[2];
    __shared__ float sv_s[2][128];
    __shared__ float yv_s[2][128];

    const int b = blockIdx.x, t = threadIdx.x;
    const int warp = t >> 5, lane = t & 31;
    const int warp_m = warp >> 1, g = warp & 1;
    const int gid = lane >> 2, tg = lane & 3;

    // zero halo rows 0 and 129
    if (t < 64) sts32(smb + CR_A + ((t < 32) ? 0 : (129 * 128)) + (t & 31) * 4, 0u);

    {
        const char* src = (const char*)(g_c + (size_t)b * C64L);
        for (int i = t; i < 128 * 8; i += 256) {
            int row = (i >> 3) + 1, ch = i & 7;
            CP16(smb + CR_A + row * 128 + ((ch ^ (row & 7)) << 4), src + (row - 1) * 128 + ch * 16);
        }
        const char* wsrc = (const char*)g_wc2;
        for (int i = t; i < 3 * 64 * 40 * 2 / 16; i += 256)
            CP16(smb + CR_W + i * 16, wsrc + i * 16);
        CP_COMMIT(); CP_WAIT0();
    }
    __syncthreads();

    // BN + ReLU in place on A rows 1..128
    for (int idx = t; idx < 128 * 32; idx += 256) {
        int r = (idx >> 5) + 1, wd = idx & 31;
        int o = wd * 2;
        uint32_t addr = smb + CR_A + r * 128 + (((wd >> 2) ^ (r & 7)) << 4) + ((wd * 4) & 15);
        uint32_t v = lds32(addr);
        __half2 h = *reinterpret_cast<__half2*>(&v);
        float f0 = fmaxf(__low2float(h)  * g_bnscale[o]     + g_bnshift[o],     0.f);
        float f1 = fmaxf(__high2float(h) * g_bnscale[o + 1] + g_bnshift[o + 1], 0.f);
        sts32(addr, hpack(f0, f1));
    }
    __syncthreads();

    float acc[2][4][4];
#pragma unroll
    for (int a = 0; a < 2; a++)
#pragma unroll
        for (int bb = 0; bb < 4; bb++)
#pragma unroll
            for (int c = 0; c < 4; c++) acc[a][bb][c] = 0.f;

#pragma unroll
    for (int k = 0; k < 3; k++) {
#pragma unroll
        for (int ks = 0; ks < 2; ks++) {
            uint32_t bf[4][2];
#pragma unroll
            for (int nt = 0; nt < 4; nt++) {
                uint32_t ba = smb + CR_W + k * (64 * 80) + (g * 32 + nt * 8 + gid) * 80 + ks * 32 + tg * 4;
                bf[nt][0] = lds32(ba);
                bf[nt][1] = lds32(ba + 16);
            }
            int cbase = g * 4 + ks * 2;
#pragma unroll
            for (int mt = 0; mt < 2; mt++) {
                int r0 = warp_m * 32 + mt * 16 + gid + k;
                int r1 = r0 + 8;
                uint32_t af[4];
                af[0] = lds32(smb + CR_A + r0 * 128 + (((cbase)     ^ (r0 & 7)) << 4) + tg * 4);
                af[1] = lds32(smb + CR_A + r1 * 128 + (((cbase)     ^ (r1 & 7)) << 4) + tg * 4);
                af[2] = lds32(smb + CR_A + r0 * 128 + (((cbase + 1) ^ (r0 & 7)) << 4) + tg * 4);
                af[3] = lds32(smb + CR_A + r1 * 128 + (((cbase + 1) ^ (r1 & 7)) << 4) + tg * 4);
#pragma unroll
                for (int nt = 0; nt < 4; nt++)
                    mma_f16(acc[mt][nt], af, bf[nt]);
            }
        }
    }

#pragma unroll
    for (int mt = 0; mt < 2; mt++) {
        int l0 = warp_m * 32 + mt * 16 + gid;
#pragma unroll
        for (int nt = 0; nt < 4; nt++) {
            int o = g * 32 + nt * 8 + tg * 2;
            float bb0 = cb[o], bb1 = cb[o + 1];
            sout[l0 * 73 + o]           = acc[mt][nt][0] + bb0;
            sout[l0 * 73 + o + 1]       = acc[mt][nt][1] + bb1;
            sout[(l0 + 8) * 73 + o]     = acc[mt][nt][2] + bb0;
            sout[(l0 + 8) * 73 + o + 1] = acc[mt][nt][3] + bb1;
        }
    }
    __syncthreads();

    {
        int o = t & 63, seg = t >> 6;
        float p = 0.f;
        for (int l = seg * 32; l < seg * 32 + 32; l++) {
            float v = sout[l * 73 + o];
            p += v * v;
        }
        red4[seg][o] = p;
    }
    __syncthreads();
    if (t < 64) {
        float tot = red4[0][t] + red4[1][t] + red4[2][t] + red4[3][t];
        sfac[t] = squash_factor(tot);
    }
    __syncthreads();
    if (t < 128) {
        int i = t >> 6, j = t & 63;
        coef[i][j] = sfac[j] * (1.0f + rb[i * 64 + j]);
    }
    __syncthreads();

    int i = t >> 7;
    int f = t & 127;
    float acc2 = 0.f;
    const float* rwi = rW + i * 8192 + f;
    const float* srow = sout + f * 73;
#pragma unroll 8
    for (int j = 0; j < 64; j++)
        acc2 += srow[j] * rwi[j * 128] * coef[i][j];

    float sq = acc2 * acc2;
    for (int off = 16; off; off >>= 1) sq += __shfl_xor_sync(0xffffffffu, sq, off);
    if ((t & 31) == 0) warp_sq[t >> 5] = sq;
    __syncthreads();
    if (t < 2) {
        float tot = warp_sq[t * 4 + 0] + warp_sq[t * 4 + 1] + warp_sq[t * 4 + 2] + warp_sq[t * 4 + 3];
        factor_s[t] = squash_factor(tot);
    }
    __syncthreads();
    sv_s[i][f] = acc2 * factor_s[i];
    __syncthreads();
    yv_s[i][f] = sv_s[i][f] + fmaxf(sv_s[0][f], sv_s[1][f]);
    __syncthreads();

    {
        int ii = t >> 7;
        int o  = (t >> 1) & 63;
        int p  = t & 1;
        float a = 0.f;
        const float* yb = yv_s[ii];
        const float* fb = fc1 + p * 64 * 64 + o;
#pragma unroll 8
        for (int ff = 0; ff < 64; ff++) a += yb[p * 64 + ff] * fb[ff * 64];
        a += __shfl_xor_sync(0xffffffffu, a, 1);
        double s = 0.0, q = 0.0;
        if (p == 0) {
            g_g1[(size_t)b * 128 + ii * 64 + o] = a;
            s = a; q = (double)a * a;
        }
        for (int off = 16; off; off >>= 1) {
            s += __shfl_xor_sync(0xffffffffu, s, off);
            q += __shfl_xor_sync(0xffffffffu, q, off);
        }
        if ((t & 31) == 0) {
            atomicAdd(&g_bn1acc[ii], s);
            atomicAdd(&g_bn1acc[2 + ii], q);
        }
    }
}

__global__ void bn1_fin(const float* __restrict__ g, const float* __restrict__ bb) {
    int i = threadIdx.x;
    double inv = 1.0 / ((double)BATCH * 64.0);
    double mu = g_bn1acc[i] * inv;
    double var = g_bn1acc[2 + i] * inv - mu * mu;
    float sc = g[i] * rsqrtf((float)var + 1e-5f);
    g_bn1p[i] = sc;
    g_bn1p[2 + i] = bb[i] - (float)mu * sc;
}

// ---------------------------------------------------------------------------
// 11. head1
// ---------------------------------------------------------------------------
__global__ void head1_kernel(const float* __restrict__ fc2) {
    __shared__ float a_s[4][128];
    int t = threadIdx.x;
    for (int idx = t; idx < 512; idx += 256) {
        int lbb = idx >> 7, rr = idx & 127;
        int ii = rr >> 6;
        float v = g_g1[(size_t)(blockIdx.x * 4 + lbb) * 128 + rr];
        a_s[lbb][rr] = fmaxf(v * g_bn1p[ii] + g_bn1p[2 + ii], 0.f);
    }
    __syncthreads();
    int lb = t >> 6, r = t & 63;
    int b = blockIdx.x * 4 + lb;
    int ii = r >> 5, m = r & 31;
    float acc = 0.f;
    const float* arow = &a_s[lb][ii * 64];
#pragma unroll 8
    for (int o = 0; o < 64; o++) acc += arow[o] * fc2[o * 32 + m];
    g_g2[(size_t)b * 64 + ii * 32 + m] = acc;
    double s = acc, q = (double)acc * acc;
    for (int off = 16; off; off >>= 1) {
        s += __shfl_xor_sync(0xffffffffu, s, off);
        q += __shfl_xor_sync(0xffffffffu, q, off);
    }
    if ((t & 31) == 0) {
        atomicAdd(&g_bn2acc[ii], s);
        atomicAdd(&g_bn2acc[2 + ii], q);
    }
}

__global__ void bn2_fin(const float* __restrict__ g, const float* __restrict__ bb) {
    int i = threadIdx.x;
    double inv = 1.0 / ((double)BATCH * 32.0);
    double mu = g_bn2acc[i] * inv;
    double var = g_bn2acc[2 + i] * inv - mu * mu;
    float sc = g[i] * rsqrtf((float)var + 1e-5f);
    g_bn2p[i] = sc;
    g_bn2p[2 + i] = bb[i] - (float)mu * sc;
}

// ---------------------------------------------------------------------------
// 13. head2
// ---------------------------------------------------------------------------
__global__ void head2_kernel(const float* __restrict__ fc3, float* __restrict__ out) {
    int b = blockIdx.x * 256 + threadIdx.x;
    if (b >= BATCH) return;
    float best = -1e30f;
#pragma unroll
    for (int i = 0; i < 2; i++) {
        float sc = g_bn2p[i], sh = g_bn2p[2 + i];
        float s = 0.f;
#pragma unroll
        for (int m = 0; m < 32; m++) {
            float v = fmaxf(g_g2[(size_t)b * 64 + i * 32 + m] * sc + sh, 0.f);
            s += v * fc3[m];
        }
        float sig = 1.f / (1.f + expf(-s));
        best = fmaxf(best, sig);
    }
    out[b] = best;
}

// ---------------------------------------------------------------------------
// launch
// ---------------------------------------------------------------------------
extern "C" void kernel_launch(void* const* d_in, const int* in_sizes, int n_in,
                              void* d_out, int out_size)
{
    const int*   x      = (const int*)d_in[0];
    const float* emb    = (const float*)d_in[1];
    const float* W3     = (const float*)d_in[2];
    const float* b3     = (const float*)d_in[3];
    const float* W5     = (const float*)d_in[4];
    const float* b5     = (const float*)d_in[5];
    const float* W7     = (const float*)d_in[6];
    const float* b7     = (const float*)d_in[7];
    const float* conv1w = (const float*)d_in[8];
    const float* conv1b = (const float*)d_in[9];
    const float* bng    = (const float*)d_in[10];
    const float* bnb    = (const float*)d_in[11];
    const float* capsw  = (const float*)d_in[12];
    const float* capsb  = (const float*)d_in[13];
    const float* routeW = (const float*)d_in[14];
    const float* routeb = (const float*)d_in[15];
    const float* fc1    = (const float*)d_in[16];
    const float* bn1g   = (const float*)d_in[17];
    const float* bn1b   = (const float*)d_in[18];
    const float* fc2    = (const float*)d_in[19];
    const float* bn2g   = (const float*)d_in[20];
    const float* bn2b   = (const float*)d_in[21];
    const float* fc3    = (const float*)d_in[22];
    float* out = (float*)d_out;

    cudaFuncSetAttribute(conv1_kernel,     cudaFuncAttributeMaxDynamicSharedMemorySize, CONV1_SMEM);
    cudaFuncSetAttribute(capsroute_kernel, cudaFuncAttributeMaxDynamicSharedMemorySize, CR_SMEM);
    cudaFuncSetAttribute(pl_kernel<3>, cudaFuncAttributeMaxDynamicSharedMemorySize, PL_SMEM);
    cudaFuncSetAttribute(pl_kernel<5>, cudaFuncAttributeMaxDynamicSharedMemorySize, PL_SMEM);
    cudaFuncSetAttribute(pl_kernel<7>, cudaFuncAttributeMaxDynamicSharedMemorySize, PL_SMEM);

    __half *h0, *h1, *w16;
    cudaGetSymbolAddress((void**)&h0,  g_h0);
    cudaGetSymbolAddress((void**)&h1,  g_h1);
    cudaGetSymbolAddress((void**)&w16, g_w16);

    wprep_conv<<<42, 256>>>(conv1w, capsw);
    embed_kernel<<<(BATCH * SEQ * 16 + 255) / 256, 256>>>(x, emb);
    wprep_all<<<dim3(60, 41), 256>>>(W3, W5, W7);

    pl_kernel<3><<<dim3(32, 41), 256, PL_SMEM>>>(h0, w16 + WOFF3, b3, h1);
    pl_kernel<5><<<dim3(32, 41), 256, PL_SMEM>>>(h1, w16 + WOFF5, b5, h0);
    pl_kernel<7><<<dim3(32, 41), 256, PL_SMEM>>>(h0, w16 + WOFF7, b7, h1);

    conv1_kernel<<<BATCH, 256, CONV1_SMEM>>>(conv1b);
    bn_fin_conv<<<1, 64>>>(bng, bnb);
    capsroute_kernel<<<BATCH, 256, CR_SMEM>>>(capsb, routeW, routeb, fc1);
    bn1_fin<<<1, 2>>>(bn1g, bn1b);
    head1_kernel<<<BATCH / 4, 256>>>(fc2);
    bn2_fin<<<1, 2>>>(bn2g, bn2b);
    head2_kernel<<<(BATCH + 255) / 256, 256>>>(fc3, out);
}

// round 11
// speedup vs baseline: 4.9788x; 1.0148x over previous
#include <cuda_runtime.h>
#include <cuda_fp16.h>
#include <math.h>
#include <stdint.h>

// ---------------------------------------------------------------------------
// Problem constants
// ---------------------------------------------------------------------------
#define BATCH 4096
#define SEQ   41
#define FDIM  128
#define SF    (SEQ*FDIM)        // 5248
#define C64L  (64*128)          // 8192

// ---------------------------------------------------------------------------
// Scratch (device globals; allocation-free contract)
// ---------------------------------------------------------------------------
__device__ __align__(256) __half g_h0[(size_t)BATCH * SF];   // activation ping
__device__ __align__(256) __half g_h1[(size_t)BATCH * SF];   // activation pong
__device__ __align__(256) __half g_c[(size_t)BATCH * C64L];  // conv1 out [b][l=128][o=64]
__device__ __align__(256) float  g_g1[(size_t)BATCH * 128];  // [B,2,64]
__device__ __align__(256) float  g_g2[(size_t)BATCH * 64];   // [B,2,32]
__device__ double g_bnsum[64], g_bnsq[64];
__device__ float  g_bnscale[64], g_bnshift[64];
__device__ double g_bn1acc[4];
__device__ double g_bn2acc[4];
__device__ float  g_bn1p[4];
__device__ float  g_bn2p[4];

// transposed fp16 PL weights: layout [s][n=128][K], layers packed
#define WOFF3 ((size_t)0)
#define WOFF5 ((size_t)41*384*128)
#define WOFF7 ((size_t)(41*384*128) + (size_t)41*640*128)
#define WTOT  ((size_t)41*1920*128)
__device__ __align__(256) __half g_w16[WTOT];

// conv weights fp16, pitched: wc1 [3][64][56], wc2 [3][64][40]
__device__ __align__(256) __half g_wc1[3*64*56];
__device__ __align__(256) __half g_wc2[3*64*40];

// single shared extern symbol for all dynamic-smem kernels
extern __shared__ __align__(1024) char sm_raw[];

__device__ __forceinline__ float squash_factor(float ssq) {
    float n = sqrtf(ssq);
    return (1.f - 1.f / (expf(n) + 1e-21f)) / (n + 1e-21f);
}

// ---------------------------------------------------------------------------
// PTX helpers (compute_100-safe: mma.sync + cp.async + ldmatrix)
// ---------------------------------------------------------------------------
__device__ __forceinline__ uint32_t smem_u32(const void* p) {
    uint32_t a;
    asm("{ .reg .u64 t; cvta.to.shared.u64 t, %1; cvt.u32.u64 %0, t; }" : "=r"(a) : "l"(p));
    return a;
}
__device__ __forceinline__ uint32_t lds32(uint32_t a) {
    uint32_t v;
    asm volatile("ld.shared.b32 %0, [%1];" : "=r"(v) : "r"(a));
    return v;
}
__device__ __forceinline__ void sts32(uint32_t a, uint32_t v) {
    asm volatile("st.shared.b32 [%0], %1;" :: "r"(a), "r"(v));
}
__device__ __forceinline__ void sts16(uint32_t a, uint16_t v) {
    asm volatile("st.shared.u16 [%0], %1;" :: "r"(a), "h"(v));
}
__device__ __forceinline__ void ldsm_x4(uint32_t* r, uint32_t addr) {
    asm volatile("ldmatrix.sync.aligned.m8n8.x4.shared.b16 {%0,%1,%2,%3}, [%4];"
        : "=r"(r[0]), "=r"(r[1]), "=r"(r[2]), "=r"(r[3]) : "r"(addr));
}
__device__ __forceinline__ void mma_f16(float* c, const uint32_t* a, const uint32_t* b) {
    asm volatile(
        "mma.sync.aligned.m16n8k16.row.col.f32.f16.f16.f32 "
        "{%0,%1,%2,%3}, {%4,%5,%6,%7}, {%8,%9}, {%0,%1,%2,%3};"
        : "+f"(c[0]), "+f"(c[1]), "+f"(c[2]), "+f"(c[3])
        : "r"(a[0]), "r"(a[1]), "r"(a[2]), "r"(a[3]), "r"(b[0]), "r"(b[1]));
}
#define CP16(dst, src)    asm volatile("cp.async.cg.shared.global [%0], [%1], 16;" :: "r"(dst), "l"(src))
#define CP_COMMIT()       asm volatile("cp.async.commit_group;" ::: "memory")
#define CP_WAIT0()        asm volatile("cp.async.wait_group 0;" ::: "memory")

__device__ __forceinline__ uint32_t hpack(float a, float b) {
    __half2 t = __floats2half2_rn(a, b);
    return *reinterpret_cast<uint32_t*>(&t);
}

// ---------------------------------------------------------------------------
// 0. conv weight prep + accumulator zero (single launch)
// ---------------------------------------------------------------------------
__global__ void wprep_conv(const float* __restrict__ c1w, const float* __restrict__ c2w) {
    int t = blockIdx.x * 256 + threadIdx.x;
    if (blockIdx.x == 0) {
        int tt = threadIdx.x;
        if (tt < 64) { g_bnsum[tt] = 0.0; g_bnsq[tt] = 0.0; }
        if (tt < 4)  { g_bn1acc[tt] = 0.0; g_bn2acc[tt] = 0.0; }
    }
    if (t < 3 * 64 * 56) {
        int c = t % 56, o = (t / 56) % 64, k = t / (56 * 64);
        g_wc1[t] = (c < 41) ? __float2half(c1w[(o * 41 + c) * 3 + k]) : __float2half(0.f);
    }
    if (t < 3 * 64 * 40) {
        int c = t % 40, o = (t / 40) % 64, k = t / (40 * 64);
        g_wc2[t] = (c < 32) ? __float2half(c2w[(o * 32 + c) * 3 + k]) : __float2half(0.f);
    }
}

// ---------------------------------------------------------------------------
// 1. embedding gather -> g_h0 fp16
// ---------------------------------------------------------------------------
__global__ void embed_kernel(const int* __restrict__ x, const float* __restrict__ emb) {
    int gid = blockIdx.x * 256 + threadIdx.x;
    int pos = gid >> 4;
    int f0  = (gid & 15) * 8;
    if (pos >= BATCH * SEQ) return;
    int e = x[pos];
    const float4* sp = reinterpret_cast<const float4*>(emb + e * FDIM + f0);
    float4 v0 = sp[0], v1 = sp[1];
    uint4 o;
    o.x = hpack(v0.x, v0.y); o.y = hpack(v0.z, v0.w);
    o.z = hpack(v1.x, v1.y); o.w = hpack(v1.z, v1.w);
    *reinterpret_cast<uint4*>(g_h0 + (size_t)pos * FDIM + f0) = o;
}

// ---------------------------------------------------------------------------
// 1b. PL weight prep, all 3 layers in one launch.
// ---------------------------------------------------------------------------
__global__ void wprep_all(const float* __restrict__ W3, const float* __restrict__ W5,
                          const float* __restrict__ W7) {
    __shared__ float tile[32][129];
    int bx = blockIdx.x, s = blockIdx.y, t = threadIdx.x;
    const float* W; __half* o; int K, kb;
    if (bx < 12)      { W = W3; o = g_w16 + WOFF3; K = 384; kb = bx * 32; }
    else if (bx < 32) { W = W5; o = g_w16 + WOFF5; K = 640; kb = (bx - 12) * 32; }
    else              { W = W7; o = g_w16 + WOFF7; K = 896; kb = (bx - 32) * 32; }
#pragma unroll
    for (int i = 0; i < 16; i++) {
        int e = t + i * 256;
        int kk = e >> 7, n = e & 127;
        tile[kk][n] = W[((size_t)s * K + kb + kk) * 128 + n];
    }
    __syncthreads();
    int n = t >> 1, h = (t & 1) * 16;
    size_t ob = ((size_t)(s * 128 + n)) * K + kb + h;
#pragma unroll
    for (int kk = 0; kk < 16; kk += 2) {
        *reinterpret_cast<uint32_t*>(&o[ob + kk]) = hpack(tile[h + kk][n], tile[h + kk + 1][n]);
    }
}

// ---------------------------------------------------------------------------
// 2-4. position_linear: fp16 MMA, K-chunk 64, ldmatrix, 3-stage pipeline
//      (one __syncthreads per stage).
// ---------------------------------------------------------------------------
#define PL_SMEM (3 * 32768)   // 98304

template<int WIN>
__global__ void __launch_bounds__(256, 2)
pl_kernel(const __half* __restrict__ aIn, const __half* __restrict__ wIn,
          const float* __restrict__ bst, __half* __restrict__ aOut)
{
    constexpr int P = WIN / 2;
    constexpr int K = WIN * 128;
    const uint32_t smb = smem_u32(sm_raw);
    const int s   = blockIdx.y;
    const int bm  = blockIdx.x * 128;
    const int tid = threadIdx.x;
    const int warp = tid >> 5, lane = tid & 31;
    const int warp_m = warp >> 2, warp_n = warp & 3;
    const int gid = lane >> 2, tg = lane & 3;

    const int j0 = (P - s) > 0 ? (P - s) : 0;
    const int j1 = (WIN - 1) < (P + SEQ - 1 - s) ? (WIN - 1) : (P + SEQ - 1 - s);
    const int nst = (j1 - j0 + 1) * 2;     // k64 stages (>= 4 always)

    // ldmatrix lane-invariant address components
    const int a_moff = (lane & 7) + ((lane >> 3) & 1) * 8;
    const int a_cbit = lane >> 4;
    const int b_roff = ((lane >> 4) & 1) * 8 + (lane & 7);
    const int b_cbit = (lane >> 3) & 1;

    float acc[4][4][4];
#pragma unroll
    for (int a = 0; a < 4; a++)
#pragma unroll
        for (int b = 0; b < 4; b++)
#pragma unroll
            for (int c = 0; c < 4; c++) acc[a][b][c] = 0.f;

    auto load_stage = [&](int st) {
        const int jj = j0 + (st >> 1);
        const int f0 = (st & 1) * 64;
        const int tsrc = s + jj - P;
        const int k0 = jj * 128 + f0;
        const uint32_t sb = smb + (uint32_t)(st % 3) * 32768;
#pragma unroll
        for (int i = 0; i < 4; i++) {
            int idx = tid + i * 256;           // 0..1023
            int row = idx >> 3, ch = idx & 7;
            uint32_t d = sb + row * 128 + (((ch ^ (row & 7)) << 4));
            size_t aoff = ((size_t)(bm + row) * SEQ + tsrc) * 128 + f0 + ch * 8;
            size_t boff = ((size_t)(s * 128 + row)) * K + k0 + ch * 8;
            CP16(d,         (const char*)(aIn + aoff));
            CP16(d + 16384, (const char*)(wIn + boff));
        }
        CP_COMMIT();
    };

    load_stage(0);
    load_stage(1);

    for (int st = 0; st < nst; st++) {
        // ensure stage st's group is complete
        if (st + 1 < nst) {
            asm volatile("cp.async.wait_group 1;" ::: "memory");
        } else {
            asm volatile("cp.async.wait_group 0;" ::: "memory");
        }
        __syncthreads();   // data visible to all; all warps done reading buf (st+2)%3

        if (st + 2 < nst) load_stage(st + 2);

        const uint32_t ab = smb + (uint32_t)(st % 3) * 32768;
#pragma unroll
        for (int kt = 0; kt < 4; kt++) {
            uint32_t bf[4][2];
#pragma unroll
            for (int p = 0; p < 2; p++) {
                int row = warp_n * 32 + p * 16 + b_roff;
                int sw = row & 7;
                uint32_t addr = ab + 16384 + row * 128 + (((kt * 2 + b_cbit) ^ sw) << 4);
                uint32_t r[4];
                ldsm_x4(r, addr);
                bf[2 * p][0] = r[0]; bf[2 * p][1] = r[1];
                bf[2 * p + 1][0] = r[2]; bf[2 * p + 1][1] = r[3];
            }
#pragma unroll
            for (int mt = 0; mt < 4; mt++) {
                int row = warp_m * 64 + mt * 16 + a_moff;
                int sw = row & 7;
                uint32_t addr = ab + row * 128 + (((kt * 2 + a_cbit) ^ sw) << 4);
                uint32_t af[4];
                ldsm_x4(af, addr);
#pragma unroll
                for (int nt = 0; nt < 4; nt++)
                    mma_f16(acc[mt][nt], af, bf[nt]);
            }
        }
    }

    const float* bias = bst + s * 128;
#pragma unroll
    for (int mt = 0; mt < 4; mt++) {
        int rbase = warp_m * 64 + mt * 16 + gid;
#pragma unroll
        for (int half = 0; half < 2; half++) {
            int r = rbase + half * 8;
            size_t ob = ((size_t)(bm + r) * SEQ + s) * 128;
#pragma unroll
            for (int nt = 0; nt < 4; nt++) {
                int col = warp_n * 32 + nt * 8 + tg * 2;
                float v0 = fmaxf(acc[mt][nt][half * 2 + 0] + bias[col],     0.f);
                float v1 = fmaxf(acc[mt][nt][half * 2 + 1] + bias[col + 1], 0.f);
                *reinterpret_cast<uint32_t*>(aOut + ob + col) = hpack(v0, v1);
            }
        }
    }
}

// ---------------------------------------------------------------------------
// 5. conv1 via tensor cores. Per-batch CTA.
// ---------------------------------------------------------------------------
#define C1_STG   0
#define C1_A     10496
#define C1_W     (C1_A + 130*112)        // 25056
#define C1_STATS (C1_W + 3*64*112)       // 46560
#define CONV1_SMEM (C1_STATS + 2*64*4)   // 47072

__global__ void __launch_bounds__(256, 2)
conv1_kernel(const float* __restrict__ bias) {
    const uint32_t smb = smem_u32(sm_raw);
    const int b = blockIdx.x, t = threadIdx.x;
    const int warp = t >> 5, lane = t & 31;
    const int warp_m = warp >> 1, warp_n = warp & 1;
    const int gid = lane >> 2, tg = lane & 3;

    for (int i = t; i < 130 * 112 / 4; i += 256) sts32(smb + C1_A + i * 4, 0u);
    for (int i = t; i < 128; i += 256) sts32(smb + C1_STATS + i * 4, 0u);

    {
        const char* src = (const char*)(g_h1 + (size_t)b * SF);
        for (int i = t; i < 41 * 16; i += 256)
            CP16(smb + C1_STG + i * 16, src + i * 16);
        const char* wsrc = (const char*)g_wc1;
        for (int i = t; i < 3 * 64 * 56 * 2 / 16; i += 256)
            CP16(smb + C1_W + i * 16, wsrc + i * 16);
        CP_COMMIT(); CP_WAIT0();
    }
    __syncthreads();

    for (int idx = t; idx < 41 * 64; idx += 256) {
        int c = idx >> 6, f2 = idx & 63;
        uint32_t v = lds32(smb + C1_STG + c * 256 + f2 * 4);
        sts16(smb + C1_A + (2 * f2 + 1) * 112 + c * 2, (uint16_t)(v & 0xFFFF));
        sts16(smb + C1_A + (2 * f2 + 2) * 112 + c * 2, (uint16_t)(v >> 16));
    }
    __syncthreads();

    float acc[2][4][4];
#pragma unroll
    for (int a = 0; a < 2; a++)
#pragma unroll
        for (int bb = 0; bb < 4; bb++)
#pragma unroll
            for (int c = 0; c < 4; c++) acc[a][bb][c] = 0.f;

#pragma unroll
    for (int k = 0; k < 3; k++) {
#pragma unroll
        for (int ks = 0; ks < 3; ks++) {
            uint32_t bf[4][2];
#pragma unroll
            for (int nt = 0; nt < 4; nt++) {
                uint32_t ba = smb + C1_W + k * (64 * 112) + (warp_n * 32 + nt * 8 + gid) * 112 + ks * 32 + tg * 4;
                bf[nt][0] = lds32(ba);
                bf[nt][1] = lds32(ba + 16);
            }
#pragma unroll
            for (int mt = 0; mt < 2; mt++) {
                int r0 = warp_m * 32 + mt * 16 + gid + k;
                uint32_t a0a = smb + C1_A + r0 * 112 + ks * 32 + tg * 4;
                uint32_t a1a = a0a + 8 * 112;
                uint32_t af[4];
                af[0] = lds32(a0a);
                af[1] = lds32(a1a);
                af[2] = lds32(a0a + 16);
                af[3] = lds32(a1a + 16);
#pragma unroll
                for (int nt = 0; nt < 4; nt++)
                    mma_f16(acc[mt][nt], af, bf[nt]);
            }
        }
    }

    float s0[4], s1[4], q0[4], q1[4];
#pragma unroll
    for (int nt = 0; nt < 4; nt++) { s0[nt] = s1[nt] = q0[nt] = q1[nt] = 0.f; }
    __half* dst = g_c + (size_t)b * C64L;
#pragma unroll
    for (int mt = 0; mt < 2; mt++) {
        int l0 = warp_m * 32 + mt * 16 + gid;
#pragma unroll
        for (int nt = 0; nt < 4; nt++) {
            int o = warp_n * 32 + nt * 8 + tg * 2;
            float bb0 = bias[o], bb1 = bias[o + 1];
            float v0 = acc[mt][nt][0] + bb0, v1 = acc[mt][nt][1] + bb1;
            float v2 = acc[mt][nt][2] + bb0, v3 = acc[mt][nt][3] + bb1;
            *reinterpret_cast<uint32_t*>(dst + l0 * 64 + o)       = hpack(v0, v1);
            *reinterpret_cast<uint32_t*>(dst + (l0 + 8) * 64 + o) = hpack(v2, v3);
            s0[nt] += v0 + v2; s1[nt] += v1 + v3;
            q0[nt] += v0 * v0 + v2 * v2; q1[nt] += v1 * v1 + v3 * v3;
        }
    }
#pragma unroll
    for (int nt = 0; nt < 4; nt++) {
#pragma unroll
        for (int off = 4; off < 32; off <<= 1) {
            s0[nt] += __shfl_xor_sync(0xffffffffu, s0[nt], off);
            s1[nt] += __shfl_xor_sync(0xffffffffu, s1[nt], off);
            q0[nt] += __shfl_xor_sync(0xffffffffu, q0[nt], off);
            q1[nt] += __shfl_xor_sync(0xffffffffu, q1[nt], off);
        }
    }
    if (gid == 0) {
        float* sums = reinterpret_cast<float*>(sm_raw + C1_STATS);
        float* sqs  = sums + 64;
#pragma unroll
        for (int nt = 0; nt < 4; nt++) {
            int o = warp_n * 32 + nt * 8 + tg * 2;
            atomicAdd(&sums[o],     s0[nt]);
            atomicAdd(&sums[o + 1], s1[nt]);
            atomicAdd(&sqs[o],      q0[nt]);
            atomicAdd(&sqs[o + 1],  q1[nt]);
        }
    }
    __syncthreads();
    if (t < 64) {
        float* sums = reinterpret_cast<float*>(sm_raw + C1_STATS);
        atomicAdd(&g_bnsum[t], (double)sums[t]);
        atomicAdd(&g_bnsq[t],  (double)sums[64 + t]);
    }
}

__global__ void bn_fin_conv(const float* __restrict__ g, const float* __restrict__ bb) {
    int c = threadIdx.x;
    double inv = 1.0 / ((double)BATCH * 128.0);
    double mu = g_bnsum[c] * inv;
    double var = g_bnsq[c] * inv - mu * mu;
    float sc = g[c] * rsqrtf((float)var + 1e-5f);
    g_bnscale[c] = sc;
    g_bnshift[c] = bb[c] - (float)mu * sc;
}

// ---------------------------------------------------------------------------
// 8-9. FUSED capsroute (3 CTAs/SM)
// ---------------------------------------------------------------------------
#define CR_A    0
#define CR_W    16640
#define CR_SOUT 32000
#define CR_SMEM (CR_SOUT + 128*73*4)   // 69376

__global__ void __launch_bounds__(256, 3)
capsroute_kernel(const float* __restrict__ cb,
                 const float* __restrict__ rW, const float* __restrict__ rb,
                 const float* __restrict__ fc1)
{
    const uint32_t smb = smem_u32(sm_raw);
    float* sout = reinterpret_cast<float*>(sm_raw + CR_SOUT);  // [128 l][73]
    __shared__ float red4[4][64];
    __shared__ float sfac[64];
    __shared__ float coef[2][64];
    __shared__ float warp_sq[8];
    __shared__ float factor_s[2];
    __shared__ float sv_s[2][128];
    __shared__ float yv_s[2][128];

    const int b = blockIdx.x, t = threadIdx.x;
    const int warp = t >> 5, lane = t & 31;
    const int warp_m = warp >> 1, g = warp & 1;
    const int gid = lane >> 2, tg = lane & 3;

    // zero halo rows 0 and 129
    if (t < 64) sts32(smb + CR_A + ((t < 32) ? 0 : (129 * 128)) + (t & 31) * 4, 0u);

    {
        const char* src = (const char*)(g_c + (size_t)b * C64L);
        for (int i = t; i < 128 * 8; i += 256) {
            int row = (i >> 3) + 1, ch = i & 7;
            CP16(smb + CR_A + row * 128 + ((ch ^ (row & 7)) << 4), src + (row - 1) * 128 + ch * 16);
        }
        const char* wsrc = (const char*)g_wc2;
        for (int i = t; i < 3 * 64 * 40 * 2 / 16; i += 256)
            CP16(smb + CR_W + i * 16, wsrc + i * 16);
        CP_COMMIT(); CP_WAIT0();
    }
    __syncthreads();

    // BN + ReLU in place on A rows 1..128
    for (int idx = t; idx < 128 * 32; idx += 256) {
        int r = (idx >> 5) + 1, wd = idx & 31;
        int o = wd * 2;
        uint32_t addr = smb + CR_A + r * 128 + (((wd >> 2) ^ (r & 7)) << 4) + ((wd * 4) & 15);
        uint32_t v = lds32(addr);
        __half2 h = *reinterpret_cast<__half2*>(&v);
        float f0 = fmaxf(__low2float(h)  * g_bnscale[o]     + g_bnshift[o],     0.f);
        float f1 = fmaxf(__high2float(h) * g_bnscale[o + 1] + g_bnshift[o + 1], 0.f);
        sts32(addr, hpack(f0, f1));
    }
    __syncthreads();

    float acc[2][4][4];
#pragma unroll
    for (int a = 0; a < 2; a++)
#pragma unroll
        for (int bb = 0; bb < 4; bb++)
#pragma unroll
            for (int c = 0; c < 4; c++) acc[a][bb][c] = 0.f;

#pragma unroll
    for (int k = 0; k < 3; k++) {
#pragma unroll
        for (int ks = 0; ks < 2; ks++) {
            uint32_t bf[4][2];
#pragma unroll
            for (int nt = 0; nt < 4; nt++) {
                uint32_t ba = smb + CR_W + k * (64 * 80) + (g * 32 + nt * 8 + gid) * 80 + ks * 32 + tg * 4;
                bf[nt][0] = lds32(ba);
                bf[nt][1] = lds32(ba + 16);
            }
            int cbase = g * 4 + ks * 2;
#pragma unroll
            for (int mt = 0; mt < 2; mt++) {
                int r0 = warp_m * 32 + mt * 16 + gid + k;
                int r1 = r0 + 8;
                uint32_t af[4];
                af[0] = lds32(smb + CR_A + r0 * 128 + (((cbase)     ^ (r0 & 7)) << 4) + tg * 4);
                af[1] = lds32(smb + CR_A + r1 * 128 + (((cbase)     ^ (r1 & 7)) << 4) + tg * 4);
                af[2] = lds32(smb + CR_A + r0 * 128 + (((cbase + 1) ^ (r0 & 7)) << 4) + tg * 4);
                af[3] = lds32(smb + CR_A + r1 * 128 + (((cbase + 1) ^ (r1 & 7)) << 4) + tg * 4);
#pragma unroll
                for (int nt = 0; nt < 4; nt++)
                    mma_f16(acc[mt][nt], af, bf[nt]);
            }
        }
    }

#pragma unroll
    for (int mt = 0; mt < 2; mt++) {
        int l0 = warp_m * 32 + mt * 16 + gid;
#pragma unroll
        for (int nt = 0; nt < 4; nt++) {
            int o = g * 32 + nt * 8 + tg * 2;
            float bb0 = cb[o], bb1 = cb[o + 1];
            sout[l0 * 73 + o]           = acc[mt][nt][0] + bb0;
            sout[l0 * 73 + o + 1]       = acc[mt][nt][1] + bb1;
            sout[(l0 + 8) * 73 + o]     = acc[mt][nt][2] + bb0;
            sout[(l0 + 8) * 73 + o + 1] = acc[mt][nt][3] + bb1;
        }
    }
    __syncthreads();

    {
        int o = t & 63, seg = t >> 6;
        float p = 0.f;
        for (int l = seg * 32; l < seg * 32 + 32; l++) {
            float v = sout[l * 73 + o];
            p += v * v;
        }
        red4[seg][o] = p;
    }
    __syncthreads();
    if (t < 64) {
        float tot = red4[0][t] + red4[1][t] + red4[2][t] + red4[3][t];
        sfac[t] = squash_factor(tot);
    }
    __syncthreads();
    if (t < 128) {
        int i = t >> 6, j = t & 63;
        coef[i][j] = sfac[j] * (1.0f + rb[i * 64 + j]);
    }
    __syncthreads();

    int i = t >> 7;
    int f = t & 127;
    float acc2 = 0.f;
    const float* rwi = rW + i * 8192 + f;
    const float* srow = sout + f * 73;
#pragma unroll 8
    for (int j = 0; j < 64; j++)
        acc2 += srow[j] * rwi[j * 128] * coef[i][j];

    float sq = acc2 * acc2;
    for (int off = 16; off; off >>= 1) sq += __shfl_xor_sync(0xffffffffu, sq, off);
    if ((t & 31) == 0) warp_sq[t >> 5] = sq;
    __syncthreads();
    if (t < 2) {
        float tot = warp_sq[t * 4 + 0] + warp_sq[t * 4 + 1] + warp_sq[t * 4 + 2] + warp_sq[t * 4 + 3];
        factor_s[t] = squash_factor(tot);
    }
    __syncthreads();
    sv_s[i][f] = acc2 * factor_s[i];
    __syncthreads();
    yv_s[i][f] = sv_s[i][f] + fmaxf(sv_s[0][f], sv_s[1][f]);
    __syncthreads();

    {
        int ii = t >> 7;
        int o  = (t >> 1) & 63;
        int p  = t & 1;
        float a = 0.f;
        const float* yb = yv_s[ii];
        const float* fb = fc1 + p * 64 * 64 + o;
#pragma unroll 8
        for (int ff = 0; ff < 64; ff++) a += yb[p * 64 + ff] * fb[ff * 64];
        a += __shfl_xor_sync(0xffffffffu, a, 1);
        double s = 0.0, q = 0.0;
        if (p == 0) {
            g_g1[(size_t)b * 128 + ii * 64 + o] = a;
            s = a; q = (double)a * a;
        }
        for (int off = 16; off; off >>= 1) {
            s += __shfl_xor_sync(0xffffffffu, s, off);
            q += __shfl_xor_sync(0xffffffffu, q, off);
        }
        if ((t & 31) == 0) {
            atomicAdd(&g_bn1acc[ii], s);
            atomicAdd(&g_bn1acc[2 + ii], q);
        }
    }
}

__global__ void bn1_fin(const float* __restrict__ g, const float* __restrict__ bb) {
    int i = threadIdx.x;
    double inv = 1.0 / ((double)BATCH * 64.0);
    double mu = g_bn1acc[i] * inv;
    double var = g_bn1acc[2 + i] * inv - mu * mu;
    float sc = g[i] * rsqrtf((float)var + 1e-5f);
    g_bn1p[i] = sc;
    g_bn1p[2 + i] = bb[i] - (float)mu * sc;
}

// ---------------------------------------------------------------------------
// 11. head1
// ---------------------------------------------------------------------------
__global__ void head1_kernel(const float* __restrict__ fc2) {
    __shared__ float a_s[4][128];
    int t = threadIdx.x;
    for (int idx = t; idx < 512; idx += 256) {
        int lbb = idx >> 7, rr = idx & 127;
        int ii = rr >> 6;
        float v = g_g1[(size_t)(blockIdx.x * 4 + lbb) * 128 + rr];
        a_s[lbb][rr] = fmaxf(v * g_bn1p[ii] + g_bn1p[2 + ii], 0.f);
    }
    __syncthreads();
    int lb = t >> 6, r = t & 63;
    int b = blockIdx.x * 4 + lb;
    int ii = r >> 5, m = r & 31;
    float acc = 0.f;
    const float* arow = &a_s[lb][ii * 64];
#pragma unroll 8
    for (int o = 0; o < 64; o++) acc += arow[o] * fc2[o * 32 + m];
    g_g2[(size_t)b * 64 + ii * 32 + m] = acc;
    double s = acc, q = (double)acc * acc;
    for (int off = 16; off; off >>= 1) {
        s += __shfl_xor_sync(0xffffffffu, s, off);
        q += __shfl_xor_sync(0xffffffffu, q, off);
    }
    if ((t & 31) == 0) {
        atomicAdd(&g_bn2acc[ii], s);
        atomicAdd(&g_bn2acc[2 + ii], q);
    }
}

__global__ void bn2_fin(const float* __restrict__ g, const float* __restrict__ bb) {
    int i = threadIdx.x;
    double inv = 1.0 / ((double)BATCH * 32.0);
    double mu = g_bn2acc[i] * inv;
    double var = g_bn2acc[2 + i] * inv - mu * mu;
    float sc = g[i] * rsqrtf((float)var + 1e-5f);
    g_bn2p[i] = sc;
    g_bn2p[2 + i] = bb[i] - (float)mu * sc;
}

// ---------------------------------------------------------------------------
// 13. head2
// ---------------------------------------------------------------------------
__global__ void head2_kernel(const float* __restrict__ fc3, float* __restrict__ out) {
    int b = blockIdx.x * 256 + threadIdx.x;
    if (b >= BATCH) return;
    float best = -1e30f;
#pragma unroll
    for (int i = 0; i < 2; i++) {
        float sc = g_bn2p[i], sh = g_bn2p[2 + i];
        float s = 0.f;
#pragma unroll
        for (int m = 0; m < 32; m++) {
            float v = fmaxf(g_g2[(size_t)b * 64 + i * 32 + m] * sc + sh, 0.f);
            s += v * fc3[m];
        }
        float sig = 1.f / (1.f + expf(-s));
        best = fmaxf(best, sig);
    }
    out[b] = best;
}

// ---------------------------------------------------------------------------
// launch
// ---------------------------------------------------------------------------
extern "C" void kernel_launch(void* const* d_in, const int* in_sizes, int n_in,
                              void* d_out, int out_size)
{
    const int*   x      = (const int*)d_in[0];
    const float* emb    = (const float*)d_in[1];
    const float* W3     = (const float*)d_in[2];
    const float* b3     = (const float*)d_in[3];
    const float* W5     = (const float*)d_in[4];
    const float* b5     = (const float*)d_in[5];
    const float* W7     = (const float*)d_in[6];
    const float* b7     = (const float*)d_in[7];
    const float* conv1w = (const float*)d_in[8];
    const float* conv1b = (const float*)d_in[9];
    const float* bng    = (const float*)d_in[10];
    const float* bnb    = (const float*)d_in[11];
    const float* capsw  = (const float*)d_in[12];
    const float* capsb  = (const float*)d_in[13];
    const float* routeW = (const float*)d_in[14];
    const float* routeb = (const float*)d_in[15];
    const float* fc1    = (const float*)d_in[16];
    const float* bn1g   = (const float*)d_in[17];
    const float* bn1b   = (const float*)d_in[18];
    const float* fc2    = (const float*)d_in[19];
    const float* bn2g   = (const float*)d_in[20];
    const float* bn2b   = (const float*)d_in[21];
    const float* fc3    = (const float*)d_in[22];
    float* out = (float*)d_out;

    cudaFuncSetAttribute(conv1_kernel,     cudaFuncAttributeMaxDynamicSharedMemorySize, CONV1_SMEM);
    cudaFuncSetAttribute(capsroute_kernel, cudaFuncAttributeMaxDynamicSharedMemorySize, CR_SMEM);
    cudaFuncSetAttribute(pl_kernel<3>, cudaFuncAttributeMaxDynamicSharedMemorySize, PL_SMEM);
    cudaFuncSetAttribute(pl_kernel<5>, cudaFuncAttributeMaxDynamicSharedMemorySize, PL_SMEM);
    cudaFuncSetAttribute(pl_kernel<7>, cudaFuncAttributeMaxDynamicSharedMemorySize, PL_SMEM);

    __half *h0, *h1, *w16;
    cudaGetSymbolAddress((void**)&h0,  g_h0);
    cudaGetSymbolAddress((void**)&h1,  g_h1);
    cudaGetSymbolAddress((void**)&w16, g_w16);

    wprep_conv<<<42, 256>>>(conv1w, capsw);
    embed_kernel<<<(BATCH * SEQ * 16 + 255) / 256, 256>>>(x, emb);
    wprep_all<<<dim3(60, 41), 256>>>(W3, W5, W7);

    pl_kernel<3><<<dim3(32, 41), 256, PL_SMEM>>>(h0, w16 + WOFF3, b3, h1);
    pl_kernel<5><<<dim3(32, 41), 256, PL_SMEM>>>(h1, w16 + WOFF5, b5, h0);
    pl_kernel<7><<<dim3(32, 41), 256, PL_SMEM>>>(h0, w16 + WOFF7, b7, h1);

    conv1_kernel<<<BATCH, 256, CONV1_SMEM>>>(conv1b);
    bn_fin_conv<<<1, 64>>>(bng, bnb);
    capsroute_kernel<<<BATCH, 256, CR_SMEM>>>(capsb, routeW, routeb, fc1);
    bn1_fin<<<1, 2>>>(bn1g, bn1b);
    head1_kernel<<<BATCH / 4, 256>>>(fc2);
    bn2_fin<<<1, 2>>>(bn2g, bn2b);
    head2_kernel<<<(BATCH + 255) / 256, 256>>>(fc3, out);
}

// round 12
// speedup vs baseline: 5.2500x; 1.0545x over previous
#include <cuda_runtime.h>
#include <cuda_fp16.h>
#include <math.h>
#include <stdint.h>

// ---------------------------------------------------------------------------
// Problem constants
// ---------------------------------------------------------------------------
#define BATCH 4096
#define SEQ   41
#define FDIM  128
#define SF    (SEQ*FDIM)        // 5248
#define C64L  (64*128)          // 8192

// ---------------------------------------------------------------------------
// Scratch (device globals; allocation-free contract)
// ---------------------------------------------------------------------------
__device__ __align__(256) __half g_h0[(size_t)BATCH * SF];   // activation ping
__device__ __align__(256) __half g_h1[(size_t)BATCH * SF];   // activation pong
__device__ __align__(256) __half g_c[(size_t)BATCH * C64L];  // conv1 out [b][l=128][o=64]
__device__ __align__(256) float  g_g1[(size_t)BATCH * 128];  // [B,2,64]
__device__ __align__(256) float  g_g2[(size_t)BATCH * 64];   // [B,2,32]
__device__ double g_bnsum[64], g_bnsq[64];
__device__ double g_bn1acc[4];
__device__ double g_bn2acc[4];

// transposed fp16 PL weights: layout [s][n=128][K], layers packed
#define WOFF3 ((size_t)0)
#define WOFF5 ((size_t)41*384*128)
#define WOFF7 ((size_t)(41*384*128) + (size_t)41*640*128)
#define WTOT  ((size_t)41*1920*128)
__device__ __align__(256) __half g_w16[WTOT];

// conv weights fp16, pitched: wc1 [3][64][56], wc2 [3][64][40]
__device__ __align__(256) __half g_wc1[3*64*56];
__device__ __align__(256) __half g_wc2[3*64*40];

// single shared extern symbol for all dynamic-smem kernels
extern __shared__ __align__(1024) char sm_raw[];

__device__ __forceinline__ float squash_factor(float ssq) {
    float n = sqrtf(ssq);
    return (1.f - 1.f / (expf(n) + 1e-21f)) / (n + 1e-21f);
}

// ---------------------------------------------------------------------------
// PTX helpers (compute_100-safe: mma.sync + cp.async + ldmatrix)
// ---------------------------------------------------------------------------
__device__ __forceinline__ uint32_t smem_u32(const void* p) {
    uint32_t a;
    asm("{ .reg .u64 t; cvta.to.shared.u64 t, %1; cvt.u32.u64 %0, t; }" : "=r"(a) : "l"(p));
    return a;
}
__device__ __forceinline__ uint32_t lds32(uint32_t a) {
    uint32_t v;
    asm volatile("ld.shared.b32 %0, [%1];" : "=r"(v) : "r"(a));
    return v;
}
__device__ __forceinline__ void sts32(uint32_t a, uint32_t v) {
    asm volatile("st.shared.b32 [%0], %1;" :: "r"(a), "r"(v));
}
__device__ __forceinline__ void sts16(uint32_t a, uint16_t v) {
    asm volatile("st.shared.u16 [%0], %1;" :: "r"(a), "h"(v));
}
__device__ __forceinline__ void ldsm_x4(uint32_t* r, uint32_t addr) {
    asm volatile("ldmatrix.sync.aligned.m8n8.x4.shared.b16 {%0,%1,%2,%3}, [%4];"
        : "=r"(r[0]), "=r"(r[1]), "=r"(r[2]), "=r"(r[3]) : "r"(addr));
}
__device__ __forceinline__ void mma_f16(float* c, const uint32_t* a, const uint32_t* b) {
    asm volatile(
        "mma.sync.aligned.m16n8k16.row.col.f32.f16.f16.f32 "
        "{%0,%1,%2,%3}, {%4,%5,%6,%7}, {%8,%9}, {%0,%1,%2,%3};"
        : "+f"(c[0]), "+f"(c[1]), "+f"(c[2]), "+f"(c[3])
        : "r"(a[0]), "r"(a[1]), "r"(a[2]), "r"(a[3]), "r"(b[0]), "r"(b[1]));
}
#define CP16(dst, src)    asm volatile("cp.async.cg.shared.global [%0], [%1], 16;" :: "r"(dst), "l"(src))
#define CP_COMMIT()       asm volatile("cp.async.commit_group;" ::: "memory")
#define CP_WAIT0()        asm volatile("cp.async.wait_group 0;" ::: "memory")

__device__ __forceinline__ uint32_t hpack(float a, float b) {
    __half2 t = __floats2half2_rn(a, b);
    return *reinterpret_cast<uint32_t*>(&t);
}

// ---------------------------------------------------------------------------
// 0. prep_misc: conv weight prep + accumulator zero + embedding gather
//    blocks [0,42): conv weights / zero;  blocks [42,...): embed
// ---------------------------------------------------------------------------
__global__ void prep_misc(const float* __restrict__ c1w, const float* __restrict__ c2w,
                          const int* __restrict__ x, const float* __restrict__ emb) {
    int bx = blockIdx.x;
    if (bx < 42) {
        int t = bx * 256 + threadIdx.x;
        if (bx == 0) {
            int tt = threadIdx.x;
            if (tt < 64) { g_bnsum[tt] = 0.0; g_bnsq[tt] = 0.0; }
            if (tt < 4)  { g_bn1acc[tt] = 0.0; g_bn2acc[tt] = 0.0; }
        }
        if (t < 3 * 64 * 56) {
            int c = t % 56, o = (t / 56) % 64, k = t / (56 * 64);
            g_wc1[t] = (c < 41) ? __float2half(c1w[(o * 41 + c) * 3 + k]) : __float2half(0.f);
        }
        if (t < 3 * 64 * 40) {
            int c = t % 40, o = (t / 40) % 64, k = t / (40 * 64);
            g_wc2[t] = (c < 32) ? __float2half(c2w[(o * 32 + c) * 3 + k]) : __float2half(0.f);
        }
    } else {
        int gid = (bx - 42) * 256 + threadIdx.x;
        int pos = gid >> 4;
        int f0  = (gid & 15) * 8;
        if (pos >= BATCH * SEQ) return;
        int e = x[pos];
        const float4* sp = reinterpret_cast<const float4*>(emb + e * FDIM + f0);
        float4 v0 = sp[0], v1 = sp[1];
        uint4 o;
        o.x = hpack(v0.x, v0.y); o.y = hpack(v0.z, v0.w);
        o.z = hpack(v1.x, v1.y); o.w = hpack(v1.z, v1.w);
        *reinterpret_cast<uint4*>(g_h0 + (size_t)pos * FDIM + f0) = o;
    }
}

// ---------------------------------------------------------------------------
// 1b. PL weight prep, all 3 layers in one launch.
// ---------------------------------------------------------------------------
__global__ void wprep_all(const float* __restrict__ W3, const float* __restrict__ W5,
                          const float* __restrict__ W7) {
    __shared__ float tile[32][129];
    int bx = blockIdx.x, s = blockIdx.y, t = threadIdx.x;
    const float* W; __half* o; int K, kb;
    if (bx < 12)      { W = W3; o = g_w16 + WOFF3; K = 384; kb = bx * 32; }
    else if (bx < 32) { W = W5; o = g_w16 + WOFF5; K = 640; kb = (bx - 12) * 32; }
    else              { W = W7; o = g_w16 + WOFF7; K = 896; kb = (bx - 32) * 32; }
#pragma unroll
    for (int i = 0; i < 16; i++) {
        int e = t + i * 256;
        int kk = e >> 7, n = e & 127;
        tile[kk][n] = W[((size_t)s * K + kb + kk) * 128 + n];
    }
    __syncthreads();
    int n = t >> 1, h = (t & 1) * 16;
    size_t ob = ((size_t)(s * 128 + n)) * K + kb + h;
#pragma unroll
    for (int kk = 0; kk < 16; kk += 2) {
        *reinterpret_cast<uint32_t*>(&o[ob + kk]) = hpack(tile[h + kk][n], tile[h + kk + 1][n]);
    }
}

// ---------------------------------------------------------------------------
// 2-4. position_linear: fp16 MMA, K-chunk 64, ldmatrix, 3-stage pipeline
// ---------------------------------------------------------------------------
#define PL_SMEM (3 * 32768)   // 98304

template<int WIN>
__global__ void __launch_bounds__(256, 2)
pl_kernel(const __half* __restrict__ aIn, const __half* __restrict__ wIn,
          const float* __restrict__ bst, __half* __restrict__ aOut)
{
    constexpr int P = WIN / 2;
    constexpr int K = WIN * 128;
    const uint32_t smb = smem_u32(sm_raw);
    const int s   = blockIdx.y;
    const int bm  = blockIdx.x * 128;
    const int tid = threadIdx.x;
    const int warp = tid >> 5, lane = tid & 31;
    const int warp_m = warp >> 2, warp_n = warp & 3;
    const int gid = lane >> 2, tg = lane & 3;

    const int j0 = (P - s) > 0 ? (P - s) : 0;
    const int j1 = (WIN - 1) < (P + SEQ - 1 - s) ? (WIN - 1) : (P + SEQ - 1 - s);
    const int nst = (j1 - j0 + 1) * 2;     // k64 stages (>= 4 always)

    const int a_moff = (lane & 7) + ((lane >> 3) & 1) * 8;
    const int a_cbit = lane >> 4;
    const int b_roff = ((lane >> 4) & 1) * 8 + (lane & 7);
    const int b_cbit = (lane >> 3) & 1;

    float acc[4][4][4];
#pragma unroll
    for (int a = 0; a < 4; a++)
#pragma unroll
        for (int b = 0; b < 4; b++)
#pragma unroll
            for (int c = 0; c < 4; c++) acc[a][b][c] = 0.f;

    auto load_stage = [&](int st) {
        const int jj = j0 + (st >> 1);
        const int f0 = (st & 1) * 64;
        const int tsrc = s + jj - P;
        const int k0 = jj * 128 + f0;
        const uint32_t sb = smb + (uint32_t)(st % 3) * 32768;
#pragma unroll
        for (int i = 0; i < 4; i++) {
            int idx = tid + i * 256;
            int row = idx >> 3, ch = idx & 7;
            uint32_t d = sb + row * 128 + (((ch ^ (row & 7)) << 4));
            size_t aoff = ((size_t)(bm + row) * SEQ + tsrc) * 128 + f0 + ch * 8;
            size_t boff = ((size_t)(s * 128 + row)) * K + k0 + ch * 8;
            CP16(d,         (const char*)(aIn + aoff));
            CP16(d + 16384, (const char*)(wIn + boff));
        }
        CP_COMMIT();
    };

    load_stage(0);
    load_stage(1);

    for (int st = 0; st < nst; st++) {
        if (st + 1 < nst) {
            asm volatile("cp.async.wait_group 1;" ::: "memory");
        } else {
            asm volatile("cp.async.wait_group 0;" ::: "memory");
        }
        __syncthreads();

        if (st + 2 < nst) load_stage(st + 2);

        const uint32_t ab = smb + (uint32_t)(st % 3) * 32768;
#pragma unroll
        for (int kt = 0; kt < 4; kt++) {
            uint32_t bf[4][2];
#pragma unroll
            for (int p = 0; p < 2; p++) {
                int row = warp_n * 32 + p * 16 + b_roff;
                int sw = row & 7;
                uint32_t addr = ab + 16384 + row * 128 + (((kt * 2 + b_cbit) ^ sw) << 4);
                uint32_t r[4];
                ldsm_x4(r, addr);
                bf[2 * p][0] = r[0]; bf[2 * p][1] = r[1];
                bf[2 * p + 1][0] = r[2]; bf[2 * p + 1][1] = r[3];
            }
#pragma unroll
            for (int mt = 0; mt < 4; mt++) {
                int row = warp_m * 64 + mt * 16 + a_moff;
                int sw = row & 7;
                uint32_t addr = ab + row * 128 + (((kt * 2 + a_cbit) ^ sw) << 4);
                uint32_t af[4];
                ldsm_x4(af, addr);
#pragma unroll
                for (int nt = 0; nt < 4; nt++)
                    mma_f16(acc[mt][nt], af, bf[nt]);
            }
        }
    }

    const float* bias = bst + s * 128;
#pragma unroll
    for (int mt = 0; mt < 4; mt++) {
        int rbase = warp_m * 64 + mt * 16 + gid;
#pragma unroll
        for (int half = 0; half < 2; half++) {
            int r = rbase + half * 8;
            size_t ob = ((size_t)(bm + r) * SEQ + s) * 128;
#pragma unroll
            for (int nt = 0; nt < 4; nt++) {
                int col = warp_n * 32 + nt * 8 + tg * 2;
                float v0 = fmaxf(acc[mt][nt][half * 2 + 0] + bias[col],     0.f);
                float v1 = fmaxf(acc[mt][nt][half * 2 + 1] + bias[col + 1], 0.f);
                *reinterpret_cast<uint32_t*>(aOut + ob + col) = hpack(v0, v1);
            }
        }
    }
}

// ---------------------------------------------------------------------------
// 5. conv1 via tensor cores. 2 batches per CTA.
// ---------------------------------------------------------------------------
#define C1_STG   0
#define C1_A     10496
#define C1_W     (C1_A + 130*112)        // 25056
#define C1_STATS (C1_W + 3*64*112)       // 46560
#define CONV1_SMEM (C1_STATS + 2*64*4)   // 47072

__global__ void __launch_bounds__(256, 2)
conv1_kernel(const float* __restrict__ bias) {
    const uint32_t smb = smem_u32(sm_raw);
    const int t = threadIdx.x;
    const int warp = t >> 5, lane = t & 31;
    const int warp_m = warp >> 1, warp_n = warp & 1;
    const int gid = lane >> 2, tg = lane & 3;

    for (int i = t; i < 130 * 112 / 4; i += 256) sts32(smb + C1_A + i * 4, 0u);
    for (int i = t; i < 128; i += 256) sts32(smb + C1_STATS + i * 4, 0u);

    // weights + staging for batch b0
    {
        const char* src = (const char*)(g_h1 + (size_t)(blockIdx.x * 2) * SF);
        for (int i = t; i < 41 * 16; i += 256)
            CP16(smb + C1_STG + i * 16, src + i * 16);
        const char* wsrc = (const char*)g_wc1;
        for (int i = t; i < 3 * 64 * 56 * 2 / 16; i += 256)
            CP16(smb + C1_W + i * 16, wsrc + i * 16);
        CP_COMMIT(); CP_WAIT0();
    }
    __syncthreads();

    float s0[4], s1[4], q0[4], q1[4];
#pragma unroll
    for (int nt = 0; nt < 4; nt++) { s0[nt] = s1[nt] = q0[nt] = q1[nt] = 0.f; }

    for (int bb2 = 0; bb2 < 2; bb2++) {
        const int b = blockIdx.x * 2 + bb2;

        // transpose staging [c][f] -> A[(f+1)*112 + c*2]
        for (int idx = t; idx < 41 * 64; idx += 256) {
            int c = idx >> 6, f2 = idx & 63;
            uint32_t v = lds32(smb + C1_STG + c * 256 + f2 * 4);
            sts16(smb + C1_A + (2 * f2 + 1) * 112 + c * 2, (uint16_t)(v & 0xFFFF));
            sts16(smb + C1_A + (2 * f2 + 2) * 112 + c * 2, (uint16_t)(v >> 16));
        }
        __syncthreads();   // transpose reads of staging done; A visible

        // prefetch next batch staging (overlaps MMA below)
        if (bb2 == 0) {
            const char* src = (const char*)(g_h1 + (size_t)(b + 1) * SF);
            for (int i = t; i < 41 * 16; i += 256)
                CP16(smb + C1_STG + i * 16, src + i * 16);
            CP_COMMIT();
        }

        float acc[2][4][4];
#pragma unroll
        for (int a = 0; a < 2; a++)
#pragma unroll
            for (int bb = 0; bb < 4; bb++)
#pragma unroll
                for (int c = 0; c < 4; c++) acc[a][bb][c] = 0.f;

#pragma unroll
        for (int k = 0; k < 3; k++) {
#pragma unroll
            for (int ks = 0; ks < 3; ks++) {
                uint32_t bf[4][2];
#pragma unroll
                for (int nt = 0; nt < 4; nt++) {
                    uint32_t ba = smb + C1_W + k * (64 * 112) + (warp_n * 32 + nt * 8 + gid) * 112 + ks * 32 + tg * 4;
                    bf[nt][0] = lds32(ba);
                    bf[nt][1] = lds32(ba + 16);
                }
#pragma unroll
                for (int mt = 0; mt < 2; mt++) {
                    int r0 = warp_m * 32 + mt * 16 + gid + k;
                    uint32_t a0a = smb + C1_A + r0 * 112 + ks * 32 + tg * 4;
                    uint32_t a1a = a0a + 8 * 112;
                    uint32_t af[4];
                    af[0] = lds32(a0a);
                    af[1] = lds32(a1a);
                    af[2] = lds32(a0a + 16);
                    af[3] = lds32(a1a + 16);
#pragma unroll
                    for (int nt = 0; nt < 4; nt++)
                        mma_f16(acc[mt][nt], af, bf[nt]);
                }
            }
        }

        __half* dst = g_c + (size_t)b * C64L;
#pragma unroll
        for (int mt = 0; mt < 2; mt++) {
            int l0 = warp_m * 32 + mt * 16 + gid;
#pragma unroll
            for (int nt = 0; nt < 4; nt++) {
                int o = warp_n * 32 + nt * 8 + tg * 2;
                float bb0 = bias[o], bb1 = bias[o + 1];
                float v0 = acc[mt][nt][0] + bb0, v1 = acc[mt][nt][1] + bb1;
                float v2 = acc[mt][nt][2] + bb0, v3 = acc[mt][nt][3] + bb1;
                *reinterpret_cast<uint32_t*>(dst + l0 * 64 + o)       = hpack(v0, v1);
                *reinterpret_cast<uint32_t*>(dst + (l0 + 8) * 64 + o) = hpack(v2, v3);
                s0[nt] += v0 + v2; s1[nt] += v1 + v3;
                q0[nt] += v0 * v0 + v2 * v2; q1[nt] += v1 * v1 + v3 * v3;
            }
        }

        if (bb2 == 0) { CP_WAIT0(); }
        __syncthreads();   // MMA reads of A done before next transpose; staging visible
    }

#pragma unroll
    for (int nt = 0; nt < 4; nt++) {
#pragma unroll
        for (int off = 4; off < 32; off <<= 1) {
            s0[nt] += __shfl_xor_sync(0xffffffffu, s0[nt], off);
            s1[nt] += __shfl_xor_sync(0xffffffffu, s1[nt], off);
            q0[nt] += __shfl_xor_sync(0xffffffffu, q0[nt], off);
            q1[nt] += __shfl_xor_sync(0xffffffffu, q1[nt], off);
        }
    }
    if (gid == 0) {
        float* sums = reinterpret_cast<float*>(sm_raw + C1_STATS);
        float* sqs  = sums + 64;
#pragma unroll
        for (int nt = 0; nt < 4; nt++) {
            int o = warp_n * 32 + nt * 8 + tg * 2;
            atomicAdd(&sums[o],     s0[nt]);
            atomicAdd(&sums[o + 1], s1[nt]);
            atomicAdd(&sqs[o],      q0[nt]);
            atomicAdd(&sqs[o + 1],  q1[nt]);
        }
    }
    __syncthreads();
    if (t < 64) {
        float* sums = reinterpret_cast<float*>(sm_raw + C1_STATS);
        atomicAdd(&g_bnsum[t], (double)sums[t]);
        atomicAdd(&g_bnsq[t],  (double)sums[64 + t]);
    }
}

// ---------------------------------------------------------------------------
// 8-9. FUSED capsroute (3 CTAs/SM) — BN params computed locally
// ---------------------------------------------------------------------------
#define CR_A    0
#define CR_W    16640
#define CR_SOUT 32000
#define CR_SMEM (CR_SOUT + 128*73*4)   // 69376

__global__ void __launch_bounds__(256, 3)
capsroute_kernel(const float* __restrict__ bng, const float* __restrict__ bnb,
                 const float* __restrict__ cb,
                 const float* __restrict__ rW, const float* __restrict__ rb,
                 const float* __restrict__ fc1)
{
    const uint32_t smb = smem_u32(sm_raw);
    float* sout = reinterpret_cast<float*>(sm_raw + CR_SOUT);  // [128 l][73]
    __shared__ float bnsc[64], bnsh[64];
    __shared__ float red4[4][64];
    __shared__ float sfac[64];
    __shared__ float coef[2][64];
    __shared__ float warp_sq[8];
    __shared__ float factor_s[2];
    __shared__ float sv_s[2][128];
    __shared__ float yv_s[2][128];

    const int b = blockIdx.x, t = threadIdx.x;
    const int warp = t >> 5, lane = t & 31;
    const int warp_m = warp >> 1, g = warp & 1;
    const int gid = lane >> 2, tg = lane & 3;

    // zero halo rows 0 and 129; local BN params
    if (t < 64) {
        sts32(smb + CR_A + ((t < 32) ? 0 : (129 * 128)) + (t & 31) * 4, 0u);
        double inv = 1.0 / ((double)BATCH * 128.0);
        double mu = g_bnsum[t] * inv;
        double var = g_bnsq[t] * inv - mu * mu;
        float sc = bng[t] * rsqrtf((float)var + 1e-5f);
        bnsc[t] = sc;
        bnsh[t] = bnb[t] - (float)mu * sc;
    } else if (t < 96) {
        sts32(smb + CR_A + 129 * 128 + (t & 31) * 4 + 128 - 128, 0u);  // no-op style; keep halo row129 upper half
    }
    // complete halo row 129 (cols 32..63 of its 128B row were covered above? row is 128B = 32 words; t<64 covers both rows fully)

    {
        const char* src = (const char*)(g_c + (size_t)b * C64L);
        for (int i = t; i < 128 * 8; i += 256) {
            int row = (i >> 3) + 1, ch = i & 7;
            CP16(smb + CR_A + row * 128 + ((ch ^ (row & 7)) << 4), src + (row - 1) * 128 + ch * 16);
        }
        const char* wsrc = (const char*)g_wc2;
        for (int i = t; i < 3 * 64 * 40 * 2 / 16; i += 256)
            CP16(smb + CR_W + i * 16, wsrc + i * 16);
        CP_COMMIT(); CP_WAIT0();
    }
    __syncthreads();

    // BN + ReLU in place on A rows 1..128
    for (int idx = t; idx < 128 * 32; idx += 256) {
        int r = (idx >> 5) + 1, wd = idx & 31;
        int o = wd * 2;
        uint32_t addr = smb + CR_A + r * 128 + (((wd >> 2) ^ (r & 7)) << 4) + ((wd * 4) & 15);
        uint32_t v = lds32(addr);
        __half2 h = *reinterpret_cast<__half2*>(&v);
        float f0 = fmaxf(__low2float(h)  * bnsc[o]     + bnsh[o],     0.f);
        float f1 = fmaxf(__high2float(h) * bnsc[o + 1] + bnsh[o + 1], 0.f);
        sts32(addr, hpack(f0, f1));
    }
    __syncthreads();

    float acc[2][4][4];
#pragma unroll
    for (int a = 0; a < 2; a++)
#pragma unroll
        for (int bb = 0; bb < 4; bb++)
#pragma unroll
            for (int c = 0; c < 4; c++) acc[a][bb][c] = 0.f;

#pragma unroll
    for (int k = 0; k < 3; k++) {
#pragma unroll
        for (int ks = 0; ks < 2; ks++) {
            uint32_t bf[4][2];
#pragma unroll
            for (int nt = 0; nt < 4; nt++) {
                uint32_t ba = smb + CR_W + k * (64 * 80) + (g * 32 + nt * 8 + gid) * 80 + ks * 32 + tg * 4;
                bf[nt][0] = lds32(ba);
                bf[nt][1] = lds32(ba + 16);
            }
            int cbase = g * 4 + ks * 2;
#pragma unroll
            for (int mt = 0; mt < 2; mt++) {
                int r0 = warp_m * 32 + mt * 16 + gid + k;
                int r1 = r0 + 8;
                uint32_t af[4];
                af[0] = lds32(smb + CR_A + r0 * 128 + (((cbase)     ^ (r0 & 7)) << 4) + tg * 4);
                af[1] = lds32(smb + CR_A + r1 * 128 + (((cbase)     ^ (r1 & 7)) << 4) + tg * 4);
                af[2] = lds32(smb + CR_A + r0 * 128 + (((cbase + 1) ^ (r0 & 7)) << 4) + tg * 4);
                af[3] = lds32(smb + CR_A + r1 * 128 + (((cbase + 1) ^ (r1 & 7)) << 4) + tg * 4);
#pragma unroll
                for (int nt = 0; nt < 4; nt++)
                    mma_f16(acc[mt][nt], af, bf[nt]);
            }
        }
    }

#pragma unroll
    for (int mt = 0; mt < 2; mt++) {
        int l0 = warp_m * 32 + mt * 16 + gid;
#pragma unroll
        for (int nt = 0; nt < 4; nt++) {
            int o = g * 32 + nt * 8 + tg * 2;
            float bb0 = cb[o], bb1 = cb[o + 1];
            sout[l0 * 73 + o]           = acc[mt][nt][0] + bb0;
            sout[l0 * 73 + o + 1]       = acc[mt][nt][1] + bb1;
            sout[(l0 + 8) * 73 + o]     = acc[mt][nt][2] + bb0;
            sout[(l0 + 8) * 73 + o + 1] = acc[mt][nt][3] + bb1;
        }
    }
    __syncthreads();

    {
        int o = t & 63, seg = t >> 6;
        float p = 0.f;
        for (int l = seg * 32; l < seg * 32 + 32; l++) {
            float v = sout[l * 73 + o];
            p += v * v;
        }
        red4[seg][o] = p;
    }
    __syncthreads();
    if (t < 64) {
        float tot = red4[0][t] + red4[1][t] + red4[2][t] + red4[3][t];
        sfac[t] = squash_factor(tot);
    }
    __syncthreads();
    if (t < 128) {
        int i = t >> 6, j = t & 63;
        coef[i][j] = sfac[j] * (1.0f + rb[i * 64 + j]);
    }
    __syncthreads();

    int i = t >> 7;
    int f = t & 127;
    float acc2 = 0.f;
    const float* rwi = rW + i * 8192 + f;
    const float* srow = sout + f * 73;
#pragma unroll 8
    for (int j = 0; j < 64; j++)
        acc2 += srow[j] * rwi[j * 128] * coef[i][j];

    float sq = acc2 * acc2;
    for (int off = 16; off; off >>= 1) sq += __shfl_xor_sync(0xffffffffu, sq, off);
    if ((t & 31) == 0) warp_sq[t >> 5] = sq;
    __syncthreads();
    if (t < 2) {
        float tot = warp_sq[t * 4 + 0] + warp_sq[t * 4 + 1] + warp_sq[t * 4 + 2] + warp_sq[t * 4 + 3];
        factor_s[t] = squash_factor(tot);
    }
    __syncthreads();
    sv_s[i][f] = acc2 * factor_s[i];
    __syncthreads();
    yv_s[i][f] = sv_s[i][f] + fmaxf(sv_s[0][f], sv_s[1][f]);
    __syncthreads();

    {
        int ii = t >> 7;
        int o  = (t >> 1) & 63;
        int p  = t & 1;
        float a = 0.f;
        const float* yb = yv_s[ii];
        const float* fb = fc1 + p * 64 * 64 + o;
#pragma unroll 8
        for (int ff = 0; ff < 64; ff++) a += yb[p * 64 + ff] * fb[ff * 64];
        a += __shfl_xor_sync(0xffffffffu, a, 1);
        double s = 0.0, q = 0.0;
        if (p == 0) {
            g_g1[(size_t)b * 128 + ii * 64 + o] = a;
            s = a; q = (double)a * a;
        }
        for (int off = 16; off; off >>= 1) {
            s += __shfl_xor_sync(0xffffffffu, s, off);
            q += __shfl_xor_sync(0xffffffffu, q, off);
        }
        if ((t & 31) == 0) {
            atomicAdd(&g_bn1acc[ii], s);
            atomicAdd(&g_bn1acc[2 + ii], q);
        }
    }
}

// ---------------------------------------------------------------------------
// 11. head1 (bn1 params computed locally)
// ---------------------------------------------------------------------------
__global__ void head1_kernel(const float* __restrict__ bn1g, const float* __restrict__ bn1b,
                             const float* __restrict__ fc2) {
    __shared__ float a_s[4][128];
    __shared__ float p1[4];
    int t = threadIdx.x;
    if (t < 2) {
        double inv = 1.0 / ((double)BATCH * 64.0);
        double mu = g_bn1acc[t] * inv;
        double var = g_bn1acc[2 + t] * inv - mu * mu;
        float sc = bn1g[t] * rsqrtf((float)var + 1e-5f);
        p1[t] = sc;
        p1[2 + t] = bn1b[t] - (float)mu * sc;
    }
    __syncthreads();
    for (int idx = t; idx < 512; idx += 256) {
        int lbb = idx >> 7, rr = idx & 127;
        int ii = rr >> 6;
        float v = g_g1[(size_t)(blockIdx.x * 4 + lbb) * 128 + rr];
        a_s[lbb][rr] = fmaxf(v * p1[ii] + p1[2 + ii], 0.f);
    }
    __syncthreads();
    int lb = t >> 6, r = t & 63;
    int b = blockIdx.x * 4 + lb;
    int ii = r >> 5, m = r & 31;
    float acc = 0.f;
    const float* arow = &a_s[lb][ii * 64];
#pragma unroll 8
    for (int o = 0; o < 64; o++) acc += arow[o] * fc2[o * 32 + m];
    g_g2[(size_t)b * 64 + ii * 32 + m] = acc;
    double s = acc, q = (double)acc * acc;
    for (int off = 16; off; off >>= 1) {
        s += __shfl_xor_sync(0xffffffffu, s, off);
        q += __shfl_xor_sync(0xffffffffu, q, off);
    }
    if ((t & 31) == 0) {
        atomicAdd(&g_bn2acc[ii], s);
        atomicAdd(&g_bn2acc[2 + ii], q);
    }
}

// ---------------------------------------------------------------------------
// 13. head2 (bn2 params computed locally)
// ---------------------------------------------------------------------------
__global__ void head2_kernel(const float* __restrict__ bn2g, const float* __restrict__ bn2b,
                             const float* __restrict__ fc3, float* __restrict__ out) {
    __shared__ float p2[4];
    if (threadIdx.x < 2) {
        int i = threadIdx.x;
        double inv = 1.0 / ((double)BATCH * 32.0);
        double mu = g_bn2acc[i] * inv;
        double var = g_bn2acc[2 + i] * inv - mu * mu;
        float sc = bn2g[i] * rsqrtf((float)var + 1e-5f);
        p2[i] = sc;
        p2[2 + i] = bn2b[i] - (float)mu * sc;
    }
    __syncthreads();
    int b = blockIdx.x * 256 + threadIdx.x;
    if (b >= BATCH) return;
    float best = -1e30f;
#pragma unroll
    for (int i = 0; i < 2; i++) {
        float sc = p2[i], sh = p2[2 + i];
        float s = 0.f;
#pragma unroll
        for (int m = 0; m < 32; m++) {
            float v = fmaxf(g_g2[(size_t)b * 64 + i * 32 + m] * sc + sh, 0.f);
            s += v * fc3[m];
        }
        float sig = 1.f / (1.f + expf(-s));
        best = fmaxf(best, sig);
    }
    out[b] = best;
}

// ---------------------------------------------------------------------------
// launch
// ---------------------------------------------------------------------------
extern "C" void kernel_launch(void* const* d_in, const int* in_sizes, int n_in,
                              void* d_out, int out_size)
{
    const int*   x      = (const int*)d_in[0];
    const float* emb    = (const float*)d_in[1];
    const float* W3     = (const float*)d_in[2];
    const float* b3     = (const float*)d_in[3];
    const float* W5     = (const float*)d_in[4];
    const float* b5     = (const float*)d_in[5];
    const float* W7     = (const float*)d_in[6];
    const float* b7     = (const float*)d_in[7];
    const float* conv1w = (const float*)d_in[8];
    const float* conv1b = (const float*)d_in[9];
    const float* bng    = (const float*)d_in[10];
    const float* bnb    = (const float*)d_in[11];
    const float* capsw  = (const float*)d_in[12];
    const float* capsb  = (const float*)d_in[13];
    const float* routeW = (const float*)d_in[14];
    const float* routeb = (const float*)d_in[15];
    const float* fc1    = (const float*)d_in[16];
    const float* bn1g   = (const float*)d_in[17];
    const float* bn1b   = (const float*)d_in[18];
    const float* fc2    = (const float*)d_in[19];
    const float* bn2g   = (const float*)d_in[20];
    const float* bn2b   = (const float*)d_in[21];
    const float* fc3    = (const float*)d_in[22];
    float* out = (float*)d_out;

    cudaFuncSetAttribute(conv1_kernel,     cudaFuncAttributeMaxDynamicSharedMemorySize, CONV1_SMEM);
    cudaFuncSetAttribute(capsroute_kernel, cudaFuncAttributeMaxDynamicSharedMemorySize, CR_SMEM);
    cudaFuncSetAttribute(pl_kernel<3>, cudaFuncAttributeMaxDynamicSharedMemorySize, PL_SMEM);
    cudaFuncSetAttribute(pl_kernel<5>, cudaFuncAttributeMaxDynamicSharedMemorySize, PL_SMEM);
    cudaFuncSetAttribute(pl_kernel<7>, cudaFuncAttributeMaxDynamicSharedMemorySize, PL_SMEM);

    __half *h0, *h1, *w16;
    cudaGetSymbolAddress((void**)&h0,  g_h0);
    cudaGetSymbolAddress((void**)&h1,  g_h1);
    cudaGetSymbolAddress((void**)&w16, g_w16);

    prep_misc<<<42 + (BATCH * SEQ * 16 + 255) / 256, 256>>>(conv1w, capsw, x, emb);
    wprep_all<<<dim3(60, 41), 256>>>(W3, W5, W7);

    pl_kernel<3><<<dim3(32, 41), 256, PL_SMEM>>>(h0, w16 + WOFF3, b3, h1);
    pl_kernel<5><<<dim3(32, 41), 256, PL_SMEM>>>(h1, w16 + WOFF5, b5, h0);
    pl_kernel<7><<<dim3(32, 41), 256, PL_SMEM>>>(h0, w16 + WOFF7, b7, h1);

    conv1_kernel<<<BATCH / 2, 256, CONV1_SMEM>>>(conv1b);
    capsroute_kernel<<<BATCH, 256, CR_SMEM>>>(bng, bnb, capsb, routeW, routeb, fc1);
    head1_kernel<<<BATCH / 4, 256>>>(bn1g, bn1b, fc2);
    head2_kernel<<<(BATCH + 255) / 256, 256>>>(bn2g, bn2b, fc3, out);
}